// round 10
// baseline (speedup 1.0000x reference)
#include <cuda_runtime.h>
#include <cuda_bf16.h>
#include <math.h>

// Problem constants
#define BB   128
#define LW   400
#define SSL  30
#define VV   50000
#define EMB_ 128
#define HH   512
#define MMD  512
#define OOVN 30
#define VE   (VV + OOVN)   // 50030

// Output layout: concat of (final_dist, h_next, word_ctx, word_attn, p_gen, word_cov)
#define OUT_FINAL 0
#define OUT_H     (BB * VE)
#define OUT_WCTX  (OUT_H + BB * HH)
#define OUT_WATTN (OUT_WCTX + BB * MMD)
#define OUT_PGEN  (OUT_WATTN + BB * LW)
#define OUT_WCOV  (OUT_PGEN + BB)

#define SPITCH 40   // smem bf16 row pitch (conflict-free frag loads; 80B rows)

// -------------------- scratch (no allocations allowed) --------------------
__device__ float g_yemb[BB * EMB_];
__device__ float g_gi[BB * 3 * HH];
__device__ float g_gh[BB * 3 * HH];
__device__ float g_hlast[BB * HH];
__device__ float g_dpw[BB * HH];
__device__ float g_dps[BB * HH];
__device__ float g_wscores[BB * LW];
__device__ float g_sscores[BB * SSL];
__device__ float g_sattn[BB * SSL];
__device__ float g_cat[BB * 3 * HH];     // [word_ctx | sent_ctx | h_last]
__device__ float g_hid[BB * HH];
__device__ float g_pgen[BB];
__device__ float g_logits[(size_t)BB * VV];

// pre-split bf16 (hi, lo) buffers
__device__ __nv_bfloat16 g_wmemH[(size_t)BB * LW * MMD];
__device__ __nv_bfloat16 g_wmemL[(size_t)BB * LW * MMD];
__device__ __nv_bfloat16 g_smemH[BB * SSL * MMD];
__device__ __nv_bfloat16 g_smemL[BB * SSL * MMD];
__device__ __nv_bfloat16 g_wmpH[HH * MMD];
__device__ __nv_bfloat16 g_wmpL[HH * MMD];
__device__ __nv_bfloat16 g_smpH[HH * MMD];
__device__ __nv_bfloat16 g_smpL[HH * MMD];
__device__ __nv_bfloat16 g_hidH[BB * HH];
__device__ __nv_bfloat16 g_hidL[BB * HH];
__device__ __nv_bfloat16 g_vd2wH[(size_t)VV * HH];
__device__ __nv_bfloat16 g_vd2wL[(size_t)VV * HH];

// -------------------- helpers --------------------
__device__ __forceinline__ unsigned pack_bf2(__nv_bfloat16 a, __nv_bfloat16 b) {
    __nv_bfloat162 t(a, b);
    return *(unsigned*)&t;
}
__device__ __forceinline__ void split1(float x, __nv_bfloat16& h, __nv_bfloat16& l) {
    h = __float2bfloat16_rn(x);
    l = __float2bfloat16_rn(x - __bfloat162float(h));
}
__device__ __forceinline__ void split2(float x, float y, unsigned& hi2, unsigned& lo2) {
    __nv_bfloat16 hx, lx, hy, ly;
    split1(x, hx, lx); split1(y, hy, ly);
    hi2 = pack_bf2(hx, hy);
    lo2 = pack_bf2(lx, ly);
}
__device__ __forceinline__ void mma_bf16(float* c, const unsigned* a, const unsigned* b) {
    asm volatile(
        "mma.sync.aligned.m16n8k16.row.col.f32.bf16.bf16.f32 "
        "{%0,%1,%2,%3}, {%4,%5,%6,%7}, {%8,%9}, {%0,%1,%2,%3};"
        : "+f"(c[0]), "+f"(c[1]), "+f"(c[2]), "+f"(c[3])
        : "r"(a[0]), "r"(a[1]), "r"(a[2]), "r"(a[3]), "r"(b[0]), "r"(b[1]));
}
// cp.async 16B
__device__ __forceinline__ void cp16(void* sptr, const void* gptr) {
    unsigned sa = (unsigned)__cvta_generic_to_shared(sptr);
    asm volatile("cp.async.cg.shared.global [%0], [%1], 16;" :: "r"(sa), "l"(gptr));
}
__device__ __forceinline__ void cp16z(void* sptr, const void* gptr, bool ok) {
    unsigned sa = (unsigned)__cvta_generic_to_shared(sptr);
    int sz = ok ? 16 : 0;
    asm volatile("cp.async.cg.shared.global [%0], [%1], 16, %2;" :: "r"(sa), "l"(gptr), "r"(sz));
}
#define CP_COMMIT() asm volatile("cp.async.commit_group;")
template <int N> __device__ __forceinline__ void cp_wait() {
    asm volatile("cp.async.wait_group %0;" :: "n"(N));
}

// -------------------- hid presplit (separate small launch) --------------------
__global__ void presplit_kernel(const float* __restrict__ src, __nv_bfloat16* __restrict__ dh,
                                __nv_bfloat16* __restrict__ dl, int n4) {
    int i = blockIdx.x * 256 + threadIdx.x;
    if (i >= n4) return;
    float4 x = ((const float4*)src)[i];
    unsigned h01, l01, h23, l23;
    split2(x.x, x.y, h01, l01);
    split2(x.z, x.w, h23, l23);
    ((uint2*)dh)[i] = make_uint2(h01, h23);
    ((uint2*)dl)[i] = make_uint2(l01, l23);
}

// ==================== prep: gigh GEMMs + ALL big presplits, one launch ====================
#define NB_GIGH 96
#define NB_WMEM 25600   // BB*LW*MMD/1024
#define NB_SMEM 1920    // BB*SSL*MMD/1024
#define NB_WMP  256     // HH*MMD/1024
#define NB_SMP  256
#define NB_VD2W 25000   // VV*HH/1024
#define NB_PREP (NB_GIGH + NB_WMEM + NB_SMEM + NB_WMP + NB_SMP + NB_VD2W)

__global__ void prep_kernel(
    const float* __restrict__ emb, const int* __restrict__ y, const float* __restrict__ h0,
    const float* __restrict__ gwih, const float* __restrict__ gbih,
    const float* __restrict__ gwhh, const float* __restrict__ gbhh,
    float* __restrict__ gi, float* __restrict__ gh, float* __restrict__ yemb,
    const float* __restrict__ wmem, __nv_bfloat16* __restrict__ wmH, __nv_bfloat16* __restrict__ wmL,
    const float* __restrict__ smemb, __nv_bfloat16* __restrict__ smH, __nv_bfloat16* __restrict__ smL,
    const float* __restrict__ wmp, __nv_bfloat16* __restrict__ wpH, __nv_bfloat16* __restrict__ wpL,
    const float* __restrict__ smp, __nv_bfloat16* __restrict__ spH, __nv_bfloat16* __restrict__ spL,
    const float* __restrict__ vd2w, __nv_bfloat16* __restrict__ v2H, __nv_bfloat16* __restrict__ v2L)
{
    __shared__ float As[16][68];
    __shared__ float Ws[16][68];
    int bid = blockIdx.x;
    int tid = threadIdx.x;

    if (bid >= NB_GIGH) {
        // ---- presplit region ----
        int pb = bid - NB_GIGH;
        const float* src; __nv_bfloat16* dh; __nv_bfloat16* dl; int base;
        if (pb < NB_WMEM)                       { src = wmem;  dh = wmH; dl = wmL; base = pb; }
        else if (pb < NB_WMEM + NB_SMEM)        { src = smemb; dh = smH; dl = smL; base = pb - NB_WMEM; }
        else if (pb < NB_WMEM + NB_SMEM + NB_WMP) { src = wmp; dh = wpH; dl = wpL; base = pb - NB_WMEM - NB_SMEM; }
        else if (pb < NB_WMEM + NB_SMEM + NB_WMP + NB_SMP) { src = smp; dh = spH; dl = spL; base = pb - NB_WMEM - NB_SMEM - NB_WMP; }
        else { src = vd2w; dh = v2H; dl = v2L; base = pb - NB_WMEM - NB_SMEM - NB_WMP - NB_SMP; }
        size_t i = (size_t)base * 256 + tid;
        float4 x = ((const float4*)src)[i];
        unsigned h01, l01, h23, l23;
        split2(x.x, x.y, h01, l01);
        split2(x.z, x.w, h23, l23);
        ((uint2*)dh)[i] = make_uint2(h01, h23);
        ((uint2*)dl)[i] = make_uint2(l01, l23);
        return;
    }

    // ---- gigh GEMM: z=0 -> gi (A = emb[y]); z=1 -> gh (A = h0) ----
    int gx = bid % 24, gy = (bid / 24) % 2, gz = bid / 48;
    int tx = tid & 15, ty = tid >> 4;
    int K = gz ? HH : EMB_;
    const float* W = gz ? gwhh : gwih;
    const float* bias = gz ? gbhh : gbih;
    float* C = gz ? gh : gi;
    int rb = gy * 64, cb = gx * 64;
    int lr = tid >> 2, kq = tid & 3;
    int yrow = gz ? 0 : y[rb + lr];
    const float* Arow = gz ? &h0[(size_t)(rb + lr) * HH] : &emb[(size_t)yrow * EMB_];
    float acc[4][4] = {};

    for (int k0 = 0; k0 < K; k0 += 16) {
        float4 a4 = *(const float4*)&Arow[k0 + kq * 4];
        float4 w4 = *(const float4*)&W[(size_t)(cb + lr) * K + k0 + kq * 4];
        if (gz == 0 && gx == 0)
            *(float4*)&yemb[(size_t)(rb + lr) * EMB_ + k0 + kq * 4] = a4;
        As[kq * 4 + 0][lr] = a4.x; As[kq * 4 + 1][lr] = a4.y;
        As[kq * 4 + 2][lr] = a4.z; As[kq * 4 + 3][lr] = a4.w;
        Ws[kq * 4 + 0][lr] = w4.x; Ws[kq * 4 + 1][lr] = w4.y;
        Ws[kq * 4 + 2][lr] = w4.z; Ws[kq * 4 + 3][lr] = w4.w;
        __syncthreads();
#pragma unroll
        for (int kk = 0; kk < 16; kk++) {
            float4 a = *(const float4*)&As[kk][ty * 4];
            float4 w = *(const float4*)&Ws[kk][tx * 4];
            acc[0][0] += a.x * w.x; acc[0][1] += a.x * w.y; acc[0][2] += a.x * w.z; acc[0][3] += a.x * w.w;
            acc[1][0] += a.y * w.x; acc[1][1] += a.y * w.y; acc[1][2] += a.y * w.z; acc[1][3] += a.y * w.w;
            acc[2][0] += a.z * w.x; acc[2][1] += a.z * w.y; acc[2][2] += a.z * w.z; acc[2][3] += a.z * w.w;
            acc[3][0] += a.w * w.x; acc[3][1] += a.w * w.y; acc[3][2] += a.w * w.z; acc[3][3] += a.w * w.w;
        }
        __syncthreads();
    }
#pragma unroll
    for (int i = 0; i < 4; i++) {
        int row = rb + ty * 4 + i;
#pragma unroll
        for (int j = 0; j < 4; j++) {
            int col = cb + tx * 4 + j;
            C[(size_t)row * (3 * HH) + col] = acc[i][j] + bias[col];
        }
    }
}

// -------------------- fused decoder projections: z=0 -> dpw, z=1 -> dps --------------------
__global__ void dpwdps_kernel(const float* __restrict__ hl,
                              const float* __restrict__ wdpw, const float* __restrict__ wdpb,
                              const float* __restrict__ sdpw, const float* __restrict__ sdpb,
                              float* __restrict__ dpw, float* __restrict__ dps) {
    __shared__ float As[16][68];
    __shared__ float Ws[16][68];
    int tid = threadIdx.x;
    int tx = tid & 15, ty = tid >> 4;
    int z = blockIdx.z;
    const float* W = z ? sdpw : wdpw;
    const float* bias = z ? sdpb : wdpb;
    float* C = z ? dps : dpw;
    const int K = HH;
    int rb = blockIdx.y * 64, cb = blockIdx.x * 64;
    int lr = tid >> 2, kq = tid & 3;
    float acc[4][4] = {};

    for (int k0 = 0; k0 < K; k0 += 16) {
        float4 a4 = *(const float4*)&hl[(size_t)(rb + lr) * K + k0 + kq * 4];
        float4 w4 = *(const float4*)&W[(size_t)(cb + lr) * K + k0 + kq * 4];
        As[kq * 4 + 0][lr] = a4.x; As[kq * 4 + 1][lr] = a4.y;
        As[kq * 4 + 2][lr] = a4.z; As[kq * 4 + 3][lr] = a4.w;
        Ws[kq * 4 + 0][lr] = w4.x; Ws[kq * 4 + 1][lr] = w4.y;
        Ws[kq * 4 + 2][lr] = w4.z; Ws[kq * 4 + 3][lr] = w4.w;
        __syncthreads();
#pragma unroll
        for (int kk = 0; kk < 16; kk++) {
            float4 a = *(const float4*)&As[kk][ty * 4];
            float4 w = *(const float4*)&Ws[kk][tx * 4];
            acc[0][0] += a.x * w.x; acc[0][1] += a.x * w.y; acc[0][2] += a.x * w.z; acc[0][3] += a.x * w.w;
            acc[1][0] += a.y * w.x; acc[1][1] += a.y * w.y; acc[1][2] += a.y * w.z; acc[1][3] += a.y * w.w;
            acc[2][0] += a.z * w.x; acc[2][1] += a.z * w.y; acc[2][2] += a.z * w.z; acc[2][3] += a.z * w.w;
            acc[3][0] += a.w * w.x; acc[3][1] += a.w * w.y; acc[3][2] += a.w * w.z; acc[3][3] += a.w * w.w;
        }
        __syncthreads();
    }
#pragma unroll
    for (int i = 0; i < 4; i++) {
        int row = rb + ty * 4 + i;
#pragma unroll
        for (int j = 0; j < 4; j++) {
            int col = cb + tx * 4 + j;
            C[(size_t)row * HH + col] = acc[i][j] + bias[col];
        }
    }
}

// -------------------- generic scalar SGEMM (hid) --------------------
__global__ void gemm_bias_kernel(const float* __restrict__ A, const float* __restrict__ W,
                                 const float* __restrict__ bias, float* __restrict__ C,
                                 int M, int N, int K) {
    __shared__ float As[16][68];
    __shared__ float Ws[16][68];
    int tid = threadIdx.x;
    int tx = tid & 15, ty = tid >> 4;
    int rb = blockIdx.y * 64, cb = blockIdx.x * 64;
    int lr = tid >> 2, kq = tid & 3;
    float acc[4][4] = {};

    for (int k0 = 0; k0 < K; k0 += 16) {
        float4 a4 = make_float4(0.f, 0.f, 0.f, 0.f);
        float4 w4 = make_float4(0.f, 0.f, 0.f, 0.f);
        if (rb + lr < M) a4 = *(const float4*)&A[(size_t)(rb + lr) * K + k0 + kq * 4];
        if (cb + lr < N) w4 = *(const float4*)&W[(size_t)(cb + lr) * K + k0 + kq * 4];
        As[kq * 4 + 0][lr] = a4.x; As[kq * 4 + 1][lr] = a4.y;
        As[kq * 4 + 2][lr] = a4.z; As[kq * 4 + 3][lr] = a4.w;
        Ws[kq * 4 + 0][lr] = w4.x; Ws[kq * 4 + 1][lr] = w4.y;
        Ws[kq * 4 + 2][lr] = w4.z; Ws[kq * 4 + 3][lr] = w4.w;
        __syncthreads();
#pragma unroll
        for (int kk = 0; kk < 16; kk++) {
            float4 a = *(const float4*)&As[kk][ty * 4];
            float4 w = *(const float4*)&Ws[kk][tx * 4];
            acc[0][0] += a.x * w.x; acc[0][1] += a.x * w.y; acc[0][2] += a.x * w.z; acc[0][3] += a.x * w.w;
            acc[1][0] += a.y * w.x; acc[1][1] += a.y * w.y; acc[1][2] += a.y * w.z; acc[1][3] += a.y * w.w;
            acc[2][0] += a.z * w.x; acc[2][1] += a.z * w.y; acc[2][2] += a.z * w.z; acc[2][3] += a.z * w.w;
            acc[3][0] += a.w * w.x; acc[3][1] += a.w * w.y; acc[3][2] += a.w * w.z; acc[3][3] += a.w * w.w;
        }
        __syncthreads();
    }
#pragma unroll
    for (int i = 0; i < 4; i++) {
        int row = rb + ty * 4 + i;
        if (row >= M) continue;
#pragma unroll
        for (int j = 0; j < 4; j++) {
            int col = cb + tx * 4 + j;
            if (col < N) C[(size_t)row * N + col] = acc[i][j] + (bias ? bias[col] : 0.f);
        }
    }
}

// ==================== fused attention scores: 128x128 tiles, cp.async, bf16x3 ====================
// score[r] = sum_d v[d] * tanh( sum_m Wm[d,m]*mem[r,m] + dproj[b,d] (+ cov[r]*wcov[d]) )
#define AT_T   (128 * SPITCH)                // 5120 elems per half-tile
#define AT_BUF (4 * AT_T)                    // Ah|Al|Wh|Wl
#define AT_DYN (2 * AT_BUF * 2)              // 81920 bytes
template <bool HAS_COV>
__global__ void __launch_bounds__(256, 2)
attn_scores_mma(const __nv_bfloat16* __restrict__ memH, const __nv_bfloat16* __restrict__ memL,
                const __nv_bfloat16* __restrict__ WmH, const __nv_bfloat16* __restrict__ WmL,
                const float* __restrict__ dproj, const float* __restrict__ v,
                const float* __restrict__ wcov, const float* __restrict__ cov,
                float* __restrict__ scores, int Lper) {
    const int K = 512;
    extern __shared__ __nv_bfloat16 dyn[];
    __shared__ float rowred[128];

    int tid = threadIdx.x;
    int wid = tid >> 5, lane = tid & 31;
    int rg = wid >> 2, cg = wid & 3;         // 2 row-groups x 4 col-groups
    int warpRow = rg * 64, warpCol = cg * 32;
    int g = lane >> 2, tg = lane & 3;
    int rowBase = blockIdx.x * 128;
    int frow = tid & 127, fhf = tid >> 7;    // fill: 128 rows x 2 halves (conflict-free phases)

    if (tid < 128) rowred[tid] = 0.f;

    float covr[8];
    if (HAS_COV) {
#pragma unroll
        for (int mt = 0; mt < 4; mt++) {
            covr[2 * mt]     = cov[rowBase + warpRow + mt * 16 + g];
            covr[2 * mt + 1] = cov[rowBase + warpRow + mt * 16 + g + 8];
        }
    }
    float rs[8] = {};

    auto do_fill = [&](int b, int col0, int k0) {
        __nv_bfloat16* base = dyn + b * AT_BUF;
        size_t ga = (size_t)(rowBase + frow) * K + k0 + fhf * 8;
        size_t gw = (size_t)(col0 + frow) * K + k0 + fhf * 8;
        unsigned so = frow * SPITCH + fhf * 8;
        cp16(&base[0 * AT_T + so], &memH[ga]);
        cp16(&base[1 * AT_T + so], &memL[ga]);
        cp16(&base[2 * AT_T + so], &WmH[gw]);
        cp16(&base[3 * AT_T + so], &WmL[gw]);
        CP_COMMIT();
    };

    do_fill(0, 0, 0);
    int cur = 0;
    for (int chunk = 0; chunk < 4; chunk++) {
        int col0 = chunk * 128;
        float acc[4][4][4] = {};
        for (int k0 = 0; k0 < K; k0 += 16) {
            bool last = (chunk == 3) && (k0 + 16 >= K);
            if (!last) {
                int nk = (k0 + 16 < K) ? k0 + 16 : 0;
                int nc = (k0 + 16 < K) ? col0 : col0 + 128;
                do_fill(cur ^ 1, nc, nk);
                cp_wait<1>();
            } else cp_wait<0>();
            __syncthreads();

            const __nv_bfloat16* base = dyn + cur * AT_BUF;
            const __nv_bfloat16* Ah = base;
            const __nv_bfloat16* Al = base + AT_T;
            const __nv_bfloat16* Wh = base + 2 * AT_T;
            const __nv_bfloat16* Wl = base + 3 * AT_T;

            unsigned b_h[4][2], b_l[4][2];
#pragma unroll
            for (int nb = 0; nb < 4; nb++) {
                int wc = warpCol + nb * 8 + g;
                b_h[nb][0] = *(const unsigned*)&Wh[wc * SPITCH + tg * 2];
                b_h[nb][1] = *(const unsigned*)&Wh[wc * SPITCH + tg * 2 + 8];
                b_l[nb][0] = *(const unsigned*)&Wl[wc * SPITCH + tg * 2];
                b_l[nb][1] = *(const unsigned*)&Wl[wc * SPITCH + tg * 2 + 8];
            }
#pragma unroll
            for (int mt = 0; mt < 4; mt++) {
                int row = warpRow + mt * 16;
                unsigned a_h[4], a_l[4];
                a_h[0] = *(const unsigned*)&Ah[(row + g) * SPITCH + tg * 2];
                a_h[1] = *(const unsigned*)&Ah[(row + g + 8) * SPITCH + tg * 2];
                a_h[2] = *(const unsigned*)&Ah[(row + g) * SPITCH + tg * 2 + 8];
                a_h[3] = *(const unsigned*)&Ah[(row + g + 8) * SPITCH + tg * 2 + 8];
                a_l[0] = *(const unsigned*)&Al[(row + g) * SPITCH + tg * 2];
                a_l[1] = *(const unsigned*)&Al[(row + g + 8) * SPITCH + tg * 2];
                a_l[2] = *(const unsigned*)&Al[(row + g) * SPITCH + tg * 2 + 8];
                a_l[3] = *(const unsigned*)&Al[(row + g + 8) * SPITCH + tg * 2 + 8];
#pragma unroll
                for (int nb = 0; nb < 4; nb++) {
                    mma_bf16(acc[mt][nb], a_h, b_h[nb]);
                    mma_bf16(acc[mt][nb], a_h, b_l[nb]);
                    mma_bf16(acc[mt][nb], a_l, b_h[nb]);
                }
            }
            __syncthreads();
            cur ^= 1;
        }
        // epilogue for this chunk's 128 d-columns
#pragma unroll
        for (int mt = 0; mt < 4; mt++) {
            int r0 = rowBase + warpRow + mt * 16 + g;
            int r1 = r0 + 8;
            int b0 = r0 / Lper, b1 = r1 / Lper;
#pragma unroll
            for (int nb = 0; nb < 4; nb++) {
                int d = col0 + warpCol + nb * 8 + tg * 2;
#pragma unroll
                for (int jj = 0; jj < 2; jj++) {
                    int dd = d + jj;
                    float vd = v[dd];
                    float wc = HAS_COV ? wcov[dd] : 0.f;
                    float f0 = acc[mt][nb][jj]     + dproj[(size_t)b0 * HH + dd];
                    float f1 = acc[mt][nb][2 + jj] + dproj[(size_t)b1 * HH + dd];
                    if (HAS_COV) { f0 += covr[2 * mt] * wc; f1 += covr[2 * mt + 1] * wc; }
                    rs[2 * mt]     += tanhf(f0) * vd;
                    rs[2 * mt + 1] += tanhf(f1) * vd;
                }
            }
        }
    }
#pragma unroll
    for (int i = 0; i < 8; i++) {
        float s = rs[i];
        s += __shfl_xor_sync(0xffffffffu, s, 1);
        s += __shfl_xor_sync(0xffffffffu, s, 2);
        int mt = i >> 1;
        int localRow = warpRow + mt * 16 + g + (i & 1) * 8;
        if (tg == 0) atomicAdd(&rowred[localRow], s);
    }
    __syncthreads();
    if (tid < 128) scores[rowBase + tid] = rowred[tid];
}

// ==================== bf16x3 mma GEMM, cp.async double-buffered (vocab logits) ====================
#define VB_A  (64 * SPITCH)
#define VB_SZ (4 * VB_A)
__global__ void __launch_bounds__(256)
mma_gemm_bias(const __nv_bfloat16* __restrict__ AH, const __nv_bfloat16* __restrict__ AL,
              const __nv_bfloat16* __restrict__ WH, const __nv_bfloat16* __restrict__ WL,
              const float* __restrict__ bias, float* __restrict__ C,
              int M, int N, int K) {
    __shared__ __nv_bfloat16 smem[2][VB_SZ];
    int tid = threadIdx.x;
    int wid = tid >> 5, lane = tid & 31;
    int warpM = wid & 3, warpN = wid >> 2;
    int warpRow = warpM * 16, warpCol = warpN * 32;
    int g = lane >> 2, tg = lane & 3;
    int rb = blockIdx.y * 64, cb = blockIdx.x * 64;

    int frow = tid >> 1, fhf = tid & 1;
    int wfrow = (tid - 128) >> 1, wfhf = (tid - 128) & 1;

    float acc[4][4] = {};

    auto do_fill = [&](int b, int k0) {
        if (tid < 128) {
            cp16(&smem[b][0 * VB_A + frow * SPITCH + fhf * 8],
                 &AH[(size_t)(rb + frow) * K + k0 + fhf * 8]);
            cp16(&smem[b][1 * VB_A + frow * SPITCH + fhf * 8],
                 &AL[(size_t)(rb + frow) * K + k0 + fhf * 8]);
        } else {
            bool ok = cb + wfrow < N;
            const __nv_bfloat16* srcH = &WH[(size_t)(ok ? cb + wfrow : 0) * K + k0 + wfhf * 8];
            const __nv_bfloat16* srcL = &WL[(size_t)(ok ? cb + wfrow : 0) * K + k0 + wfhf * 8];
            cp16z(&smem[b][2 * VB_A + wfrow * SPITCH + wfhf * 8], srcH, ok);
            cp16z(&smem[b][3 * VB_A + wfrow * SPITCH + wfhf * 8], srcL, ok);
        }
        CP_COMMIT();
    };

    do_fill(0, 0);
    int cur = 0;
    for (int k0 = 0; k0 < K; k0 += 16) {
        bool has_next = (k0 + 16 < K);
        if (has_next) { do_fill(cur ^ 1, k0 + 16); cp_wait<1>(); }
        else cp_wait<0>();
        __syncthreads();

        const __nv_bfloat16* Ah = &smem[cur][0 * VB_A];
        const __nv_bfloat16* Al = &smem[cur][1 * VB_A];
        const __nv_bfloat16* Wh = &smem[cur][2 * VB_A];
        const __nv_bfloat16* Wl = &smem[cur][3 * VB_A];

        unsigned a_h[4], a_l[4];
        a_h[0] = *(const unsigned*)&Ah[(warpRow + g) * SPITCH + tg * 2];
        a_h[1] = *(const unsigned*)&Ah[(warpRow + g + 8) * SPITCH + tg * 2];
        a_h[2] = *(const unsigned*)&Ah[(warpRow + g) * SPITCH + tg * 2 + 8];
        a_h[3] = *(const unsigned*)&Ah[(warpRow + g + 8) * SPITCH + tg * 2 + 8];
        a_l[0] = *(const unsigned*)&Al[(warpRow + g) * SPITCH + tg * 2];
        a_l[1] = *(const unsigned*)&Al[(warpRow + g + 8) * SPITCH + tg * 2];
        a_l[2] = *(const unsigned*)&Al[(warpRow + g) * SPITCH + tg * 2 + 8];
        a_l[3] = *(const unsigned*)&Al[(warpRow + g + 8) * SPITCH + tg * 2 + 8];
#pragma unroll
        for (int nb = 0; nb < 4; nb++) {
            int wc = warpCol + nb * 8 + g;
            unsigned bh[2], bl[2];
            bh[0] = *(const unsigned*)&Wh[wc * SPITCH + tg * 2];
            bh[1] = *(const unsigned*)&Wh[wc * SPITCH + tg * 2 + 8];
            bl[0] = *(const unsigned*)&Wl[wc * SPITCH + tg * 2];
            bl[1] = *(const unsigned*)&Wl[wc * SPITCH + tg * 2 + 8];
            mma_bf16(acc[nb], a_h, bh);
            mma_bf16(acc[nb], a_h, bl);
            mma_bf16(acc[nb], a_l, bh);
        }
        __syncthreads();
        cur ^= 1;
    }

#pragma unroll
    for (int nb = 0; nb < 4; nb++) {
        int col = cb + warpCol + nb * 8 + tg * 2;
        int r0 = rb + warpRow + g, r1 = r0 + 8;
        if (col < N) {
            float bs = bias ? bias[col] : 0.f;
            if (r0 < M) C[(size_t)r0 * N + col] = acc[nb][0] + bs;
            if (r1 < M) C[(size_t)r1 * N + col] = acc[nb][2] + bs;
        }
        if (col + 1 < N) {
            float bs = bias ? bias[col + 1] : 0.f;
            if (r0 < M) C[(size_t)r0 * N + col + 1] = acc[nb][1] + bs;
            if (r1 < M) C[(size_t)r1 * N + col + 1] = acc[nb][3] + bs;
        }
    }
}

// -------------------- GRU combine (PyTorch gate layout r,z,n) --------------------
__global__ void gru_kernel(const float* __restrict__ gi, const float* __restrict__ gh,
                           const float* __restrict__ h0, float* __restrict__ hlast,
                           float* __restrict__ cat, float* __restrict__ out_h) {
    int idx = blockIdx.x * 256 + threadIdx.x;
    if (idx >= BB * HH) return;
    int b = idx / HH, j = idx % HH;
    const float* gib = gi + (size_t)b * 3 * HH;
    const float* ghb = gh + (size_t)b * 3 * HH;
    float ir = gib[j], iz = gib[HH + j], in_ = gib[2 * HH + j];
    float hr = ghb[j], hz = ghb[HH + j], hn = ghb[2 * HH + j];
    float r = 1.f / (1.f + expf(-(ir + hr)));
    float z = 1.f / (1.f + expf(-(iz + hz)));
    float n = tanhf(in_ + r * hn);
    float hl = (1.f - z) * n + z * h0[idx];
    hlast[idx] = hl;
    cat[(size_t)b * 1536 + 1024 + j] = hl;
    out_h[idx] = hl;
}

// -------------------- softmax -> mask -> renormalize (+ coverage update) --------------------
__global__ void softmax_mask_kernel(const float* __restrict__ scores, const float* __restrict__ mask,
                                    const float* __restrict__ cov, float* __restrict__ attn_out,
                                    float* __restrict__ cov_out, int N) {
    __shared__ float buf[512];
    __shared__ float red[128];
    int b = blockIdx.x, tid = threadIdx.x;
    const float* s = scores + (size_t)b * N;
    float mx = -1e30f;
    for (int i = tid; i < N; i += 128) { float vv = s[i]; buf[i] = vv; mx = fmaxf(mx, vv); }
    red[tid] = mx; __syncthreads();
    for (int off = 64; off; off >>= 1) { if (tid < off) red[tid] = fmaxf(red[tid], red[tid + off]); __syncthreads(); }
    mx = red[0]; __syncthreads();
    float sum = 0.f;
    for (int i = tid; i < N; i += 128) { float e = expf(buf[i] - mx); buf[i] = e; sum += e; }
    red[tid] = sum; __syncthreads();
    for (int off = 64; off; off >>= 1) { if (tid < off) red[tid] += red[tid + off]; __syncthreads(); }
    sum = red[0]; __syncthreads();
    float s2 = 0.f;
    for (int i = tid; i < N; i += 128) { float t = (buf[i] / sum) * mask[(size_t)b * N + i]; buf[i] = t; s2 += t; }
    red[tid] = s2; __syncthreads();
    for (int off = 64; off; off >>= 1) { if (tid < off) red[tid] += red[tid + off]; __syncthreads(); }
    s2 = red[0];
    float inv = 1.f / (s2 + 1e-10f);
    for (int i = tid; i < N; i += 128) {
        float a = buf[i] * inv;
        attn_out[(size_t)b * N + i] = a;
        if (cov_out) cov_out[(size_t)b * N + i] = cov[(size_t)b * N + i] + a;
    }
}

// -------------------- context: ctx[b,m] = sum_l attn[b,l] * mem[b,l,m] --------------------
__global__ void context_kernel(const float* __restrict__ attn, const float* __restrict__ mem,
                               float* __restrict__ ctx_out, float* __restrict__ cat,
                               int Lc, int catOff) {
    __shared__ float a_s[512];
    int b = blockIdx.x;
    int m = blockIdx.y * 128 + threadIdx.x;
    for (int i = threadIdx.x; i < Lc; i += 128) a_s[i] = attn[(size_t)b * Lc + i];
    __syncthreads();
    const float* mb = mem + (size_t)b * Lc * MMD + m;
    float acc = 0.f;
#pragma unroll 4
    for (int l = 0; l < Lc; l++) acc += a_s[l] * mb[(size_t)l * MMD];
    if (ctx_out) ctx_out[(size_t)b * MMD + m] = acc;
    cat[(size_t)b * 1536 + catOff + m] = acc;
}

// -------------------- p_gen --------------------
__global__ void pgen_kernel(const float* __restrict__ cat, const float* __restrict__ yemb,
                            const float* __restrict__ pw, const float* __restrict__ pb,
                            float* __restrict__ pg_scr, float* __restrict__ pg_out) {
    __shared__ float red[256];
    int b = blockIdx.x, tid = threadIdx.x;
    float s = 0.f;
    for (int i = tid; i < 1536; i += 256) s += cat[(size_t)b * 1536 + i] * pw[i];
    for (int i = tid; i < EMB_; i += 256) s += yemb[(size_t)b * EMB_ + i] * pw[1536 + i];
    red[tid] = s; __syncthreads();
    for (int off = 128; off; off >>= 1) { if (tid < off) red[tid] += red[tid + off]; __syncthreads(); }
    if (tid == 0) {
        float p = 1.f / (1.f + expf(-(red[0] + pb[0])));
        pg_scr[b] = p;
        pg_out[b] = p;
    }
}

// -------------------- vocab softmax + p_gen mix + OOV scatter (1024 thr) --------------------
__global__ void __launch_bounds__(1024)
final_kernel(const float* __restrict__ logits, const float* __restrict__ pgen,
             const float* __restrict__ wattn, const int* __restrict__ src_oov,
             float* __restrict__ out_final) {
    __shared__ float red[1024];
    int b = blockIdx.x, tid = threadIdx.x;
    const float4* lg4 = (const float4*)(logits + (size_t)b * VV);
    const int n4 = VV / 4;
    float* fr = out_final + (size_t)b * VE;
    float2* fr2 = (float2*)fr;

    float mx = -1e30f;
    for (int i = tid; i < n4; i += 1024) {
        float4 x = lg4[i];
        mx = fmaxf(mx, fmaxf(fmaxf(x.x, x.y), fmaxf(x.z, x.w)));
    }
    red[tid] = mx; __syncthreads();
    for (int off = 512; off; off >>= 1) { if (tid < off) red[tid] = fmaxf(red[tid], red[tid + off]); __syncthreads(); }
    mx = red[0]; __syncthreads();

    float sum = 0.f;
    for (int i = tid; i < n4; i += 1024) {
        float4 x = lg4[i];
        float e0 = expf(x.x - mx), e1 = expf(x.y - mx);
        float e2 = expf(x.z - mx), e3 = expf(x.w - mx);
        sum += (e0 + e1) + (e2 + e3);
        fr2[2 * i]     = make_float2(e0, e1);
        fr2[2 * i + 1] = make_float2(e2, e3);
    }
    red[tid] = sum; __syncthreads();
    for (int off = 512; off; off >>= 1) { if (tid < off) red[tid] += red[tid + off]; __syncthreads(); }
    sum = red[0];
    float pg = pgen[b];
    float scale = pg / sum;
    for (int i = tid; i < n4; i += 1024) {
        float2 p0 = fr2[2 * i], p1 = fr2[2 * i + 1];
        p0.x *= scale; p0.y *= scale; p1.x *= scale; p1.y *= scale;
        fr2[2 * i] = p0; fr2[2 * i + 1] = p1;
    }
    for (int i = VV + tid; i < VE; i += 1024) fr[i] = 0.f;
    __syncthreads();
    float om = 1.f - pg;
    if (tid < LW) {
        int idx = src_oov[(size_t)b * LW + tid];
        atomicAdd(&fr[idx], om * wattn[(size_t)b * LW + tid]);
    }
}

// -------------------- launcher --------------------
extern "C" void kernel_launch(void* const* d_in, const int* in_sizes, int n_in,
                              void* d_out, int out_size) {
    (void)in_sizes; (void)n_in; (void)out_size;
    const float* h0   = (const float*)d_in[0];
    const float* wmem = (const float*)d_in[1];
    const float* smem_bank = (const float*)d_in[2];
    const float* wmask = (const float*)d_in[3];
    const float* smask = (const float*)d_in[4];
    const float* cov   = (const float*)d_in[5];
    const float* emb   = (const float*)d_in[6];
    const float* gwih  = (const float*)d_in[7];
    const float* gwhh  = (const float*)d_in[8];
    const float* gbih  = (const float*)d_in[9];
    const float* gbhh  = (const float*)d_in[10];
    const float* wmp   = (const float*)d_in[11];
    const float* wdpw  = (const float*)d_in[12];
    const float* wdpb  = (const float*)d_in[13];
    const float* wv    = (const float*)d_in[14];
    const float* wcp   = (const float*)d_in[15];
    const float* smp   = (const float*)d_in[16];
    const float* sdpw  = (const float*)d_in[17];
    const float* sdpb  = (const float*)d_in[18];
    const float* sv    = (const float*)d_in[19];
    const float* pgw   = (const float*)d_in[20];
    const float* pgb   = (const float*)d_in[21];
    const float* vd1w  = (const float*)d_in[22];
    const float* vd1b  = (const float*)d_in[23];
    const float* vd2w  = (const float*)d_in[24];
    const float* vd2b  = (const float*)d_in[25];
    const int*   y     = (const int*)d_in[26];
    const int*   soov  = (const int*)d_in[27];
    float* out = (float*)d_out;

    float *yemb, *gi, *gh, *hl, *dpw, *dps, *wsc, *ssc, *sat, *cat, *hid, *pg, *lg;
    __nv_bfloat16 *wmH, *wmL, *smH, *smL, *wpH, *wpL, *spH, *spL, *hdH, *hdL, *v2H, *v2L;
    cudaGetSymbolAddress((void**)&yemb, g_yemb);
    cudaGetSymbolAddress((void**)&gi,   g_gi);
    cudaGetSymbolAddress((void**)&gh,   g_gh);
    cudaGetSymbolAddress((void**)&hl,   g_hlast);
    cudaGetSymbolAddress((void**)&dpw,  g_dpw);
    cudaGetSymbolAddress((void**)&dps,  g_dps);
    cudaGetSymbolAddress((void**)&wsc,  g_wscores);
    cudaGetSymbolAddress((void**)&ssc,  g_sscores);
    cudaGetSymbolAddress((void**)&sat,  g_sattn);
    cudaGetSymbolAddress((void**)&cat,  g_cat);
    cudaGetSymbolAddress((void**)&hid,  g_hid);
    cudaGetSymbolAddress((void**)&pg,   g_pgen);
    cudaGetSymbolAddress((void**)&lg,   g_logits);
    cudaGetSymbolAddress((void**)&wmH,  g_wmemH);
    cudaGetSymbolAddress((void**)&wmL,  g_wmemL);
    cudaGetSymbolAddress((void**)&smH,  g_smemH);
    cudaGetSymbolAddress((void**)&smL,  g_smemL);
    cudaGetSymbolAddress((void**)&wpH,  g_wmpH);
    cudaGetSymbolAddress((void**)&wpL,  g_wmpL);
    cudaGetSymbolAddress((void**)&spH,  g_smpH);
    cudaGetSymbolAddress((void**)&spL,  g_smpL);
    cudaGetSymbolAddress((void**)&hdH,  g_hidH);
    cudaGetSymbolAddress((void**)&hdL,  g_hidL);
    cudaGetSymbolAddress((void**)&v2H,  g_vd2wH);
    cudaGetSymbolAddress((void**)&v2L,  g_vd2wL);

    cudaFuncSetAttribute(attn_scores_mma<true>,
                         cudaFuncAttributeMaxDynamicSharedMemorySize, AT_DYN);
    cudaFuncSetAttribute(attn_scores_mma<false>,
                         cudaFuncAttributeMaxDynamicSharedMemorySize, AT_DYN);

    // 0: prep — gigh GEMMs + all big presplits, one launch
    prep_kernel<<<NB_PREP, 256>>>(emb, y, h0, gwih, gbih, gwhh, gbhh, gi, gh, yemb,
                                  wmem, wmH, wmL, smem_bank, smH, smL,
                                  wmp, wpH, wpL, smp, spH, spL, vd2w, v2H, v2L);
    // 1: GRU combine
    gru_kernel<<<(BB * HH + 255) / 256, 256>>>(gi, gh, h0, hl, cat, out + OUT_H);
    // 2: fused decoder-state projections
    dpwdps_kernel<<<dim3(8, 2, 2), 256>>>(hl, wdpw, wdpb, sdpw, sdpb, dpw, dps);
    // 3: word attention scores  <-- profiled launch
    attn_scores_mma<true ><<<(BB * LW) / 128, 256, AT_DYN>>>(wmH, wmL, wpH, wpL, dpw, wv, wcp, cov, wsc, LW);
    // 4: sentence attention scores
    attn_scores_mma<false><<<(BB * SSL) / 128, 256, AT_DYN>>>(smH, smL, spH, spL, dps, sv, nullptr, nullptr, ssc, SSL);

    // softmax + mask + renorm (+ coverage output for word)
    softmax_mask_kernel<<<BB, 128>>>(wsc, wmask, cov, out + OUT_WATTN, out + OUT_WCOV, LW);
    softmax_mask_kernel<<<BB, 128>>>(ssc, smask, nullptr, sat, nullptr, SSL);

    // contexts
    context_kernel<<<dim3(BB, 4), 128>>>(out + OUT_WATTN, wmem, out + OUT_WCTX, cat, LW, 0);
    context_kernel<<<dim3(BB, 4), 128>>>(sat, smem_bank, nullptr, cat, SSL, 512);

    // p_gen
    pgen_kernel<<<BB, 256>>>(cat, yemb, pgw, pgb, pg, out + OUT_PGEN);

    // vocab head
    gemm_bias_kernel<<<dim3(8, 2), 256>>>(cat, vd1w, vd1b, hid, BB, HH, 3 * HH);
    presplit_kernel<<<(BB * HH / 4 + 255) / 256, 256>>>(hid, hdH, hdL, BB * HH / 4);
    mma_gemm_bias<<<dim3((VV + 63) / 64, 2), 256>>>(hdH, hdL, v2H, v2L, vd2b, lg, BB, VV, HH);

    // vocab softmax, p_gen mix, zeros for OOV slots, scatter-add of copy dist
    final_kernel<<<BB, 1024>>>(lg, pg, out + OUT_WATTN, soov, out + OUT_FINAL);
}

// round 11
// speedup vs baseline: 1.1965x; 1.1965x over previous
#include <cuda_runtime.h>
#include <cuda_bf16.h>
#include <math.h>

// Problem constants
#define BB   128
#define LW   400
#define SSL  30
#define VV   50000
#define EMB_ 128
#define HH   512
#define MMD  512
#define OOVN 30
#define VE   (VV + OOVN)   // 50030

// Output layout: concat of (final_dist, h_next, word_ctx, word_attn, p_gen, word_cov)
#define OUT_FINAL 0
#define OUT_H     (BB * VE)
#define OUT_WCTX  (OUT_H + BB * HH)
#define OUT_WATTN (OUT_WCTX + BB * MMD)
#define OUT_PGEN  (OUT_WATTN + BB * LW)
#define OUT_WCOV  (OUT_PGEN + BB)

#define SPITCH 40   // smem bf16 row pitch (conflict-free frag loads; 80B rows)

// -------------------- scratch (no allocations allowed) --------------------
__device__ float g_yemb[BB * EMB_];
__device__ float g_gi[BB * 3 * HH];
__device__ float g_gh[BB * 3 * HH];
__device__ float g_hlast[BB * HH];
__device__ float g_dpw[BB * HH];
__device__ float g_dps[BB * HH];
__device__ float g_wscores[BB * LW];
__device__ float g_sscores[BB * SSL];
__device__ float g_sattn[BB * SSL];
__device__ float g_cat[BB * 3 * HH];     // [word_ctx | sent_ctx | h_last]
__device__ float g_hid[BB * HH];
__device__ float g_pgen[BB];
__device__ float g_logits[(size_t)BB * VV];

// pre-split bf16 (hi, lo) buffers
__device__ __nv_bfloat16 g_wmemH[(size_t)BB * LW * MMD];
__device__ __nv_bfloat16 g_wmemL[(size_t)BB * LW * MMD];
__device__ __nv_bfloat16 g_smemH[BB * SSL * MMD];
__device__ __nv_bfloat16 g_smemL[BB * SSL * MMD];
__device__ __nv_bfloat16 g_wmpH[HH * MMD];
__device__ __nv_bfloat16 g_wmpL[HH * MMD];
__device__ __nv_bfloat16 g_smpH[HH * MMD];
__device__ __nv_bfloat16 g_smpL[HH * MMD];
__device__ __nv_bfloat16 g_hidH[BB * HH];
__device__ __nv_bfloat16 g_hidL[BB * HH];
__device__ __nv_bfloat16 g_vd2wH[(size_t)VV * HH];
__device__ __nv_bfloat16 g_vd2wL[(size_t)VV * HH];

// -------------------- helpers --------------------
__device__ __forceinline__ unsigned pack_bf2(__nv_bfloat16 a, __nv_bfloat16 b) {
    __nv_bfloat162 t(a, b);
    return *(unsigned*)&t;
}
__device__ __forceinline__ void split1(float x, __nv_bfloat16& h, __nv_bfloat16& l) {
    h = __float2bfloat16_rn(x);
    l = __float2bfloat16_rn(x - __bfloat162float(h));
}
__device__ __forceinline__ void split2(float x, float y, unsigned& hi2, unsigned& lo2) {
    __nv_bfloat16 hx, lx, hy, ly;
    split1(x, hx, lx); split1(y, hy, ly);
    hi2 = pack_bf2(hx, hy);
    lo2 = pack_bf2(lx, ly);
}
__device__ __forceinline__ void mma_bf16(float* c, const unsigned* a, const unsigned* b) {
    asm volatile(
        "mma.sync.aligned.m16n8k16.row.col.f32.bf16.bf16.f32 "
        "{%0,%1,%2,%3}, {%4,%5,%6,%7}, {%8,%9}, {%0,%1,%2,%3};"
        : "+f"(c[0]), "+f"(c[1]), "+f"(c[2]), "+f"(c[3])
        : "r"(a[0]), "r"(a[1]), "r"(a[2]), "r"(a[3]), "r"(b[0]), "r"(b[1]));
}
// cp.async 16B
__device__ __forceinline__ void cp16(void* sptr, const void* gptr) {
    unsigned sa = (unsigned)__cvta_generic_to_shared(sptr);
    asm volatile("cp.async.cg.shared.global [%0], [%1], 16;" :: "r"(sa), "l"(gptr));
}
__device__ __forceinline__ void cp16z(void* sptr, const void* gptr, bool ok) {
    unsigned sa = (unsigned)__cvta_generic_to_shared(sptr);
    int sz = ok ? 16 : 0;
    asm volatile("cp.async.cg.shared.global [%0], [%1], 16, %2;" :: "r"(sa), "l"(gptr), "r"(sz));
}
#define CP_COMMIT() asm volatile("cp.async.commit_group;")
template <int N> __device__ __forceinline__ void cp_wait() {
    asm volatile("cp.async.wait_group %0;" :: "n"(N));
}

// -------------------- hid presplit (separate small launch) --------------------
__global__ void presplit_kernel(const float* __restrict__ src, __nv_bfloat16* __restrict__ dh,
                                __nv_bfloat16* __restrict__ dl, int n4) {
    int i = blockIdx.x * 256 + threadIdx.x;
    if (i >= n4) return;
    float4 x = ((const float4*)src)[i];
    unsigned h01, l01, h23, l23;
    split2(x.x, x.y, h01, l01);
    split2(x.z, x.w, h23, l23);
    ((uint2*)dh)[i] = make_uint2(h01, h23);
    ((uint2*)dl)[i] = make_uint2(l01, l23);
}

// ==================== prep: gigh GEMMs + ALL big presplits, one launch ====================
#define NB_GIGH 96
#define NB_WMEM 25600   // BB*LW*MMD/1024
#define NB_SMEM 1920    // BB*SSL*MMD/1024
#define NB_WMP  256     // HH*MMD/1024
#define NB_SMP  256
#define NB_VD2W 25000   // VV*HH/1024
#define NB_PREP (NB_GIGH + NB_WMEM + NB_SMEM + NB_WMP + NB_SMP + NB_VD2W)

__global__ void prep_kernel(
    const float* __restrict__ emb, const int* __restrict__ y, const float* __restrict__ h0,
    const float* __restrict__ gwih, const float* __restrict__ gbih,
    const float* __restrict__ gwhh, const float* __restrict__ gbhh,
    float* __restrict__ gi, float* __restrict__ gh, float* __restrict__ yemb,
    const float* __restrict__ wmem, __nv_bfloat16* __restrict__ wmH, __nv_bfloat16* __restrict__ wmL,
    const float* __restrict__ smemb, __nv_bfloat16* __restrict__ smH, __nv_bfloat16* __restrict__ smL,
    const float* __restrict__ wmp, __nv_bfloat16* __restrict__ wpH, __nv_bfloat16* __restrict__ wpL,
    const float* __restrict__ smp, __nv_bfloat16* __restrict__ spH, __nv_bfloat16* __restrict__ spL,
    const float* __restrict__ vd2w, __nv_bfloat16* __restrict__ v2H, __nv_bfloat16* __restrict__ v2L)
{
    __shared__ float As[16][68];
    __shared__ float Ws[16][68];
    int bid = blockIdx.x;
    int tid = threadIdx.x;

    if (bid >= NB_GIGH) {
        // ---- presplit region ----
        int pb = bid - NB_GIGH;
        const float* src; __nv_bfloat16* dh; __nv_bfloat16* dl; int base;
        if (pb < NB_WMEM)                       { src = wmem;  dh = wmH; dl = wmL; base = pb; }
        else if (pb < NB_WMEM + NB_SMEM)        { src = smemb; dh = smH; dl = smL; base = pb - NB_WMEM; }
        else if (pb < NB_WMEM + NB_SMEM + NB_WMP) { src = wmp; dh = wpH; dl = wpL; base = pb - NB_WMEM - NB_SMEM; }
        else if (pb < NB_WMEM + NB_SMEM + NB_WMP + NB_SMP) { src = smp; dh = spH; dl = spL; base = pb - NB_WMEM - NB_SMEM - NB_WMP; }
        else { src = vd2w; dh = v2H; dl = v2L; base = pb - NB_WMEM - NB_SMEM - NB_WMP - NB_SMP; }
        size_t i = (size_t)base * 256 + tid;
        float4 x = ((const float4*)src)[i];
        unsigned h01, l01, h23, l23;
        split2(x.x, x.y, h01, l01);
        split2(x.z, x.w, h23, l23);
        ((uint2*)dh)[i] = make_uint2(h01, h23);
        ((uint2*)dl)[i] = make_uint2(l01, l23);
        return;
    }

    // ---- gigh GEMM: z=0 -> gi (A = emb[y]); z=1 -> gh (A = h0) ----
    int gx = bid % 24, gy = (bid / 24) % 2, gz = bid / 48;
    int tx = tid & 15, ty = tid >> 4;
    int K = gz ? HH : EMB_;
    const float* W = gz ? gwhh : gwih;
    const float* bias = gz ? gbhh : gbih;
    float* C = gz ? gh : gi;
    int rb = gy * 64, cb = gx * 64;
    int lr = tid >> 2, kq = tid & 3;
    int yrow = gz ? 0 : y[rb + lr];
    const float* Arow = gz ? &h0[(size_t)(rb + lr) * HH] : &emb[(size_t)yrow * EMB_];
    float acc[4][4] = {};

    for (int k0 = 0; k0 < K; k0 += 16) {
        float4 a4 = *(const float4*)&Arow[k0 + kq * 4];
        float4 w4 = *(const float4*)&W[(size_t)(cb + lr) * K + k0 + kq * 4];
        if (gz == 0 && gx == 0)
            *(float4*)&yemb[(size_t)(rb + lr) * EMB_ + k0 + kq * 4] = a4;
        As[kq * 4 + 0][lr] = a4.x; As[kq * 4 + 1][lr] = a4.y;
        As[kq * 4 + 2][lr] = a4.z; As[kq * 4 + 3][lr] = a4.w;
        Ws[kq * 4 + 0][lr] = w4.x; Ws[kq * 4 + 1][lr] = w4.y;
        Ws[kq * 4 + 2][lr] = w4.z; Ws[kq * 4 + 3][lr] = w4.w;
        __syncthreads();
#pragma unroll
        for (int kk = 0; kk < 16; kk++) {
            float4 a = *(const float4*)&As[kk][ty * 4];
            float4 w = *(const float4*)&Ws[kk][tx * 4];
            acc[0][0] += a.x * w.x; acc[0][1] += a.x * w.y; acc[0][2] += a.x * w.z; acc[0][3] += a.x * w.w;
            acc[1][0] += a.y * w.x; acc[1][1] += a.y * w.y; acc[1][2] += a.y * w.z; acc[1][3] += a.y * w.w;
            acc[2][0] += a.z * w.x; acc[2][1] += a.z * w.y; acc[2][2] += a.z * w.z; acc[2][3] += a.z * w.w;
            acc[3][0] += a.w * w.x; acc[3][1] += a.w * w.y; acc[3][2] += a.w * w.z; acc[3][3] += a.w * w.w;
        }
        __syncthreads();
    }
#pragma unroll
    for (int i = 0; i < 4; i++) {
        int row = rb + ty * 4 + i;
#pragma unroll
        for (int j = 0; j < 4; j++) {
            int col = cb + tx * 4 + j;
            C[(size_t)row * (3 * HH) + col] = acc[i][j] + bias[col];
        }
    }
}

// -------------------- fused decoder projections: z=0 -> dpw, z=1 -> dps --------------------
__global__ void dpwdps_kernel(const float* __restrict__ hl,
                              const float* __restrict__ wdpw, const float* __restrict__ wdpb,
                              const float* __restrict__ sdpw, const float* __restrict__ sdpb,
                              float* __restrict__ dpw, float* __restrict__ dps) {
    __shared__ float As[16][68];
    __shared__ float Ws[16][68];
    int tid = threadIdx.x;
    int tx = tid & 15, ty = tid >> 4;
    int z = blockIdx.z;
    const float* W = z ? sdpw : wdpw;
    const float* bias = z ? sdpb : wdpb;
    float* C = z ? dps : dpw;
    const int K = HH;
    int rb = blockIdx.y * 64, cb = blockIdx.x * 64;
    int lr = tid >> 2, kq = tid & 3;
    float acc[4][4] = {};

    for (int k0 = 0; k0 < K; k0 += 16) {
        float4 a4 = *(const float4*)&hl[(size_t)(rb + lr) * K + k0 + kq * 4];
        float4 w4 = *(const float4*)&W[(size_t)(cb + lr) * K + k0 + kq * 4];
        As[kq * 4 + 0][lr] = a4.x; As[kq * 4 + 1][lr] = a4.y;
        As[kq * 4 + 2][lr] = a4.z; As[kq * 4 + 3][lr] = a4.w;
        Ws[kq * 4 + 0][lr] = w4.x; Ws[kq * 4 + 1][lr] = w4.y;
        Ws[kq * 4 + 2][lr] = w4.z; Ws[kq * 4 + 3][lr] = w4.w;
        __syncthreads();
#pragma unroll
        for (int kk = 0; kk < 16; kk++) {
            float4 a = *(const float4*)&As[kk][ty * 4];
            float4 w = *(const float4*)&Ws[kk][tx * 4];
            acc[0][0] += a.x * w.x; acc[0][1] += a.x * w.y; acc[0][2] += a.x * w.z; acc[0][3] += a.x * w.w;
            acc[1][0] += a.y * w.x; acc[1][1] += a.y * w.y; acc[1][2] += a.y * w.z; acc[1][3] += a.y * w.w;
            acc[2][0] += a.z * w.x; acc[2][1] += a.z * w.y; acc[2][2] += a.z * w.z; acc[2][3] += a.z * w.w;
            acc[3][0] += a.w * w.x; acc[3][1] += a.w * w.y; acc[3][2] += a.w * w.z; acc[3][3] += a.w * w.w;
        }
        __syncthreads();
    }
#pragma unroll
    for (int i = 0; i < 4; i++) {
        int row = rb + ty * 4 + i;
#pragma unroll
        for (int j = 0; j < 4; j++) {
            int col = cb + tx * 4 + j;
            C[(size_t)row * HH + col] = acc[i][j] + bias[col];
        }
    }
}

// -------------------- generic scalar SGEMM (hid) --------------------
__global__ void gemm_bias_kernel(const float* __restrict__ A, const float* __restrict__ W,
                                 const float* __restrict__ bias, float* __restrict__ C,
                                 int M, int N, int K) {
    __shared__ float As[16][68];
    __shared__ float Ws[16][68];
    int tid = threadIdx.x;
    int tx = tid & 15, ty = tid >> 4;
    int rb = blockIdx.y * 64, cb = blockIdx.x * 64;
    int lr = tid >> 2, kq = tid & 3;
    float acc[4][4] = {};

    for (int k0 = 0; k0 < K; k0 += 16) {
        float4 a4 = make_float4(0.f, 0.f, 0.f, 0.f);
        float4 w4 = make_float4(0.f, 0.f, 0.f, 0.f);
        if (rb + lr < M) a4 = *(const float4*)&A[(size_t)(rb + lr) * K + k0 + kq * 4];
        if (cb + lr < N) w4 = *(const float4*)&W[(size_t)(cb + lr) * K + k0 + kq * 4];
        As[kq * 4 + 0][lr] = a4.x; As[kq * 4 + 1][lr] = a4.y;
        As[kq * 4 + 2][lr] = a4.z; As[kq * 4 + 3][lr] = a4.w;
        Ws[kq * 4 + 0][lr] = w4.x; Ws[kq * 4 + 1][lr] = w4.y;
        Ws[kq * 4 + 2][lr] = w4.z; Ws[kq * 4 + 3][lr] = w4.w;
        __syncthreads();
#pragma unroll
        for (int kk = 0; kk < 16; kk++) {
            float4 a = *(const float4*)&As[kk][ty * 4];
            float4 w = *(const float4*)&Ws[kk][tx * 4];
            acc[0][0] += a.x * w.x; acc[0][1] += a.x * w.y; acc[0][2] += a.x * w.z; acc[0][3] += a.x * w.w;
            acc[1][0] += a.y * w.x; acc[1][1] += a.y * w.y; acc[1][2] += a.y * w.z; acc[1][3] += a.y * w.w;
            acc[2][0] += a.z * w.x; acc[2][1] += a.z * w.y; acc[2][2] += a.z * w.z; acc[2][3] += a.z * w.w;
            acc[3][0] += a.w * w.x; acc[3][1] += a.w * w.y; acc[3][2] += a.w * w.z; acc[3][3] += a.w * w.w;
        }
        __syncthreads();
    }
#pragma unroll
    for (int i = 0; i < 4; i++) {
        int row = rb + ty * 4 + i;
        if (row >= M) continue;
#pragma unroll
        for (int j = 0; j < 4; j++) {
            int col = cb + tx * 4 + j;
            if (col < N) C[(size_t)row * N + col] = acc[i][j] + (bias ? bias[col] : 0.f);
        }
    }
}

// ==================== attention scores: chunk-parallel 128x128 tiles, cp.async, bf16x3 ====================
// Block (bx, by): rows bx*128..+128, d-columns by*128..+128. Partial row-scores
// accumulated into pre-zeroed scores[] via atomicAdd. Serial depth = 32 k-stages.
#define AT_T   (128 * SPITCH)                // 5120 elems per half-tile
#define AT_BUF (4 * AT_T)                    // Ah|Al|Wh|Wl
#define AT_DYN (2 * AT_BUF * 2)              // 81920 bytes
template <bool HAS_COV>
__global__ void __launch_bounds__(256, 2)
attn_scores_mma(const __nv_bfloat16* __restrict__ memH, const __nv_bfloat16* __restrict__ memL,
                const __nv_bfloat16* __restrict__ WmH, const __nv_bfloat16* __restrict__ WmL,
                const float* __restrict__ dproj, const float* __restrict__ v,
                const float* __restrict__ wcov, const float* __restrict__ cov,
                float* __restrict__ scores, int Lper) {
    const int K = 512;
    extern __shared__ __nv_bfloat16 dyn[];
    __shared__ float rowred[128];

    int tid = threadIdx.x;
    int wid = tid >> 5, lane = tid & 31;
    int rg = wid >> 2, cg = wid & 3;         // 2 row-groups x 4 col-groups
    int warpRow = rg * 64, warpCol = cg * 32;
    int g = lane >> 2, tg = lane & 3;
    int rowBase = blockIdx.x * 128;
    int col0 = blockIdx.y * 128;
    int frow = tid & 127, fhf = tid >> 7;

    if (tid < 128) rowred[tid] = 0.f;

    float covr[8];
    if (HAS_COV) {
#pragma unroll
        for (int mt = 0; mt < 4; mt++) {
            covr[2 * mt]     = cov[rowBase + warpRow + mt * 16 + g];
            covr[2 * mt + 1] = cov[rowBase + warpRow + mt * 16 + g + 8];
        }
    }
    float rs[8] = {};

    auto do_fill = [&](int b, int k0) {
        __nv_bfloat16* base = dyn + b * AT_BUF;
        size_t ga = (size_t)(rowBase + frow) * K + k0 + fhf * 8;
        size_t gw = (size_t)(col0 + frow) * K + k0 + fhf * 8;
        unsigned so = frow * SPITCH + fhf * 8;
        cp16(&base[0 * AT_T + so], &memH[ga]);
        cp16(&base[1 * AT_T + so], &memL[ga]);
        cp16(&base[2 * AT_T + so], &WmH[gw]);
        cp16(&base[3 * AT_T + so], &WmL[gw]);
        CP_COMMIT();
    };

    do_fill(0, 0);
    int cur = 0;
    float acc[4][4][4] = {};
    for (int k0 = 0; k0 < K; k0 += 16) {
        bool has_next = (k0 + 16 < K);
        if (has_next) { do_fill(cur ^ 1, k0 + 16); cp_wait<1>(); }
        else cp_wait<0>();
        __syncthreads();

        const __nv_bfloat16* base = dyn + cur * AT_BUF;
        const __nv_bfloat16* Ah = base;
        const __nv_bfloat16* Al = base + AT_T;
        const __nv_bfloat16* Wh = base + 2 * AT_T;
        const __nv_bfloat16* Wl = base + 3 * AT_T;

        unsigned b_h[4][2], b_l[4][2];
#pragma unroll
        for (int nb = 0; nb < 4; nb++) {
            int wc = warpCol + nb * 8 + g;
            b_h[nb][0] = *(const unsigned*)&Wh[wc * SPITCH + tg * 2];
            b_h[nb][1] = *(const unsigned*)&Wh[wc * SPITCH + tg * 2 + 8];
            b_l[nb][0] = *(const unsigned*)&Wl[wc * SPITCH + tg * 2];
            b_l[nb][1] = *(const unsigned*)&Wl[wc * SPITCH + tg * 2 + 8];
        }
#pragma unroll
        for (int mt = 0; mt < 4; mt++) {
            int row = warpRow + mt * 16;
            unsigned a_h[4], a_l[4];
            a_h[0] = *(const unsigned*)&Ah[(row + g) * SPITCH + tg * 2];
            a_h[1] = *(const unsigned*)&Ah[(row + g + 8) * SPITCH + tg * 2];
            a_h[2] = *(const unsigned*)&Ah[(row + g) * SPITCH + tg * 2 + 8];
            a_h[3] = *(const unsigned*)&Ah[(row + g + 8) * SPITCH + tg * 2 + 8];
            a_l[0] = *(const unsigned*)&Al[(row + g) * SPITCH + tg * 2];
            a_l[1] = *(const unsigned*)&Al[(row + g + 8) * SPITCH + tg * 2];
            a_l[2] = *(const unsigned*)&Al[(row + g) * SPITCH + tg * 2 + 8];
            a_l[3] = *(const unsigned*)&Al[(row + g + 8) * SPITCH + tg * 2 + 8];
#pragma unroll
            for (int nb = 0; nb < 4; nb++) {
                mma_bf16(acc[mt][nb], a_h, b_h[nb]);
                mma_bf16(acc[mt][nb], a_h, b_l[nb]);
                mma_bf16(acc[mt][nb], a_l, b_h[nb]);
            }
        }
        __syncthreads();
        cur ^= 1;
    }
    // epilogue: tanh + v-weighted partial sums over this block's 128 d-columns
#pragma unroll
    for (int mt = 0; mt < 4; mt++) {
        int r0 = rowBase + warpRow + mt * 16 + g;
        int r1 = r0 + 8;
        int b0 = r0 / Lper, b1 = r1 / Lper;
#pragma unroll
        for (int nb = 0; nb < 4; nb++) {
            int d = col0 + warpCol + nb * 8 + tg * 2;
#pragma unroll
            for (int jj = 0; jj < 2; jj++) {
                int dd = d + jj;
                float vd = v[dd];
                float wc = HAS_COV ? wcov[dd] : 0.f;
                float f0 = acc[mt][nb][jj]     + dproj[(size_t)b0 * HH + dd];
                float f1 = acc[mt][nb][2 + jj] + dproj[(size_t)b1 * HH + dd];
                if (HAS_COV) { f0 += covr[2 * mt] * wc; f1 += covr[2 * mt + 1] * wc; }
                rs[2 * mt]     += tanhf(f0) * vd;
                rs[2 * mt + 1] += tanhf(f1) * vd;
            }
        }
    }
#pragma unroll
    for (int i = 0; i < 8; i++) {
        float s = rs[i];
        s += __shfl_xor_sync(0xffffffffu, s, 1);
        s += __shfl_xor_sync(0xffffffffu, s, 2);
        int mt = i >> 1;
        int localRow = warpRow + mt * 16 + g + (i & 1) * 8;
        if (tg == 0) atomicAdd(&rowred[localRow], s);
    }
    __syncthreads();
    if (tid < 128) atomicAdd(&scores[rowBase + tid], rowred[tid]);
}

// ==================== bf16x3 mma GEMM, cp.async double-buffered (vocab logits) ====================
#define VB_A  (64 * SPITCH)
#define VB_SZ (4 * VB_A)
__global__ void __launch_bounds__(256)
mma_gemm_bias(const __nv_bfloat16* __restrict__ AH, const __nv_bfloat16* __restrict__ AL,
              const __nv_bfloat16* __restrict__ WH, const __nv_bfloat16* __restrict__ WL,
              const float* __restrict__ bias, float* __restrict__ C,
              int M, int N, int K) {
    __shared__ __nv_bfloat16 smem[2][VB_SZ];
    int tid = threadIdx.x;
    int wid = tid >> 5, lane = tid & 31;
    int warpM = wid & 3, warpN = wid >> 2;
    int warpRow = warpM * 16, warpCol = warpN * 32;
    int g = lane >> 2, tg = lane & 3;
    int rb = blockIdx.y * 64, cb = blockIdx.x * 64;

    int frow = tid >> 1, fhf = tid & 1;
    int wfrow = (tid - 128) >> 1, wfhf = (tid - 128) & 1;

    float acc[4][4] = {};

    auto do_fill = [&](int b, int k0) {
        if (tid < 128) {
            cp16(&smem[b][0 * VB_A + frow * SPITCH + fhf * 8],
                 &AH[(size_t)(rb + frow) * K + k0 + fhf * 8]);
            cp16(&smem[b][1 * VB_A + frow * SPITCH + fhf * 8],
                 &AL[(size_t)(rb + frow) * K + k0 + fhf * 8]);
        } else {
            bool ok = cb + wfrow < N;
            const __nv_bfloat16* srcH = &WH[(size_t)(ok ? cb + wfrow : 0) * K + k0 + wfhf * 8];
            const __nv_bfloat16* srcL = &WL[(size_t)(ok ? cb + wfrow : 0) * K + k0 + wfhf * 8];
            cp16z(&smem[b][2 * VB_A + wfrow * SPITCH + wfhf * 8], srcH, ok);
            cp16z(&smem[b][3 * VB_A + wfrow * SPITCH + wfhf * 8], srcL, ok);
        }
        CP_COMMIT();
    };

    do_fill(0, 0);
    int cur = 0;
    for (int k0 = 0; k0 < K; k0 += 16) {
        bool has_next = (k0 + 16 < K);
        if (has_next) { do_fill(cur ^ 1, k0 + 16); cp_wait<1>(); }
        else cp_wait<0>();
        __syncthreads();

        const __nv_bfloat16* Ah = &smem[cur][0 * VB_A];
        const __nv_bfloat16* Al = &smem[cur][1 * VB_A];
        const __nv_bfloat16* Wh = &smem[cur][2 * VB_A];
        const __nv_bfloat16* Wl = &smem[cur][3 * VB_A];

        unsigned a_h[4], a_l[4];
        a_h[0] = *(const unsigned*)&Ah[(warpRow + g) * SPITCH + tg * 2];
        a_h[1] = *(const unsigned*)&Ah[(warpRow + g + 8) * SPITCH + tg * 2];
        a_h[2] = *(const unsigned*)&Ah[(warpRow + g) * SPITCH + tg * 2 + 8];
        a_h[3] = *(const unsigned*)&Ah[(warpRow + g + 8) * SPITCH + tg * 2 + 8];
        a_l[0] = *(const unsigned*)&Al[(warpRow + g) * SPITCH + tg * 2];
        a_l[1] = *(const unsigned*)&Al[(warpRow + g + 8) * SPITCH + tg * 2];
        a_l[2] = *(const unsigned*)&Al[(warpRow + g) * SPITCH + tg * 2 + 8];
        a_l[3] = *(const unsigned*)&Al[(warpRow + g + 8) * SPITCH + tg * 2 + 8];
#pragma unroll
        for (int nb = 0; nb < 4; nb++) {
            int wc = warpCol + nb * 8 + g;
            unsigned bh[2], bl[2];
            bh[0] = *(const unsigned*)&Wh[wc * SPITCH + tg * 2];
            bh[1] = *(const unsigned*)&Wh[wc * SPITCH + tg * 2 + 8];
            bl[0] = *(const unsigned*)&Wl[wc * SPITCH + tg * 2];
            bl[1] = *(const unsigned*)&Wl[wc * SPITCH + tg * 2 + 8];
            mma_bf16(acc[nb], a_h, bh);
            mma_bf16(acc[nb], a_h, bl);
            mma_bf16(acc[nb], a_l, bh);
        }
        __syncthreads();
        cur ^= 1;
    }

#pragma unroll
    for (int nb = 0; nb < 4; nb++) {
        int col = cb + warpCol + nb * 8 + tg * 2;
        int r0 = rb + warpRow + g, r1 = r0 + 8;
        if (col < N) {
            float bs = bias ? bias[col] : 0.f;
            if (r0 < M) C[(size_t)r0 * N + col] = acc[nb][0] + bs;
            if (r1 < M) C[(size_t)r1 * N + col] = acc[nb][2] + bs;
        }
        if (col + 1 < N) {
            float bs = bias ? bias[col + 1] : 0.f;
            if (r0 < M) C[(size_t)r0 * N + col + 1] = acc[nb][1] + bs;
            if (r1 < M) C[(size_t)r1 * N + col + 1] = acc[nb][3] + bs;
        }
    }
}

// -------------------- GRU combine + zero attention score buffers --------------------
__global__ void gru_kernel(const float* __restrict__ gi, const float* __restrict__ gh,
                           const float* __restrict__ h0, float* __restrict__ hlast,
                           float* __restrict__ cat, float* __restrict__ out_h,
                           float* __restrict__ wsc, float* __restrict__ ssc) {
    int idx = blockIdx.x * 256 + threadIdx.x;
    if (idx >= BB * HH) return;
    if (idx < BB * LW) wsc[idx] = 0.f;
    if (idx < BB * SSL) ssc[idx] = 0.f;
    int b = idx / HH, j = idx % HH;
    const float* gib = gi + (size_t)b * 3 * HH;
    const float* ghb = gh + (size_t)b * 3 * HH;
    float ir = gib[j], iz = gib[HH + j], in_ = gib[2 * HH + j];
    float hr = ghb[j], hz = ghb[HH + j], hn = ghb[2 * HH + j];
    float r = 1.f / (1.f + expf(-(ir + hr)));
    float z = 1.f / (1.f + expf(-(iz + hz)));
    float n = tanhf(in_ + r * hn);
    float hl = (1.f - z) * n + z * h0[idx];
    hlast[idx] = hl;
    cat[(size_t)b * 1536 + 1024 + j] = hl;
    out_h[idx] = hl;
}

// -------------------- softmax -> mask -> renormalize (+ coverage update) --------------------
__global__ void softmax_mask_kernel(const float* __restrict__ scores, const float* __restrict__ mask,
                                    const float* __restrict__ cov, float* __restrict__ attn_out,
                                    float* __restrict__ cov_out, int N) {
    __shared__ float buf[512];
    __shared__ float red[128];
    int b = blockIdx.x, tid = threadIdx.x;
    const float* s = scores + (size_t)b * N;
    float mx = -1e30f;
    for (int i = tid; i < N; i += 128) { float vv = s[i]; buf[i] = vv; mx = fmaxf(mx, vv); }
    red[tid] = mx; __syncthreads();
    for (int off = 64; off; off >>= 1) { if (tid < off) red[tid] = fmaxf(red[tid], red[tid + off]); __syncthreads(); }
    mx = red[0]; __syncthreads();
    float sum = 0.f;
    for (int i = tid; i < N; i += 128) { float e = expf(buf[i] - mx); buf[i] = e; sum += e; }
    red[tid] = sum; __syncthreads();
    for (int off = 64; off; off >>= 1) { if (tid < off) red[tid] += red[tid + off]; __syncthreads(); }
    sum = red[0]; __syncthreads();
    float s2 = 0.f;
    for (int i = tid; i < N; i += 128) { float t = (buf[i] / sum) * mask[(size_t)b * N + i]; buf[i] = t; s2 += t; }
    red[tid] = s2; __syncthreads();
    for (int off = 64; off; off >>= 1) { if (tid < off) red[tid] += red[tid + off]; __syncthreads(); }
    s2 = red[0];
    float inv = 1.f / (s2 + 1e-10f);
    for (int i = tid; i < N; i += 128) {
        float a = buf[i] * inv;
        attn_out[(size_t)b * N + i] = a;
        if (cov_out) cov_out[(size_t)b * N + i] = cov[(size_t)b * N + i] + a;
    }
}

// -------------------- context: ctx[b,m] = sum_l attn[b,l] * mem[b,l,m] --------------------
__global__ void context_kernel(const float* __restrict__ attn, const float* __restrict__ mem,
                               float* __restrict__ ctx_out, float* __restrict__ cat,
                               int Lc, int catOff) {
    __shared__ float a_s[512];
    int b = blockIdx.x;
    int m = blockIdx.y * 128 + threadIdx.x;
    for (int i = threadIdx.x; i < Lc; i += 128) a_s[i] = attn[(size_t)b * Lc + i];
    __syncthreads();
    const float* mb = mem + (size_t)b * Lc * MMD + m;
    float acc = 0.f;
#pragma unroll 4
    for (int l = 0; l < Lc; l++) acc += a_s[l] * mb[(size_t)l * MMD];
    if (ctx_out) ctx_out[(size_t)b * MMD + m] = acc;
    cat[(size_t)b * 1536 + catOff + m] = acc;
}

// -------------------- p_gen --------------------
__global__ void pgen_kernel(const float* __restrict__ cat, const float* __restrict__ yemb,
                            const float* __restrict__ pw, const float* __restrict__ pb,
                            float* __restrict__ pg_scr, float* __restrict__ pg_out) {
    __shared__ float red[256];
    int b = blockIdx.x, tid = threadIdx.x;
    float s = 0.f;
    for (int i = tid; i < 1536; i += 256) s += cat[(size_t)b * 1536 + i] * pw[i];
    for (int i = tid; i < EMB_; i += 256) s += yemb[(size_t)b * EMB_ + i] * pw[1536 + i];
    red[tid] = s; __syncthreads();
    for (int off = 128; off; off >>= 1) { if (tid < off) red[tid] += red[tid + off]; __syncthreads(); }
    if (tid == 0) {
        float p = 1.f / (1.f + expf(-(red[0] + pb[0])));
        pg_scr[b] = p;
        pg_out[b] = p;
    }
}

// -------------------- vocab softmax + p_gen mix + OOV scatter (1024 thr) --------------------
__global__ void __launch_bounds__(1024)
final_kernel(const float* __restrict__ logits, const float* __restrict__ pgen,
             const float* __restrict__ wattn, const int* __restrict__ src_oov,
             float* __restrict__ out_final) {
    __shared__ float red[1024];
    int b = blockIdx.x, tid = threadIdx.x;
    const float4* lg4 = (const float4*)(logits + (size_t)b * VV);
    const int n4 = VV / 4;
    float* fr = out_final + (size_t)b * VE;
    float2* fr2 = (float2*)fr;

    float mx = -1e30f;
    for (int i = tid; i < n4; i += 1024) {
        float4 x = lg4[i];
        mx = fmaxf(mx, fmaxf(fmaxf(x.x, x.y), fmaxf(x.z, x.w)));
    }
    red[tid] = mx; __syncthreads();
    for (int off = 512; off; off >>= 1) { if (tid < off) red[tid] = fmaxf(red[tid], red[tid + off]); __syncthreads(); }
    mx = red[0]; __syncthreads();

    float sum = 0.f;
    for (int i = tid; i < n4; i += 1024) {
        float4 x = lg4[i];
        float e0 = expf(x.x - mx), e1 = expf(x.y - mx);
        float e2 = expf(x.z - mx), e3 = expf(x.w - mx);
        sum += (e0 + e1) + (e2 + e3);
        fr2[2 * i]     = make_float2(e0, e1);
        fr2[2 * i + 1] = make_float2(e2, e3);
    }
    red[tid] = sum; __syncthreads();
    for (int off = 512; off; off >>= 1) { if (tid < off) red[tid] += red[tid + off]; __syncthreads(); }
    sum = red[0];
    float pg = pgen[b];
    float scale = pg / sum;
    for (int i = tid; i < n4; i += 1024) {
        float2 p0 = fr2[2 * i], p1 = fr2[2 * i + 1];
        p0.x *= scale; p0.y *= scale; p1.x *= scale; p1.y *= scale;
        fr2[2 * i] = p0; fr2[2 * i + 1] = p1;
    }
    for (int i = VV + tid; i < VE; i += 1024) fr[i] = 0.f;
    __syncthreads();
    float om = 1.f - pg;
    if (tid < LW) {
        int idx = src_oov[(size_t)b * LW + tid];
        atomicAdd(&fr[idx], om * wattn[(size_t)b * LW + tid]);
    }
}

// -------------------- launcher --------------------
extern "C" void kernel_launch(void* const* d_in, const int* in_sizes, int n_in,
                              void* d_out, int out_size) {
    (void)in_sizes; (void)n_in; (void)out_size;
    const float* h0   = (const float*)d_in[0];
    const float* wmem = (const float*)d_in[1];
    const float* smem_bank = (const float*)d_in[2];
    const float* wmask = (const float*)d_in[3];
    const float* smask = (const float*)d_in[4];
    const float* cov   = (const float*)d_in[5];
    const float* emb   = (const float*)d_in[6];
    const float* gwih  = (const float*)d_in[7];
    const float* gwhh  = (const float*)d_in[8];
    const float* gbih  = (const float*)d_in[9];
    const float* gbhh  = (const float*)d_in[10];
    const float* wmp   = (const float*)d_in[11];
    const float* wdpw  = (const float*)d_in[12];
    const float* wdpb  = (const float*)d_in[13];
    const float* wv    = (const float*)d_in[14];
    const float* wcp   = (const float*)d_in[15];
    const float* smp   = (const float*)d_in[16];
    const float* sdpw  = (const float*)d_in[17];
    const float* sdpb  = (const float*)d_in[18];
    const float* sv    = (const float*)d_in[19];
    const float* pgw   = (const float*)d_in[20];
    const float* pgb   = (const float*)d_in[21];
    const float* vd1w  = (const float*)d_in[22];
    const float* vd1b  = (const float*)d_in[23];
    const float* vd2w  = (const float*)d_in[24];
    const float* vd2b  = (const float*)d_in[25];
    const int*   y     = (const int*)d_in[26];
    const int*   soov  = (const int*)d_in[27];
    float* out = (float*)d_out;

    float *yemb, *gi, *gh, *hl, *dpw, *dps, *wsc, *ssc, *sat, *cat, *hid, *pg, *lg;
    __nv_bfloat16 *wmH, *wmL, *smH, *smL, *wpH, *wpL, *spH, *spL, *hdH, *hdL, *v2H, *v2L;
    cudaGetSymbolAddress((void**)&yemb, g_yemb);
    cudaGetSymbolAddress((void**)&gi,   g_gi);
    cudaGetSymbolAddress((void**)&gh,   g_gh);
    cudaGetSymbolAddress((void**)&hl,   g_hlast);
    cudaGetSymbolAddress((void**)&dpw,  g_dpw);
    cudaGetSymbolAddress((void**)&dps,  g_dps);
    cudaGetSymbolAddress((void**)&wsc,  g_wscores);
    cudaGetSymbolAddress((void**)&ssc,  g_sscores);
    cudaGetSymbolAddress((void**)&sat,  g_sattn);
    cudaGetSymbolAddress((void**)&cat,  g_cat);
    cudaGetSymbolAddress((void**)&hid,  g_hid);
    cudaGetSymbolAddress((void**)&pg,   g_pgen);
    cudaGetSymbolAddress((void**)&lg,   g_logits);
    cudaGetSymbolAddress((void**)&wmH,  g_wmemH);
    cudaGetSymbolAddress((void**)&wmL,  g_wmemL);
    cudaGetSymbolAddress((void**)&smH,  g_smemH);
    cudaGetSymbolAddress((void**)&smL,  g_smemL);
    cudaGetSymbolAddress((void**)&wpH,  g_wmpH);
    cudaGetSymbolAddress((void**)&wpL,  g_wmpL);
    cudaGetSymbolAddress((void**)&spH,  g_smpH);
    cudaGetSymbolAddress((void**)&spL,  g_smpL);
    cudaGetSymbolAddress((void**)&hdH,  g_hidH);
    cudaGetSymbolAddress((void**)&hdL,  g_hidL);
    cudaGetSymbolAddress((void**)&v2H,  g_vd2wH);
    cudaGetSymbolAddress((void**)&v2L,  g_vd2wL);

    cudaFuncSetAttribute(attn_scores_mma<true>,
                         cudaFuncAttributeMaxDynamicSharedMemorySize, AT_DYN);
    cudaFuncSetAttribute(attn_scores_mma<false>,
                         cudaFuncAttributeMaxDynamicSharedMemorySize, AT_DYN);

    // 0: prep — gigh GEMMs + all big presplits, one launch
    prep_kernel<<<NB_PREP, 256>>>(emb, y, h0, gwih, gbih, gwhh, gbhh, gi, gh, yemb,
                                  wmem, wmH, wmL, smem_bank, smH, smL,
                                  wmp, wpH, wpL, smp, spH, spL, vd2w, v2H, v2L);
    // 1: GRU combine (+ zero score buffers for atomic accumulation)
    gru_kernel<<<(BB * HH + 255) / 256, 256>>>(gi, gh, h0, hl, cat, out + OUT_H, wsc, ssc);
    // 2: fused decoder-state projections
    dpwdps_kernel<<<dim3(8, 2, 2), 256>>>(hl, wdpw, wdpb, sdpw, sdpb, dpw, dps);
    // 3: word attention scores (chunk-parallel)  <-- profiled launch
    attn_scores_mma<true ><<<dim3((BB * LW) / 128, 4), 256, AT_DYN>>>(wmH, wmL, wpH, wpL, dpw, wv, wcp, cov, wsc, LW);
    // 4: sentence attention scores (chunk-parallel)
    attn_scores_mma<false><<<dim3((BB * SSL) / 128, 4), 256, AT_DYN>>>(smH, smL, spH, spL, dps, sv, nullptr, nullptr, ssc, SSL);

    // softmax + mask + renorm (+ coverage output for word)
    softmax_mask_kernel<<<BB, 128>>>(wsc, wmask, cov, out + OUT_WATTN, out + OUT_WCOV, LW);
    softmax_mask_kernel<<<BB, 128>>>(ssc, smask, nullptr, sat, nullptr, SSL);

    // contexts
    context_kernel<<<dim3(BB, 4), 128>>>(out + OUT_WATTN, wmem, out + OUT_WCTX, cat, LW, 0);
    context_kernel<<<dim3(BB, 4), 128>>>(sat, smem_bank, nullptr, cat, SSL, 512);

    // p_gen
    pgen_kernel<<<BB, 256>>>(cat, yemb, pgw, pgb, pg, out + OUT_PGEN);

    // vocab head
    gemm_bias_kernel<<<dim3(8, 2), 256>>>(cat, vd1w, vd1b, hid, BB, HH, 3 * HH);
    presplit_kernel<<<(BB * HH / 4 + 255) / 256, 256>>>(hid, hdH, hdL, BB * HH / 4);
    mma_gemm_bias<<<dim3((VV + 63) / 64, 2), 256>>>(hdH, hdL, v2H, v2L, vd2b, lg, BB, VV, HH);

    // vocab softmax, p_gen mix, zeros for OOV slots, scatter-add of copy dist
    final_kernel<<<BB, 1024>>>(lg, pg, out + OUT_WATTN, soov, out + OUT_FINAL);
}

// round 12
// speedup vs baseline: 1.2194x; 1.0191x over previous
#include <cuda_runtime.h>
#include <cuda_bf16.h>
#include <math.h>

// Problem constants
#define BB   128
#define LW   400
#define SSL  30
#define VV   50000
#define EMB_ 128
#define HH   512
#define MMD  512
#define OOVN 30
#define VE   (VV + OOVN)   // 50030

// Output layout: concat of (final_dist, h_next, word_ctx, word_attn, p_gen, word_cov)
#define OUT_FINAL 0
#define OUT_H     (BB * VE)
#define OUT_WCTX  (OUT_H + BB * HH)
#define OUT_WATTN (OUT_WCTX + BB * MMD)
#define OUT_PGEN  (OUT_WATTN + BB * LW)
#define OUT_WCOV  (OUT_PGEN + BB)

#define SPITCH 40   // smem bf16 row pitch (80B rows; ldmatrix conflict-free)

// -------------------- scratch (no allocations allowed) --------------------
__device__ float g_yemb[BB * EMB_];
__device__ float g_gi[BB * 3 * HH];
__device__ float g_gh[BB * 3 * HH];
__device__ float g_hlast[BB * HH];
__device__ float g_dpw[BB * HH];
__device__ float g_dps[BB * HH];
__device__ float g_wscores[BB * LW];
__device__ float g_sscores[BB * SSL];
__device__ float g_sattn[BB * SSL];
__device__ float g_cat[BB * 3 * HH];     // [word_ctx | sent_ctx | h_last]
__device__ float g_hid[BB * HH];
__device__ float g_pgen[BB];
__device__ float g_logits[(size_t)BB * VV];

// pre-split bf16 (hi, lo) buffers
__device__ __nv_bfloat16 g_wmemH[(size_t)BB * LW * MMD];
__device__ __nv_bfloat16 g_wmemL[(size_t)BB * LW * MMD];
__device__ __nv_bfloat16 g_smemH[BB * SSL * MMD];
__device__ __nv_bfloat16 g_smemL[BB * SSL * MMD];
__device__ __nv_bfloat16 g_wmpH[HH * MMD];
__device__ __nv_bfloat16 g_wmpL[HH * MMD];
__device__ __nv_bfloat16 g_smpH[HH * MMD];
__device__ __nv_bfloat16 g_smpL[HH * MMD];
__device__ __nv_bfloat16 g_hidH[BB * HH];
__device__ __nv_bfloat16 g_hidL[BB * HH];
__device__ __nv_bfloat16 g_vd2wH[(size_t)VV * HH];
__device__ __nv_bfloat16 g_vd2wL[(size_t)VV * HH];

// -------------------- helpers --------------------
__device__ __forceinline__ unsigned pack_bf2(__nv_bfloat16 a, __nv_bfloat16 b) {
    __nv_bfloat162 t(a, b);
    return *(unsigned*)&t;
}
__device__ __forceinline__ void split1(float x, __nv_bfloat16& h, __nv_bfloat16& l) {
    h = __float2bfloat16_rn(x);
    l = __float2bfloat16_rn(x - __bfloat162float(h));
}
__device__ __forceinline__ void split2(float x, float y, unsigned& hi2, unsigned& lo2) {
    __nv_bfloat16 hx, lx, hy, ly;
    split1(x, hx, lx); split1(y, hy, ly);
    hi2 = pack_bf2(hx, hy);
    lo2 = pack_bf2(lx, ly);
}
__device__ __forceinline__ void mma_bf16(float* c, const unsigned* a, const unsigned* b) {
    asm volatile(
        "mma.sync.aligned.m16n8k16.row.col.f32.bf16.bf16.f32 "
        "{%0,%1,%2,%3}, {%4,%5,%6,%7}, {%8,%9}, {%0,%1,%2,%3};"
        : "+f"(c[0]), "+f"(c[1]), "+f"(c[2]), "+f"(c[3])
        : "r"(a[0]), "r"(a[1]), "r"(a[2]), "r"(a[3]), "r"(b[0]), "r"(b[1]));
}
// ldmatrix x4: four 8x8 b16 matrices; lane i supplies row addr for matrix i/8
__device__ __forceinline__ void ldsm_x4(unsigned* r, unsigned saddr) {
    asm volatile("ldmatrix.sync.aligned.m8n8.x4.shared.b16 {%0,%1,%2,%3}, [%4];"
        : "=r"(r[0]), "=r"(r[1]), "=r"(r[2]), "=r"(r[3]) : "r"(saddr));
}
// cp.async 16B
__device__ __forceinline__ void cp16(void* sptr, const void* gptr) {
    unsigned sa = (unsigned)__cvta_generic_to_shared(sptr);
    asm volatile("cp.async.cg.shared.global [%0], [%1], 16;" :: "r"(sa), "l"(gptr));
}
__device__ __forceinline__ void cp16z(void* sptr, const void* gptr, bool ok) {
    unsigned sa = (unsigned)__cvta_generic_to_shared(sptr);
    int sz = ok ? 16 : 0;
    asm volatile("cp.async.cg.shared.global [%0], [%1], 16, %2;" :: "r"(sa), "l"(gptr), "r"(sz));
}
#define CP_COMMIT() asm volatile("cp.async.commit_group;")
template <int N> __device__ __forceinline__ void cp_wait() {
    asm volatile("cp.async.wait_group %0;" :: "n"(N));
}

// -------------------- hid presplit (separate small launch) --------------------
__global__ void presplit_kernel(const float* __restrict__ src, __nv_bfloat16* __restrict__ dh,
                                __nv_bfloat16* __restrict__ dl, int n4) {
    int i = blockIdx.x * 256 + threadIdx.x;
    if (i >= n4) return;
    float4 x = ((const float4*)src)[i];
    unsigned h01, l01, h23, l23;
    split2(x.x, x.y, h01, l01);
    split2(x.z, x.w, h23, l23);
    ((uint2*)dh)[i] = make_uint2(h01, h23);
    ((uint2*)dl)[i] = make_uint2(l01, l23);
}

// ==================== prep: gigh GEMMs + ALL big presplits, one launch ====================
#define NB_GIGH 96
#define NB_WMEM 25600   // BB*LW*MMD/1024
#define NB_SMEM 1920    // BB*SSL*MMD/1024
#define NB_WMP  256     // HH*MMD/1024
#define NB_SMP  256
#define NB_VD2W 25000   // VV*HH/1024
#define NB_PREP (NB_GIGH + NB_WMEM + NB_SMEM + NB_WMP + NB_SMP + NB_VD2W)

__global__ void prep_kernel(
    const float* __restrict__ emb, const int* __restrict__ y, const float* __restrict__ h0,
    const float* __restrict__ gwih, const float* __restrict__ gbih,
    const float* __restrict__ gwhh, const float* __restrict__ gbhh,
    float* __restrict__ gi, float* __restrict__ gh, float* __restrict__ yemb,
    const float* __restrict__ wmem, __nv_bfloat16* __restrict__ wmH, __nv_bfloat16* __restrict__ wmL,
    const float* __restrict__ smemb, __nv_bfloat16* __restrict__ smH, __nv_bfloat16* __restrict__ smL,
    const float* __restrict__ wmp, __nv_bfloat16* __restrict__ wpH, __nv_bfloat16* __restrict__ wpL,
    const float* __restrict__ smp, __nv_bfloat16* __restrict__ spH, __nv_bfloat16* __restrict__ spL,
    const float* __restrict__ vd2w, __nv_bfloat16* __restrict__ v2H, __nv_bfloat16* __restrict__ v2L)
{
    __shared__ float As[16][68];
    __shared__ float Ws[16][68];
    int bid = blockIdx.x;
    int tid = threadIdx.x;

    if (bid >= NB_GIGH) {
        // ---- presplit region ----
        int pb = bid - NB_GIGH;
        const float* src; __nv_bfloat16* dh; __nv_bfloat16* dl; int base;
        if (pb < NB_WMEM)                       { src = wmem;  dh = wmH; dl = wmL; base = pb; }
        else if (pb < NB_WMEM + NB_SMEM)        { src = smemb; dh = smH; dl = smL; base = pb - NB_WMEM; }
        else if (pb < NB_WMEM + NB_SMEM + NB_WMP) { src = wmp; dh = wpH; dl = wpL; base = pb - NB_WMEM - NB_SMEM; }
        else if (pb < NB_WMEM + NB_SMEM + NB_WMP + NB_SMP) { src = smp; dh = spH; dl = spL; base = pb - NB_WMEM - NB_SMEM - NB_WMP; }
        else { src = vd2w; dh = v2H; dl = v2L; base = pb - NB_WMEM - NB_SMEM - NB_WMP - NB_SMP; }
        size_t i = (size_t)base * 256 + tid;
        float4 x = ((const float4*)src)[i];
        unsigned h01, l01, h23, l23;
        split2(x.x, x.y, h01, l01);
        split2(x.z, x.w, h23, l23);
        ((uint2*)dh)[i] = make_uint2(h01, h23);
        ((uint2*)dl)[i] = make_uint2(l01, l23);
        return;
    }

    // ---- gigh GEMM: z=0 -> gi (A = emb[y]); z=1 -> gh (A = h0) ----
    int gx = bid % 24, gy = (bid / 24) % 2, gz = bid / 48;
    int tx = tid & 15, ty = tid >> 4;
    int K = gz ? HH : EMB_;
    const float* W = gz ? gwhh : gwih;
    const float* bias = gz ? gbhh : gbih;
    float* C = gz ? gh : gi;
    int rb = gy * 64, cb = gx * 64;
    int lr = tid >> 2, kq = tid & 3;
    int yrow = gz ? 0 : y[rb + lr];
    const float* Arow = gz ? &h0[(size_t)(rb + lr) * HH] : &emb[(size_t)yrow * EMB_];
    float acc[4][4] = {};

    for (int k0 = 0; k0 < K; k0 += 16) {
        float4 a4 = *(const float4*)&Arow[k0 + kq * 4];
        float4 w4 = *(const float4*)&W[(size_t)(cb + lr) * K + k0 + kq * 4];
        if (gz == 0 && gx == 0)
            *(float4*)&yemb[(size_t)(rb + lr) * EMB_ + k0 + kq * 4] = a4;
        As[kq * 4 + 0][lr] = a4.x; As[kq * 4 + 1][lr] = a4.y;
        As[kq * 4 + 2][lr] = a4.z; As[kq * 4 + 3][lr] = a4.w;
        Ws[kq * 4 + 0][lr] = w4.x; Ws[kq * 4 + 1][lr] = w4.y;
        Ws[kq * 4 + 2][lr] = w4.z; Ws[kq * 4 + 3][lr] = w4.w;
        __syncthreads();
#pragma unroll
        for (int kk = 0; kk < 16; kk++) {
            float4 a = *(const float4*)&As[kk][ty * 4];
            float4 w = *(const float4*)&Ws[kk][tx * 4];
            acc[0][0] += a.x * w.x; acc[0][1] += a.x * w.y; acc[0][2] += a.x * w.z; acc[0][3] += a.x * w.w;
            acc[1][0] += a.y * w.x; acc[1][1] += a.y * w.y; acc[1][2] += a.y * w.z; acc[1][3] += a.y * w.w;
            acc[2][0] += a.z * w.x; acc[2][1] += a.z * w.y; acc[2][2] += a.z * w.z; acc[2][3] += a.z * w.w;
            acc[3][0] += a.w * w.x; acc[3][1] += a.w * w.y; acc[3][2] += a.w * w.z; acc[3][3] += a.w * w.w;
        }
        __syncthreads();
    }
#pragma unroll
    for (int i = 0; i < 4; i++) {
        int row = rb + ty * 4 + i;
#pragma unroll
        for (int j = 0; j < 4; j++) {
            int col = cb + tx * 4 + j;
            C[(size_t)row * (3 * HH) + col] = acc[i][j] + bias[col];
        }
    }
}

// -------------------- fused decoder projections: z=0 -> dpw, z=1 -> dps --------------------
__global__ void dpwdps_kernel(const float* __restrict__ hl,
                              const float* __restrict__ wdpw, const float* __restrict__ wdpb,
                              const float* __restrict__ sdpw, const float* __restrict__ sdpb,
                              float* __restrict__ dpw, float* __restrict__ dps) {
    __shared__ float As[16][68];
    __shared__ float Ws[16][68];
    int tid = threadIdx.x;
    int tx = tid & 15, ty = tid >> 4;
    int z = blockIdx.z;
    const float* W = z ? sdpw : wdpw;
    const float* bias = z ? sdpb : wdpb;
    float* C = z ? dps : dpw;
    const int K = HH;
    int rb = blockIdx.y * 64, cb = blockIdx.x * 64;
    int lr = tid >> 2, kq = tid & 3;
    float acc[4][4] = {};

    for (int k0 = 0; k0 < K; k0 += 16) {
        float4 a4 = *(const float4*)&hl[(size_t)(rb + lr) * K + k0 + kq * 4];
        float4 w4 = *(const float4*)&W[(size_t)(cb + lr) * K + k0 + kq * 4];
        As[kq * 4 + 0][lr] = a4.x; As[kq * 4 + 1][lr] = a4.y;
        As[kq * 4 + 2][lr] = a4.z; As[kq * 4 + 3][lr] = a4.w;
        Ws[kq * 4 + 0][lr] = w4.x; Ws[kq * 4 + 1][lr] = w4.y;
        Ws[kq * 4 + 2][lr] = w4.z; Ws[kq * 4 + 3][lr] = w4.w;
        __syncthreads();
#pragma unroll
        for (int kk = 0; kk < 16; kk++) {
            float4 a = *(const float4*)&As[kk][ty * 4];
            float4 w = *(const float4*)&Ws[kk][tx * 4];
            acc[0][0] += a.x * w.x; acc[0][1] += a.x * w.y; acc[0][2] += a.x * w.z; acc[0][3] += a.x * w.w;
            acc[1][0] += a.y * w.x; acc[1][1] += a.y * w.y; acc[1][2] += a.y * w.z; acc[1][3] += a.y * w.w;
            acc[2][0] += a.z * w.x; acc[2][1] += a.z * w.y; acc[2][2] += a.z * w.z; acc[2][3] += a.z * w.w;
            acc[3][0] += a.w * w.x; acc[3][1] += a.w * w.y; acc[3][2] += a.w * w.z; acc[3][3] += a.w * w.w;
        }
        __syncthreads();
    }
#pragma unroll
    for (int i = 0; i < 4; i++) {
        int row = rb + ty * 4 + i;
#pragma unroll
        for (int j = 0; j < 4; j++) {
            int col = cb + tx * 4 + j;
            C[(size_t)row * HH + col] = acc[i][j] + bias[col];
        }
    }
}

// -------------------- generic scalar SGEMM (hid) --------------------
__global__ void gemm_bias_kernel(const float* __restrict__ A, const float* __restrict__ W,
                                 const float* __restrict__ bias, float* __restrict__ C,
                                 int M, int N, int K) {
    __shared__ float As[16][68];
    __shared__ float Ws[16][68];
    int tid = threadIdx.x;
    int tx = tid & 15, ty = tid >> 4;
    int rb = blockIdx.y * 64, cb = blockIdx.x * 64;
    int lr = tid >> 2, kq = tid & 3;
    float acc[4][4] = {};

    for (int k0 = 0; k0 < K; k0 += 16) {
        float4 a4 = make_float4(0.f, 0.f, 0.f, 0.f);
        float4 w4 = make_float4(0.f, 0.f, 0.f, 0.f);
        if (rb + lr < M) a4 = *(const float4*)&A[(size_t)(rb + lr) * K + k0 + kq * 4];
        if (cb + lr < N) w4 = *(const float4*)&W[(size_t)(cb + lr) * K + k0 + kq * 4];
        As[kq * 4 + 0][lr] = a4.x; As[kq * 4 + 1][lr] = a4.y;
        As[kq * 4 + 2][lr] = a4.z; As[kq * 4 + 3][lr] = a4.w;
        Ws[kq * 4 + 0][lr] = w4.x; Ws[kq * 4 + 1][lr] = w4.y;
        Ws[kq * 4 + 2][lr] = w4.z; Ws[kq * 4 + 3][lr] = w4.w;
        __syncthreads();
#pragma unroll
        for (int kk = 0; kk < 16; kk++) {
            float4 a = *(const float4*)&As[kk][ty * 4];
            float4 w = *(const float4*)&Ws[kk][tx * 4];
            acc[0][0] += a.x * w.x; acc[0][1] += a.x * w.y; acc[0][2] += a.x * w.z; acc[0][3] += a.x * w.w;
            acc[1][0] += a.y * w.x; acc[1][1] += a.y * w.y; acc[1][2] += a.y * w.z; acc[1][3] += a.y * w.w;
            acc[2][0] += a.z * w.x; acc[2][1] += a.z * w.y; acc[2][2] += a.z * w.z; acc[2][3] += a.z * w.w;
            acc[3][0] += a.w * w.x; acc[3][1] += a.w * w.y; acc[3][2] += a.w * w.z; acc[3][3] += a.w * w.w;
        }
        __syncthreads();
    }
#pragma unroll
    for (int i = 0; i < 4; i++) {
        int row = rb + ty * 4 + i;
        if (row >= M) continue;
#pragma unroll
        for (int j = 0; j < 4; j++) {
            int col = cb + tx * 4 + j;
            if (col < N) C[(size_t)row * N + col] = acc[i][j] + (bias ? bias[col] : 0.f);
        }
    }
}

// ==================== attention scores: chunk-parallel 128x128 tiles, cp.async + ldmatrix ====================
#define AT_T   (128 * SPITCH)                // 5120 elems per half-tile
#define AT_BUF (4 * AT_T)                    // Ah|Al|Wh|Wl
#define AT_DYN (2 * AT_BUF * 2)              // 81920 bytes
template <bool HAS_COV>
__global__ void __launch_bounds__(256, 2)
attn_scores_mma(const __nv_bfloat16* __restrict__ memH, const __nv_bfloat16* __restrict__ memL,
                const __nv_bfloat16* __restrict__ WmH, const __nv_bfloat16* __restrict__ WmL,
                const float* __restrict__ dproj, const float* __restrict__ v,
                const float* __restrict__ wcov, const float* __restrict__ cov,
                float* __restrict__ scores, int Lper) {
    const int K = 512;
    extern __shared__ __nv_bfloat16 dyn[];
    __shared__ float rowred[128];

    int tid = threadIdx.x;
    int wid = tid >> 5, lane = tid & 31;
    int rg = wid >> 2, cg = wid & 3;         // 2 row-groups x 4 col-groups
    int warpRow = rg * 64, warpCol = cg * 32;
    int g = lane >> 2, tg = lane & 3;
    int rowBase = blockIdx.x * 128;
    int col0 = blockIdx.y * 128;
    int frow = tid & 127, fhf = tid >> 7;

    // ldmatrix per-lane offsets (bytes)
    int r8 = lane & 7, quad = lane >> 3;
    unsigned a_lane = ((unsigned)((r8 + (quad & 1) * 8) * SPITCH + (quad >> 1) * 8)) * 2;
    unsigned w_lane = ((unsigned)(((quad >> 1) * 8 + r8) * SPITCH + (quad & 1) * 8)) * 2;
    unsigned sdyn = (unsigned)__cvta_generic_to_shared(dyn);

    if (tid < 128) rowred[tid] = 0.f;

    float covr[8];
    if (HAS_COV) {
#pragma unroll
        for (int mt = 0; mt < 4; mt++) {
            covr[2 * mt]     = cov[rowBase + warpRow + mt * 16 + g];
            covr[2 * mt + 1] = cov[rowBase + warpRow + mt * 16 + g + 8];
        }
    }
    float rs[8] = {};

    auto do_fill = [&](int b, int k0) {
        __nv_bfloat16* base = dyn + b * AT_BUF;
        size_t ga = (size_t)(rowBase + frow) * K + k0 + fhf * 8;
        size_t gw = (size_t)(col0 + frow) * K + k0 + fhf * 8;
        unsigned so = frow * SPITCH + fhf * 8;
        cp16(&base[0 * AT_T + so], &memH[ga]);
        cp16(&base[1 * AT_T + so], &memL[ga]);
        cp16(&base[2 * AT_T + so], &WmH[gw]);
        cp16(&base[3 * AT_T + so], &WmL[gw]);
        CP_COMMIT();
    };

    do_fill(0, 0);
    int cur = 0;
    float acc[4][4][4] = {};
    for (int k0 = 0; k0 < K; k0 += 16) {
        bool has_next = (k0 + 16 < K);
        if (has_next) { do_fill(cur ^ 1, k0 + 16); cp_wait<1>(); }
        else cp_wait<0>();
        __syncthreads();

        unsigned sbase = sdyn + (unsigned)cur * (AT_BUF * 2);
        unsigned AhB = sbase;
        unsigned AlB = sbase + AT_T * 2;
        unsigned WhB = sbase + 2 * AT_T * 2;
        unsigned WlB = sbase + 3 * AT_T * 2;

        unsigned bh[2][4], bl[2][4];
#pragma unroll
        for (int p = 0; p < 2; p++) {
            unsigned wo = (unsigned)((warpCol + p * 16) * SPITCH) * 2 + w_lane;
            ldsm_x4(bh[p], WhB + wo);
            ldsm_x4(bl[p], WlB + wo);
        }
#pragma unroll
        for (int mt = 0; mt < 4; mt++) {
            unsigned ao = (unsigned)((warpRow + mt * 16) * SPITCH) * 2 + a_lane;
            unsigned ah[4], al[4];
            ldsm_x4(ah, AhB + ao);
            ldsm_x4(al, AlB + ao);
#pragma unroll
            for (int nb = 0; nb < 4; nb++) {
                const unsigned* ph = &bh[nb >> 1][(nb & 1) * 2];
                const unsigned* pl = &bl[nb >> 1][(nb & 1) * 2];
                mma_bf16(acc[mt][nb], ah, ph);
                mma_bf16(acc[mt][nb], ah, pl);
                mma_bf16(acc[mt][nb], al, ph);
            }
        }
        __syncthreads();
        cur ^= 1;
    }
    // epilogue: tanh + v-weighted partial sums over this block's 128 d-columns
#pragma unroll
    for (int mt = 0; mt < 4; mt++) {
        int r0 = rowBase + warpRow + mt * 16 + g;
        int r1 = r0 + 8;
        int b0 = r0 / Lper, b1 = r1 / Lper;
#pragma unroll
        for (int nb = 0; nb < 4; nb++) {
            int d = col0 + warpCol + nb * 8 + tg * 2;
#pragma unroll
            for (int jj = 0; jj < 2; jj++) {
                int dd = d + jj;
                float vd = v[dd];
                float wc = HAS_COV ? wcov[dd] : 0.f;
                float f0 = acc[mt][nb][jj]     + dproj[(size_t)b0 * HH + dd];
                float f1 = acc[mt][nb][2 + jj] + dproj[(size_t)b1 * HH + dd];
                if (HAS_COV) { f0 += covr[2 * mt] * wc; f1 += covr[2 * mt + 1] * wc; }
                rs[2 * mt]     += tanhf(f0) * vd;
                rs[2 * mt + 1] += tanhf(f1) * vd;
            }
        }
    }
#pragma unroll
    for (int i = 0; i < 8; i++) {
        float s = rs[i];
        s += __shfl_xor_sync(0xffffffffu, s, 1);
        s += __shfl_xor_sync(0xffffffffu, s, 2);
        int mt = i >> 1;
        int localRow = warpRow + mt * 16 + g + (i & 1) * 8;
        if (tg == 0) atomicAdd(&rowred[localRow], s);
    }
    __syncthreads();
    if (tid < 128) atomicAdd(&scores[rowBase + tid], rowred[tid]);
}

// ==================== bf16x3 mma GEMM, cp.async + ldmatrix (vocab logits) ====================
#define VB_A  (64 * SPITCH)
#define VB_SZ (4 * VB_A)
__global__ void __launch_bounds__(256)
mma_gemm_bias(const __nv_bfloat16* __restrict__ AH, const __nv_bfloat16* __restrict__ AL,
              const __nv_bfloat16* __restrict__ WH, const __nv_bfloat16* __restrict__ WL,
              const float* __restrict__ bias, float* __restrict__ C,
              int M, int N, int K) {
    __shared__ __nv_bfloat16 smem[2][VB_SZ];
    int tid = threadIdx.x;
    int wid = tid >> 5, lane = tid & 31;
    int warpM = wid & 3, warpN = wid >> 2;
    int warpRow = warpM * 16, warpCol = warpN * 32;
    int g = lane >> 2, tg = lane & 3;
    int rb = blockIdx.y * 64, cb = blockIdx.x * 64;

    int frow = tid >> 1, fhf = tid & 1;
    int wfrow = (tid - 128) >> 1, wfhf = (tid - 128) & 1;

    int r8 = lane & 7, quad = lane >> 3;
    unsigned a_lane = ((unsigned)((r8 + (quad & 1) * 8) * SPITCH + (quad >> 1) * 8)) * 2;
    unsigned w_lane = ((unsigned)(((quad >> 1) * 8 + r8) * SPITCH + (quad & 1) * 8)) * 2;
    unsigned ssm = (unsigned)__cvta_generic_to_shared(&smem[0][0]);

    float acc[4][4] = {};

    auto do_fill = [&](int b, int k0) {
        if (tid < 128) {
            cp16(&smem[b][0 * VB_A + frow * SPITCH + fhf * 8],
                 &AH[(size_t)(rb + frow) * K + k0 + fhf * 8]);
            cp16(&smem[b][1 * VB_A + frow * SPITCH + fhf * 8],
                 &AL[(size_t)(rb + frow) * K + k0 + fhf * 8]);
        } else {
            bool ok = cb + wfrow < N;
            const __nv_bfloat16* srcH = &WH[(size_t)(ok ? cb + wfrow : 0) * K + k0 + wfhf * 8];
            const __nv_bfloat16* srcL = &WL[(size_t)(ok ? cb + wfrow : 0) * K + k0 + wfhf * 8];
            cp16z(&smem[b][2 * VB_A + wfrow * SPITCH + wfhf * 8], srcH, ok);
            cp16z(&smem[b][3 * VB_A + wfrow * SPITCH + wfhf * 8], srcL, ok);
        }
        CP_COMMIT();
    };

    do_fill(0, 0);
    int cur = 0;
    for (int k0 = 0; k0 < K; k0 += 16) {
        bool has_next = (k0 + 16 < K);
        if (has_next) { do_fill(cur ^ 1, k0 + 16); cp_wait<1>(); }
        else cp_wait<0>();
        __syncthreads();

        unsigned sbase = ssm + (unsigned)cur * (VB_SZ * 2);
        unsigned AhB = sbase;
        unsigned AlB = sbase + VB_A * 2;
        unsigned WhB = sbase + 2 * VB_A * 2;
        unsigned WlB = sbase + 3 * VB_A * 2;

        unsigned ah[4], al[4];
        {
            unsigned ao = (unsigned)(warpRow * SPITCH) * 2 + a_lane;
            ldsm_x4(ah, AhB + ao);
            ldsm_x4(al, AlB + ao);
        }
        unsigned bh[2][4], bl[2][4];
#pragma unroll
        for (int p = 0; p < 2; p++) {
            unsigned wo = (unsigned)((warpCol + p * 16) * SPITCH) * 2 + w_lane;
            ldsm_x4(bh[p], WhB + wo);
            ldsm_x4(bl[p], WlB + wo);
        }
#pragma unroll
        for (int nb = 0; nb < 4; nb++) {
            const unsigned* ph = &bh[nb >> 1][(nb & 1) * 2];
            const unsigned* pl = &bl[nb >> 1][(nb & 1) * 2];
            mma_bf16(acc[nb], ah, ph);
            mma_bf16(acc[nb], ah, pl);
            mma_bf16(acc[nb], al, ph);
        }
        __syncthreads();
        cur ^= 1;
    }

#pragma unroll
    for (int nb = 0; nb < 4; nb++) {
        int col = cb + warpCol + nb * 8 + tg * 2;
        int r0 = rb + warpRow + g, r1 = r0 + 8;
        if (col < N) {
            float bs = bias ? bias[col] : 0.f;
            if (r0 < M) C[(size_t)r0 * N + col] = acc[nb][0] + bs;
            if (r1 < M) C[(size_t)r1 * N + col] = acc[nb][2] + bs;
        }
        if (col + 1 < N) {
            float bs = bias ? bias[col + 1] : 0.f;
            if (r0 < M) C[(size_t)r0 * N + col + 1] = acc[nb][1] + bs;
            if (r1 < M) C[(size_t)r1 * N + col + 1] = acc[nb][3] + bs;
        }
    }
}

// -------------------- GRU combine + zero attention score buffers --------------------
__global__ void gru_kernel(const float* __restrict__ gi, const float* __restrict__ gh,
                           const float* __restrict__ h0, float* __restrict__ hlast,
                           float* __restrict__ cat, float* __restrict__ out_h,
                           float* __restrict__ wsc, float* __restrict__ ssc) {
    int idx = blockIdx.x * 256 + threadIdx.x;
    if (idx >= BB * HH) return;
    if (idx < BB * LW) wsc[idx] = 0.f;
    if (idx < BB * SSL) ssc[idx] = 0.f;
    int b = idx / HH, j = idx % HH;
    const float* gib = gi + (size_t)b * 3 * HH;
    const float* ghb = gh + (size_t)b * 3 * HH;
    float ir = gib[j], iz = gib[HH + j], in_ = gib[2 * HH + j];
    float hr = ghb[j], hz = ghb[HH + j], hn = ghb[2 * HH + j];
    float r = 1.f / (1.f + expf(-(ir + hr)));
    float z = 1.f / (1.f + expf(-(iz + hz)));
    float n = tanhf(in_ + r * hn);
    float hl = (1.f - z) * n + z * h0[idx];
    hlast[idx] = hl;
    cat[(size_t)b * 1536 + 1024 + j] = hl;
    out_h[idx] = hl;
}

// -------------------- softmax -> mask -> renormalize (+ coverage update) --------------------
__global__ void softmax_mask_kernel(const float* __restrict__ scores, const float* __restrict__ mask,
                                    const float* __restrict__ cov, float* __restrict__ attn_out,
                                    float* __restrict__ cov_out, int N) {
    __shared__ float buf[512];
    __shared__ float red[128];
    int b = blockIdx.x, tid = threadIdx.x;
    const float* s = scores + (size_t)b * N;
    float mx = -1e30f;
    for (int i = tid; i < N; i += 128) { float vv = s[i]; buf[i] = vv; mx = fmaxf(mx, vv); }
    red[tid] = mx; __syncthreads();
    for (int off = 64; off; off >>= 1) { if (tid < off) red[tid] = fmaxf(red[tid], red[tid + off]); __syncthreads(); }
    mx = red[0]; __syncthreads();
    float sum = 0.f;
    for (int i = tid; i < N; i += 128) { float e = expf(buf[i] - mx); buf[i] = e; sum += e; }
    red[tid] = sum; __syncthreads();
    for (int off = 64; off; off >>= 1) { if (tid < off) red[tid] += red[tid + off]; __syncthreads(); }
    sum = red[0]; __syncthreads();
    float s2 = 0.f;
    for (int i = tid; i < N; i += 128) { float t = (buf[i] / sum) * mask[(size_t)b * N + i]; buf[i] = t; s2 += t; }
    red[tid] = s2; __syncthreads();
    for (int off = 64; off; off >>= 1) { if (tid < off) red[tid] += red[tid + off]; __syncthreads(); }
    s2 = red[0];
    float inv = 1.f / (s2 + 1e-10f);
    for (int i = tid; i < N; i += 128) {
        float a = buf[i] * inv;
        attn_out[(size_t)b * N + i] = a;
        if (cov_out) cov_out[(size_t)b * N + i] = cov[(size_t)b * N + i] + a;
    }
}

// -------------------- context: ctx[b,m] = sum_l attn[b,l] * mem[b,l,m] --------------------
__global__ void context_kernel(const float* __restrict__ attn, const float* __restrict__ mem,
                               float* __restrict__ ctx_out, float* __restrict__ cat,
                               int Lc, int catOff) {
    __shared__ float a_s[512];
    int b = blockIdx.x;
    int m = blockIdx.y * 128 + threadIdx.x;
    for (int i = threadIdx.x; i < Lc; i += 128) a_s[i] = attn[(size_t)b * Lc + i];
    __syncthreads();
    const float* mb = mem + (size_t)b * Lc * MMD + m;
    float acc = 0.f;
#pragma unroll 4
    for (int l = 0; l < Lc; l++) acc += a_s[l] * mb[(size_t)l * MMD];
    if (ctx_out) ctx_out[(size_t)b * MMD + m] = acc;
    cat[(size_t)b * 1536 + catOff + m] = acc;
}

// -------------------- p_gen --------------------
__global__ void pgen_kernel(const float* __restrict__ cat, const float* __restrict__ yemb,
                            const float* __restrict__ pw, const float* __restrict__ pb,
                            float* __restrict__ pg_scr, float* __restrict__ pg_out) {
    __shared__ float red[256];
    int b = blockIdx.x, tid = threadIdx.x;
    float s = 0.f;
    for (int i = tid; i < 1536; i += 256) s += cat[(size_t)b * 1536 + i] * pw[i];
    for (int i = tid; i < EMB_; i += 256) s += yemb[(size_t)b * EMB_ + i] * pw[1536 + i];
    red[tid] = s; __syncthreads();
    for (int off = 128; off; off >>= 1) { if (tid < off) red[tid] += red[tid + off]; __syncthreads(); }
    if (tid == 0) {
        float p = 1.f / (1.f + expf(-(red[0] + pb[0])));
        pg_scr[b] = p;
        pg_out[b] = p;
    }
}

// -------------------- vocab softmax + p_gen mix + OOV scatter (1024 thr) --------------------
__global__ void __launch_bounds__(1024)
final_kernel(const float* __restrict__ logits, const float* __restrict__ pgen,
             const float* __restrict__ wattn, const int* __restrict__ src_oov,
             float* __restrict__ out_final) {
    __shared__ float red[1024];
    int b = blockIdx.x, tid = threadIdx.x;
    const float4* lg4 = (const float4*)(logits + (size_t)b * VV);
    const int n4 = VV / 4;
    float* fr = out_final + (size_t)b * VE;
    float2* fr2 = (float2*)fr;

    float mx = -1e30f;
    for (int i = tid; i < n4; i += 1024) {
        float4 x = lg4[i];
        mx = fmaxf(mx, fmaxf(fmaxf(x.x, x.y), fmaxf(x.z, x.w)));
    }
    red[tid] = mx; __syncthreads();
    for (int off = 512; off; off >>= 1) { if (tid < off) red[tid] = fmaxf(red[tid], red[tid + off]); __syncthreads(); }
    mx = red[0]; __syncthreads();

    float sum = 0.f;
    for (int i = tid; i < n4; i += 1024) {
        float4 x = lg4[i];
        float e0 = expf(x.x - mx), e1 = expf(x.y - mx);
        float e2 = expf(x.z - mx), e3 = expf(x.w - mx);
        sum += (e0 + e1) + (e2 + e3);
        fr2[2 * i]     = make_float2(e0, e1);
        fr2[2 * i + 1] = make_float2(e2, e3);
    }
    red[tid] = sum; __syncthreads();
    for (int off = 512; off; off >>= 1) { if (tid < off) red[tid] += red[tid + off]; __syncthreads(); }
    sum = red[0];
    float pg = pgen[b];
    float scale = pg / sum;
    for (int i = tid; i < n4; i += 1024) {
        float2 p0 = fr2[2 * i], p1 = fr2[2 * i + 1];
        p0.x *= scale; p0.y *= scale; p1.x *= scale; p1.y *= scale;
        fr2[2 * i] = p0; fr2[2 * i + 1] = p1;
    }
    for (int i = VV + tid; i < VE; i += 1024) fr[i] = 0.f;
    __syncthreads();
    float om = 1.f - pg;
    if (tid < LW) {
        int idx = src_oov[(size_t)b * LW + tid];
        atomicAdd(&fr[idx], om * wattn[(size_t)b * LW + tid]);
    }
}

// -------------------- launcher --------------------
extern "C" void kernel_launch(void* const* d_in, const int* in_sizes, int n_in,
                              void* d_out, int out_size) {
    (void)in_sizes; (void)n_in; (void)out_size;
    const float* h0   = (const float*)d_in[0];
    const float* wmem = (const float*)d_in[1];
    const float* smem_bank = (const float*)d_in[2];
    const float* wmask = (const float*)d_in[3];
    const float* smask = (const float*)d_in[4];
    const float* cov   = (const float*)d_in[5];
    const float* emb   = (const float*)d_in[6];
    const float* gwih  = (const float*)d_in[7];
    const float* gwhh  = (const float*)d_in[8];
    const float* gbih  = (const float*)d_in[9];
    const float* gbhh  = (const float*)d_in[10];
    const float* wmp   = (const float*)d_in[11];
    const float* wdpw  = (const float*)d_in[12];
    const float* wdpb  = (const float*)d_in[13];
    const float* wv    = (const float*)d_in[14];
    const float* wcp   = (const float*)d_in[15];
    const float* smp   = (const float*)d_in[16];
    const float* sdpw  = (const float*)d_in[17];
    const float* sdpb  = (const float*)d_in[18];
    const float* sv    = (const float*)d_in[19];
    const float* pgw   = (const float*)d_in[20];
    const float* pgb   = (const float*)d_in[21];
    const float* vd1w  = (const float*)d_in[22];
    const float* vd1b  = (const float*)d_in[23];
    const float* vd2w  = (const float*)d_in[24];
    const float* vd2b  = (const float*)d_in[25];
    const int*   y     = (const int*)d_in[26];
    const int*   soov  = (const int*)d_in[27];
    float* out = (float*)d_out;

    float *yemb, *gi, *gh, *hl, *dpw, *dps, *wsc, *ssc, *sat, *cat, *hid, *pg, *lg;
    __nv_bfloat16 *wmH, *wmL, *smH, *smL, *wpH, *wpL, *spH, *spL, *hdH, *hdL, *v2H, *v2L;
    cudaGetSymbolAddress((void**)&yemb, g_yemb);
    cudaGetSymbolAddress((void**)&gi,   g_gi);
    cudaGetSymbolAddress((void**)&gh,   g_gh);
    cudaGetSymbolAddress((void**)&hl,   g_hlast);
    cudaGetSymbolAddress((void**)&dpw,  g_dpw);
    cudaGetSymbolAddress((void**)&dps,  g_dps);
    cudaGetSymbolAddress((void**)&wsc,  g_wscores);
    cudaGetSymbolAddress((void**)&ssc,  g_sscores);
    cudaGetSymbolAddress((void**)&sat,  g_sattn);
    cudaGetSymbolAddress((void**)&cat,  g_cat);
    cudaGetSymbolAddress((void**)&hid,  g_hid);
    cudaGetSymbolAddress((void**)&pg,   g_pgen);
    cudaGetSymbolAddress((void**)&lg,   g_logits);
    cudaGetSymbolAddress((void**)&wmH,  g_wmemH);
    cudaGetSymbolAddress((void**)&wmL,  g_wmemL);
    cudaGetSymbolAddress((void**)&smH,  g_smemH);
    cudaGetSymbolAddress((void**)&smL,  g_smemL);
    cudaGetSymbolAddress((void**)&wpH,  g_wmpH);
    cudaGetSymbolAddress((void**)&wpL,  g_wmpL);
    cudaGetSymbolAddress((void**)&spH,  g_smpH);
    cudaGetSymbolAddress((void**)&spL,  g_smpL);
    cudaGetSymbolAddress((void**)&hdH,  g_hidH);
    cudaGetSymbolAddress((void**)&hdL,  g_hidL);
    cudaGetSymbolAddress((void**)&v2H,  g_vd2wH);
    cudaGetSymbolAddress((void**)&v2L,  g_vd2wL);

    cudaFuncSetAttribute(attn_scores_mma<true>,
                         cudaFuncAttributeMaxDynamicSharedMemorySize, AT_DYN);
    cudaFuncSetAttribute(attn_scores_mma<false>,
                         cudaFuncAttributeMaxDynamicSharedMemorySize, AT_DYN);

    // 0: prep — gigh GEMMs + all big presplits, one launch
    prep_kernel<<<NB_PREP, 256>>>(emb, y, h0, gwih, gbih, gwhh, gbhh, gi, gh, yemb,
                                  wmem, wmH, wmL, smem_bank, smH, smL,
                                  wmp, wpH, wpL, smp, spH, spL, vd2w, v2H, v2L);
    // 1: GRU combine (+ zero score buffers for atomic accumulation)
    gru_kernel<<<(BB * HH + 255) / 256, 256>>>(gi, gh, h0, hl, cat, out + OUT_H, wsc, ssc);
    // 2: fused decoder-state projections
    dpwdps_kernel<<<dim3(8, 2, 2), 256>>>(hl, wdpw, wdpb, sdpw, sdpb, dpw, dps);
    // 3: word attention scores (chunk-parallel)  <-- profiled launch
    attn_scores_mma<true ><<<dim3((BB * LW) / 128, 4), 256, AT_DYN>>>(wmH, wmL, wpH, wpL, dpw, wv, wcp, cov, wsc, LW);
    // 4: sentence attention scores (chunk-parallel)
    attn_scores_mma<false><<<dim3((BB * SSL) / 128, 4), 256, AT_DYN>>>(smH, smL, spH, spL, dps, sv, nullptr, nullptr, ssc, SSL);

    // softmax + mask + renorm (+ coverage output for word)
    softmax_mask_kernel<<<BB, 128>>>(wsc, wmask, cov, out + OUT_WATTN, out + OUT_WCOV, LW);
    softmax_mask_kernel<<<BB, 128>>>(ssc, smask, nullptr, sat, nullptr, SSL);

    // contexts
    context_kernel<<<dim3(BB, 4), 128>>>(out + OUT_WATTN, wmem, out + OUT_WCTX, cat, LW, 0);
    context_kernel<<<dim3(BB, 4), 128>>>(sat, smem_bank, nullptr, cat, SSL, 512);

    // p_gen
    pgen_kernel<<<BB, 256>>>(cat, yemb, pgw, pgb, pg, out + OUT_PGEN);

    // vocab head
    gemm_bias_kernel<<<dim3(8, 2), 256>>>(cat, vd1w, vd1b, hid, BB, HH, 3 * HH);
    presplit_kernel<<<(BB * HH / 4 + 255) / 256, 256>>>(hid, hdH, hdL, BB * HH / 4);
    mma_gemm_bias<<<dim3((VV + 63) / 64, 2), 256>>>(hdH, hdL, v2H, v2L, vd2b, lg, BB, VV, HH);

    // vocab softmax, p_gen mix, zeros for OOV slots, scatter-add of copy dist
    final_kernel<<<BB, 1024>>>(lg, pg, out + OUT_WATTN, soov, out + OUT_FINAL);
}

// round 13
// speedup vs baseline: 1.2223x; 1.0023x over previous
#include <cuda_runtime.h>
#include <cuda_bf16.h>
#include <math.h>

// Problem constants
#define BB   128
#define LW   400
#define SSL  30
#define VV   50000
#define EMB_ 128
#define HH   512
#define MMD  512
#define OOVN 30
#define VE   (VV + OOVN)   // 50030

// Output layout: concat of (final_dist, h_next, word_ctx, word_attn, p_gen, word_cov)
#define OUT_FINAL 0
#define OUT_H     (BB * VE)
#define OUT_WCTX  (OUT_H + BB * HH)
#define OUT_WATTN (OUT_WCTX + BB * MMD)
#define OUT_PGEN  (OUT_WATTN + BB * LW)
#define OUT_WCOV  (OUT_PGEN + BB)

#define SPITCH 40   // smem bf16 row pitch (80B rows; holds 32 k-cols + pad; ldmatrix conflict-free)

// -------------------- scratch (no allocations allowed) --------------------
__device__ float g_yemb[BB * EMB_];
__device__ float g_gi[BB * 3 * HH];
__device__ float g_gh[BB * 3 * HH];
__device__ float g_hlast[BB * HH];
__device__ float g_dpw[BB * HH];
__device__ float g_dps[BB * HH];
__device__ float g_wscores[BB * LW];
__device__ float g_sscores[BB * SSL];
__device__ float g_sattn[BB * SSL];
__device__ float g_cat[BB * 3 * HH];     // [word_ctx | sent_ctx | h_last]
__device__ float g_hid[BB * HH];
__device__ float g_pgen[BB];
__device__ float g_logits[(size_t)BB * VV];

// pre-split bf16 (hi, lo) buffers
__device__ __nv_bfloat16 g_wmemH[(size_t)BB * LW * MMD];
__device__ __nv_bfloat16 g_wmemL[(size_t)BB * LW * MMD];
__device__ __nv_bfloat16 g_smemH[BB * SSL * MMD];
__device__ __nv_bfloat16 g_smemL[BB * SSL * MMD];
__device__ __nv_bfloat16 g_wmpH[HH * MMD];
__device__ __nv_bfloat16 g_wmpL[HH * MMD];
__device__ __nv_bfloat16 g_smpH[HH * MMD];
__device__ __nv_bfloat16 g_smpL[HH * MMD];
__device__ __nv_bfloat16 g_hidH[BB * HH];
__device__ __nv_bfloat16 g_hidL[BB * HH];
__device__ __nv_bfloat16 g_vd2wH[(size_t)VV * HH];
__device__ __nv_bfloat16 g_vd2wL[(size_t)VV * HH];

// -------------------- helpers --------------------
__device__ __forceinline__ unsigned pack_bf2(__nv_bfloat16 a, __nv_bfloat16 b) {
    __nv_bfloat162 t(a, b);
    return *(unsigned*)&t;
}
__device__ __forceinline__ void split1(float x, __nv_bfloat16& h, __nv_bfloat16& l) {
    h = __float2bfloat16_rn(x);
    l = __float2bfloat16_rn(x - __bfloat162float(h));
}
__device__ __forceinline__ void split2(float x, float y, unsigned& hi2, unsigned& lo2) {
    __nv_bfloat16 hx, lx, hy, ly;
    split1(x, hx, lx); split1(y, hy, ly);
    hi2 = pack_bf2(hx, hy);
    lo2 = pack_bf2(lx, ly);
}
__device__ __forceinline__ void mma_bf16(float* c, const unsigned* a, const unsigned* b) {
    asm volatile(
        "mma.sync.aligned.m16n8k16.row.col.f32.bf16.bf16.f32 "
        "{%0,%1,%2,%3}, {%4,%5,%6,%7}, {%8,%9}, {%0,%1,%2,%3};"
        : "+f"(c[0]), "+f"(c[1]), "+f"(c[2]), "+f"(c[3])
        : "r"(a[0]), "r"(a[1]), "r"(a[2]), "r"(a[3]), "r"(b[0]), "r"(b[1]));
}
// ldmatrix x4: four 8x8 b16 matrices; lane i supplies row addr for matrix i/8
__device__ __forceinline__ void ldsm_x4(unsigned* r, unsigned saddr) {
    asm volatile("ldmatrix.sync.aligned.m8n8.x4.shared.b16 {%0,%1,%2,%3}, [%4];"
        : "=r"(r[0]), "=r"(r[1]), "=r"(r[2]), "=r"(r[3]) : "r"(saddr));
}
// cp.async 16B
__device__ __forceinline__ void cp16(void* sptr, const void* gptr) {
    unsigned sa = (unsigned)__cvta_generic_to_shared(sptr);
    asm volatile("cp.async.cg.shared.global [%0], [%1], 16;" :: "r"(sa), "l"(gptr));
}
__device__ __forceinline__ void cp16z(void* sptr, const void* gptr, bool ok) {
    unsigned sa = (unsigned)__cvta_generic_to_shared(sptr);
    int sz = ok ? 16 : 0;
    asm volatile("cp.async.cg.shared.global [%0], [%1], 16, %2;" :: "r"(sa), "l"(gptr), "r"(sz));
}
#define CP_COMMIT() asm volatile("cp.async.commit_group;")
template <int N> __device__ __forceinline__ void cp_wait() {
    asm volatile("cp.async.wait_group %0;" :: "n"(N));
}

// -------------------- hid presplit (separate small launch) --------------------
__global__ void presplit_kernel(const float* __restrict__ src, __nv_bfloat16* __restrict__ dh,
                                __nv_bfloat16* __restrict__ dl, int n4) {
    int i = blockIdx.x * 256 + threadIdx.x;
    if (i >= n4) return;
    float4 x = ((const float4*)src)[i];
    unsigned h01, l01, h23, l23;
    split2(x.x, x.y, h01, l01);
    split2(x.z, x.w, h23, l23);
    ((uint2*)dh)[i] = make_uint2(h01, h23);
    ((uint2*)dl)[i] = make_uint2(l01, l23);
}

// ==================== prep: gigh GEMMs + ALL big presplits, one launch ====================
#define NB_GIGH 96
#define NB_WMEM 25600   // BB*LW*MMD/1024
#define NB_SMEM 1920    // BB*SSL*MMD/1024
#define NB_WMP  256     // HH*MMD/1024
#define NB_SMP  256
#define NB_VD2W 25000   // VV*HH/1024
#define NB_PREP (NB_GIGH + NB_WMEM + NB_SMEM + NB_WMP + NB_SMP + NB_VD2W)

__global__ void prep_kernel(
    const float* __restrict__ emb, const int* __restrict__ y, const float* __restrict__ h0,
    const float* __restrict__ gwih, const float* __restrict__ gbih,
    const float* __restrict__ gwhh, const float* __restrict__ gbhh,
    float* __restrict__ gi, float* __restrict__ gh, float* __restrict__ yemb,
    const float* __restrict__ wmem, __nv_bfloat16* __restrict__ wmH, __nv_bfloat16* __restrict__ wmL,
    const float* __restrict__ smemb, __nv_bfloat16* __restrict__ smH, __nv_bfloat16* __restrict__ smL,
    const float* __restrict__ wmp, __nv_bfloat16* __restrict__ wpH, __nv_bfloat16* __restrict__ wpL,
    const float* __restrict__ smp, __nv_bfloat16* __restrict__ spH, __nv_bfloat16* __restrict__ spL,
    const float* __restrict__ vd2w, __nv_bfloat16* __restrict__ v2H, __nv_bfloat16* __restrict__ v2L)
{
    __shared__ float As[16][68];
    __shared__ float Ws[16][68];
    int bid = blockIdx.x;
    int tid = threadIdx.x;

    if (bid >= NB_GIGH) {
        // ---- presplit region ----
        int pb = bid - NB_GIGH;
        const float* src; __nv_bfloat16* dh; __nv_bfloat16* dl; int base;
        if (pb < NB_WMEM)                       { src = wmem;  dh = wmH; dl = wmL; base = pb; }
        else if (pb < NB_WMEM + NB_SMEM)        { src = smemb; dh = smH; dl = smL; base = pb - NB_WMEM; }
        else if (pb < NB_WMEM + NB_SMEM + NB_WMP) { src = wmp; dh = wpH; dl = wpL; base = pb - NB_WMEM - NB_SMEM; }
        else if (pb < NB_WMEM + NB_SMEM + NB_WMP + NB_SMP) { src = smp; dh = spH; dl = spL; base = pb - NB_WMEM - NB_SMEM - NB_WMP; }
        else { src = vd2w; dh = v2H; dl = v2L; base = pb - NB_WMEM - NB_SMEM - NB_WMP - NB_SMP; }
        size_t i = (size_t)base * 256 + tid;
        float4 x = ((const float4*)src)[i];
        unsigned h01, l01, h23, l23;
        split2(x.x, x.y, h01, l01);
        split2(x.z, x.w, h23, l23);
        ((uint2*)dh)[i] = make_uint2(h01, h23);
        ((uint2*)dl)[i] = make_uint2(l01, l23);
        return;
    }

    // ---- gigh GEMM: z=0 -> gi (A = emb[y]); z=1 -> gh (A = h0) ----
    int gx = bid % 24, gy = (bid / 24) % 2, gz = bid / 48;
    int tx = tid & 15, ty = tid >> 4;
    int K = gz ? HH : EMB_;
    const float* W = gz ? gwhh : gwih;
    const float* bias = gz ? gbhh : gbih;
    float* C = gz ? gh : gi;
    int rb = gy * 64, cb = gx * 64;
    int lr = tid >> 2, kq = tid & 3;
    int yrow = gz ? 0 : y[rb + lr];
    const float* Arow = gz ? &h0[(size_t)(rb + lr) * HH] : &emb[(size_t)yrow * EMB_];
    float acc[4][4] = {};

    for (int k0 = 0; k0 < K; k0 += 16) {
        float4 a4 = *(const float4*)&Arow[k0 + kq * 4];
        float4 w4 = *(const float4*)&W[(size_t)(cb + lr) * K + k0 + kq * 4];
        if (gz == 0 && gx == 0)
            *(float4*)&yemb[(size_t)(rb + lr) * EMB_ + k0 + kq * 4] = a4;
        As[kq * 4 + 0][lr] = a4.x; As[kq * 4 + 1][lr] = a4.y;
        As[kq * 4 + 2][lr] = a4.z; As[kq * 4 + 3][lr] = a4.w;
        Ws[kq * 4 + 0][lr] = w4.x; Ws[kq * 4 + 1][lr] = w4.y;
        Ws[kq * 4 + 2][lr] = w4.z; Ws[kq * 4 + 3][lr] = w4.w;
        __syncthreads();
#pragma unroll
        for (int kk = 0; kk < 16; kk++) {
            float4 a = *(const float4*)&As[kk][ty * 4];
            float4 w = *(const float4*)&Ws[kk][tx * 4];
            acc[0][0] += a.x * w.x; acc[0][1] += a.x * w.y; acc[0][2] += a.x * w.z; acc[0][3] += a.x * w.w;
            acc[1][0] += a.y * w.x; acc[1][1] += a.y * w.y; acc[1][2] += a.y * w.z; acc[1][3] += a.y * w.w;
            acc[2][0] += a.z * w.x; acc[2][1] += a.z * w.y; acc[2][2] += a.z * w.z; acc[2][3] += a.z * w.w;
            acc[3][0] += a.w * w.x; acc[3][1] += a.w * w.y; acc[3][2] += a.w * w.z; acc[3][3] += a.w * w.w;
        }
        __syncthreads();
    }
#pragma unroll
    for (int i = 0; i < 4; i++) {
        int row = rb + ty * 4 + i;
#pragma unroll
        for (int j = 0; j < 4; j++) {
            int col = cb + tx * 4 + j;
            C[(size_t)row * (3 * HH) + col] = acc[i][j] + bias[col];
        }
    }
}

// -------------------- fused decoder projections: z=0 -> dpw, z=1 -> dps --------------------
__global__ void dpwdps_kernel(const float* __restrict__ hl,
                              const float* __restrict__ wdpw, const float* __restrict__ wdpb,
                              const float* __restrict__ sdpw, const float* __restrict__ sdpb,
                              float* __restrict__ dpw, float* __restrict__ dps) {
    __shared__ float As[16][68];
    __shared__ float Ws[16][68];
    int tid = threadIdx.x;
    int tx = tid & 15, ty = tid >> 4;
    int z = blockIdx.z;
    const float* W = z ? sdpw : wdpw;
    const float* bias = z ? sdpb : wdpb;
    float* C = z ? dps : dpw;
    const int K = HH;
    int rb = blockIdx.y * 64, cb = blockIdx.x * 64;
    int lr = tid >> 2, kq = tid & 3;
    float acc[4][4] = {};

    for (int k0 = 0; k0 < K; k0 += 16) {
        float4 a4 = *(const float4*)&hl[(size_t)(rb + lr) * K + k0 + kq * 4];
        float4 w4 = *(const float4*)&W[(size_t)(cb + lr) * K + k0 + kq * 4];
        As[kq * 4 + 0][lr] = a4.x; As[kq * 4 + 1][lr] = a4.y;
        As[kq * 4 + 2][lr] = a4.z; As[kq * 4 + 3][lr] = a4.w;
        Ws[kq * 4 + 0][lr] = w4.x; Ws[kq * 4 + 1][lr] = w4.y;
        Ws[kq * 4 + 2][lr] = w4.z; Ws[kq * 4 + 3][lr] = w4.w;
        __syncthreads();
#pragma unroll
        for (int kk = 0; kk < 16; kk++) {
            float4 a = *(const float4*)&As[kk][ty * 4];
            float4 w = *(const float4*)&Ws[kk][tx * 4];
            acc[0][0] += a.x * w.x; acc[0][1] += a.x * w.y; acc[0][2] += a.x * w.z; acc[0][3] += a.x * w.w;
            acc[1][0] += a.y * w.x; acc[1][1] += a.y * w.y; acc[1][2] += a.y * w.z; acc[1][3] += a.y * w.w;
            acc[2][0] += a.z * w.x; acc[2][1] += a.z * w.y; acc[2][2] += a.z * w.z; acc[2][3] += a.z * w.w;
            acc[3][0] += a.w * w.x; acc[3][1] += a.w * w.y; acc[3][2] += a.w * w.z; acc[3][3] += a.w * w.w;
        }
        __syncthreads();
    }
#pragma unroll
    for (int i = 0; i < 4; i++) {
        int row = rb + ty * 4 + i;
#pragma unroll
        for (int j = 0; j < 4; j++) {
            int col = cb + tx * 4 + j;
            C[(size_t)row * HH + col] = acc[i][j] + bias[col];
        }
    }
}

// -------------------- generic scalar SGEMM (hid) --------------------
__global__ void gemm_bias_kernel(const float* __restrict__ A, const float* __restrict__ W,
                                 const float* __restrict__ bias, float* __restrict__ C,
                                 int M, int N, int K) {
    __shared__ float As[16][68];
    __shared__ float Ws[16][68];
    int tid = threadIdx.x;
    int tx = tid & 15, ty = tid >> 4;
    int rb = blockIdx.y * 64, cb = blockIdx.x * 64;
    int lr = tid >> 2, kq = tid & 3;
    float acc[4][4] = {};

    for (int k0 = 0; k0 < K; k0 += 16) {
        float4 a4 = make_float4(0.f, 0.f, 0.f, 0.f);
        float4 w4 = make_float4(0.f, 0.f, 0.f, 0.f);
        if (rb + lr < M) a4 = *(const float4*)&A[(size_t)(rb + lr) * K + k0 + kq * 4];
        if (cb + lr < N) w4 = *(const float4*)&W[(size_t)(cb + lr) * K + k0 + kq * 4];
        As[kq * 4 + 0][lr] = a4.x; As[kq * 4 + 1][lr] = a4.y;
        As[kq * 4 + 2][lr] = a4.z; As[kq * 4 + 3][lr] = a4.w;
        Ws[kq * 4 + 0][lr] = w4.x; Ws[kq * 4 + 1][lr] = w4.y;
        Ws[kq * 4 + 2][lr] = w4.z; Ws[kq * 4 + 3][lr] = w4.w;
        __syncthreads();
#pragma unroll
        for (int kk = 0; kk < 16; kk++) {
            float4 a = *(const float4*)&As[kk][ty * 4];
            float4 w = *(const float4*)&Ws[kk][tx * 4];
            acc[0][0] += a.x * w.x; acc[0][1] += a.x * w.y; acc[0][2] += a.x * w.z; acc[0][3] += a.x * w.w;
            acc[1][0] += a.y * w.x; acc[1][1] += a.y * w.y; acc[1][2] += a.y * w.z; acc[1][3] += a.y * w.w;
            acc[2][0] += a.z * w.x; acc[2][1] += a.z * w.y; acc[2][2] += a.z * w.z; acc[2][3] += a.z * w.w;
            acc[3][0] += a.w * w.x; acc[3][1] += a.w * w.y; acc[3][2] += a.w * w.z; acc[3][3] += a.w * w.w;
        }
        __syncthreads();
    }
#pragma unroll
    for (int i = 0; i < 4; i++) {
        int row = rb + ty * 4 + i;
        if (row >= M) continue;
#pragma unroll
        for (int j = 0; j < 4; j++) {
            int col = cb + tx * 4 + j;
            if (col < N) C[(size_t)row * N + col] = acc[i][j] + (bias ? bias[col] : 0.f);
        }
    }
}

// ==================== attention scores: chunk-parallel 128x128 tiles, k-step 32, 1 barrier/stage ====================
#define AT_T   (128 * SPITCH)                // 5120 elems per half-tile (128 rows x 40 pitch; 32 k used)
#define AT_BUF (4 * AT_T)                    // Ah|Al|Wh|Wl
#define AT_DYN (2 * AT_BUF * 2)              // 81920 bytes
template <bool HAS_COV>
__global__ void __launch_bounds__(256, 2)
attn_scores_mma(const __nv_bfloat16* __restrict__ memH, const __nv_bfloat16* __restrict__ memL,
                const __nv_bfloat16* __restrict__ WmH, const __nv_bfloat16* __restrict__ WmL,
                const float* __restrict__ dproj, const float* __restrict__ v,
                const float* __restrict__ wcov, const float* __restrict__ cov,
                float* __restrict__ scores, int Lper) {
    const int K = 512;
    extern __shared__ __nv_bfloat16 dyn[];
    __shared__ float rowred[128];

    int tid = threadIdx.x;
    int wid = tid >> 5, lane = tid & 31;
    int rg = wid >> 2, cg = wid & 3;         // 2 row-groups x 4 col-groups
    int warpRow = rg * 64, warpCol = cg * 32;
    int g = lane >> 2, tg = lane & 3;
    int rowBase = blockIdx.x * 128;
    int col0 = blockIdx.y * 128;
    int frow = tid & 127, fhf = tid >> 7;    // fill: 128 rows x 2 base-halves; each thread 2 chunks/half-tile

    // ldmatrix per-lane offsets (bytes)
    int r8 = lane & 7, quad = lane >> 3;
    unsigned a_lane = ((unsigned)((r8 + (quad & 1) * 8) * SPITCH + (quad >> 1) * 8)) * 2;
    unsigned w_lane = ((unsigned)(((quad >> 1) * 8 + r8) * SPITCH + (quad & 1) * 8)) * 2;
    unsigned sdyn = (unsigned)__cvta_generic_to_shared(dyn);

    if (tid < 128) rowred[tid] = 0.f;

    float covr[8];
    if (HAS_COV) {
#pragma unroll
        for (int mt = 0; mt < 4; mt++) {
            covr[2 * mt]     = cov[rowBase + warpRow + mt * 16 + g];
            covr[2 * mt + 1] = cov[rowBase + warpRow + mt * 16 + g + 8];
        }
    }
    float rs[8] = {};

    // fills 32 k-columns: each thread 2x 16B chunks per half-tile (k-offsets fhf*8 and fhf*8+16)
    auto do_fill = [&](int b, int k0) {
        __nv_bfloat16* base = dyn + b * AT_BUF;
        size_t ga = (size_t)(rowBase + frow) * K + k0 + fhf * 8;
        size_t gw = (size_t)(col0 + frow) * K + k0 + fhf * 8;
        unsigned so = frow * SPITCH + fhf * 8;
        cp16(&base[0 * AT_T + so],      &memH[ga]);
        cp16(&base[0 * AT_T + so + 16], &memH[ga + 16]);
        cp16(&base[1 * AT_T + so],      &memL[ga]);
        cp16(&base[1 * AT_T + so + 16], &memL[ga + 16]);
        cp16(&base[2 * AT_T + so],      &WmH[gw]);
        cp16(&base[2 * AT_T + so + 16], &WmH[gw + 16]);
        cp16(&base[3 * AT_T + so],      &WmL[gw]);
        cp16(&base[3 * AT_T + so + 16], &WmL[gw + 16]);
        CP_COMMIT();
    };

    do_fill(0, 0);
    int cur = 0;
    float acc[4][4][4] = {};
    for (int k0 = 0; k0 < K; k0 += 32) {
        cp_wait<0>();
        __syncthreads();               // all warps' fills visible; prior reads done
        if (k0 + 32 < K) do_fill(cur ^ 1, k0 + 32);   // refill issued AFTER barrier -> safe

        unsigned sbase = sdyn + (unsigned)cur * (AT_BUF * 2);
#pragma unroll
        for (int h = 0; h < 2; h++) {
            unsigned hoff = (unsigned)(h * 16) * 2;   // +16 k-cols in bytes
            unsigned AhB = sbase + hoff;
            unsigned AlB = sbase + AT_T * 2 + hoff;
            unsigned WhB = sbase + 2 * AT_T * 2 + hoff;
            unsigned WlB = sbase + 3 * AT_T * 2 + hoff;

            unsigned bh[2][4], bl[2][4];
#pragma unroll
            for (int p = 0; p < 2; p++) {
                unsigned wo = (unsigned)((warpCol + p * 16) * SPITCH) * 2 + w_lane;
                ldsm_x4(bh[p], WhB + wo);
                ldsm_x4(bl[p], WlB + wo);
            }
#pragma unroll
            for (int mt = 0; mt < 4; mt++) {
                unsigned ao = (unsigned)((warpRow + mt * 16) * SPITCH) * 2 + a_lane;
                unsigned ah[4], al[4];
                ldsm_x4(ah, AhB + ao);
                ldsm_x4(al, AlB + ao);
#pragma unroll
                for (int nb = 0; nb < 4; nb++) {
                    const unsigned* ph = &bh[nb >> 1][(nb & 1) * 2];
                    const unsigned* pl = &bl[nb >> 1][(nb & 1) * 2];
                    mma_bf16(acc[mt][nb], ah, ph);
                    mma_bf16(acc[mt][nb], ah, pl);
                    mma_bf16(acc[mt][nb], al, ph);
                }
            }
        }
        cur ^= 1;
    }
    // epilogue: tanh + v-weighted partial sums over this block's 128 d-columns
#pragma unroll
    for (int mt = 0; mt < 4; mt++) {
        int r0 = rowBase + warpRow + mt * 16 + g;
        int r1 = r0 + 8;
        int b0 = r0 / Lper, b1 = r1 / Lper;
#pragma unroll
        for (int nb = 0; nb < 4; nb++) {
            int d = col0 + warpCol + nb * 8 + tg * 2;
#pragma unroll
            for (int jj = 0; jj < 2; jj++) {
                int dd = d + jj;
                float vd = v[dd];
                float wc = HAS_COV ? wcov[dd] : 0.f;
                float f0 = acc[mt][nb][jj]     + dproj[(size_t)b0 * HH + dd];
                float f1 = acc[mt][nb][2 + jj] + dproj[(size_t)b1 * HH + dd];
                if (HAS_COV) { f0 += covr[2 * mt] * wc; f1 += covr[2 * mt + 1] * wc; }
                rs[2 * mt]     += tanhf(f0) * vd;
                rs[2 * mt + 1] += tanhf(f1) * vd;
            }
        }
    }
#pragma unroll
    for (int i = 0; i < 8; i++) {
        float s = rs[i];
        s += __shfl_xor_sync(0xffffffffu, s, 1);
        s += __shfl_xor_sync(0xffffffffu, s, 2);
        int mt = i >> 1;
        int localRow = warpRow + mt * 16 + g + (i & 1) * 8;
        if (tg == 0) atomicAdd(&rowred[localRow], s);
    }
    __syncthreads();
    if (tid < 128) atomicAdd(&scores[rowBase + tid], rowred[tid]);
}

// ==================== bf16x3 mma GEMM (vocab logits): k-step 32, 1 barrier/stage ====================
#define VB_A  (64 * SPITCH)
#define VB_SZ (4 * VB_A)
__global__ void __launch_bounds__(256)
mma_gemm_bias(const __nv_bfloat16* __restrict__ AH, const __nv_bfloat16* __restrict__ AL,
              const __nv_bfloat16* __restrict__ WH, const __nv_bfloat16* __restrict__ WL,
              const float* __restrict__ bias, float* __restrict__ C,
              int M, int N, int K) {
    __shared__ __nv_bfloat16 smem[2][VB_SZ];
    int tid = threadIdx.x;
    int wid = tid >> 5, lane = tid & 31;
    int warpM = wid & 3, warpN = wid >> 2;
    int warpRow = warpM * 16, warpCol = warpN * 32;
    int g = lane >> 2, tg = lane & 3;
    int rb = blockIdx.y * 64, cb = blockIdx.x * 64;

    // fill mapping: A by threads 0-127, W by threads 128-255; 64 rows x 2 base-halves
    int frow = tid & 63, fq = (tid >> 6) & 1;
    int wfrow = (tid - 128) & 63, wfq = ((tid - 128) >> 6) & 1;

    int r8 = lane & 7, quad = lane >> 3;
    unsigned a_lane = ((unsigned)((r8 + (quad & 1) * 8) * SPITCH + (quad >> 1) * 8)) * 2;
    unsigned w_lane = ((unsigned)(((quad >> 1) * 8 + r8) * SPITCH + (quad & 1) * 8)) * 2;
    unsigned ssm = (unsigned)__cvta_generic_to_shared(&smem[0][0]);

    float acc[4][4] = {};

    auto do_fill = [&](int b, int k0) {
        if (tid < 128) {
            size_t ga = (size_t)(rb + frow) * K + k0 + fq * 8;
            unsigned so = frow * SPITCH + fq * 8;
            cp16(&smem[b][0 * VB_A + so],      &AH[ga]);
            cp16(&smem[b][0 * VB_A + so + 16], &AH[ga + 16]);
            cp16(&smem[b][1 * VB_A + so],      &AL[ga]);
            cp16(&smem[b][1 * VB_A + so + 16], &AL[ga + 16]);
        } else {
            bool ok = cb + wfrow < N;
            size_t gw = (size_t)(ok ? cb + wfrow : 0) * K + k0 + wfq * 8;
            unsigned so = wfrow * SPITCH + wfq * 8;
            cp16z(&smem[b][2 * VB_A + so],      &WH[gw], ok);
            cp16z(&smem[b][2 * VB_A + so + 16], &WH[gw + 16], ok);
            cp16z(&smem[b][3 * VB_A + so],      &WL[gw], ok);
            cp16z(&smem[b][3 * VB_A + so + 16], &WL[gw + 16], ok);
        }
        CP_COMMIT();
    };

    do_fill(0, 0);
    int cur = 0;
    for (int k0 = 0; k0 < K; k0 += 32) {
        cp_wait<0>();
        __syncthreads();
        if (k0 + 32 < K) do_fill(cur ^ 1, k0 + 32);

        unsigned sbase = ssm + (unsigned)cur * (VB_SZ * 2);
#pragma unroll
        for (int h = 0; h < 2; h++) {
            unsigned hoff = (unsigned)(h * 16) * 2;
            unsigned AhB = sbase + hoff;
            unsigned AlB = sbase + VB_A * 2 + hoff;
            unsigned WhB = sbase + 2 * VB_A * 2 + hoff;
            unsigned WlB = sbase + 3 * VB_A * 2 + hoff;

            unsigned ah[4], al[4];
            {
                unsigned ao = (unsigned)(warpRow * SPITCH) * 2 + a_lane;
                ldsm_x4(ah, AhB + ao);
                ldsm_x4(al, AlB + ao);
            }
            unsigned bh[2][4], bl[2][4];
#pragma unroll
            for (int p = 0; p < 2; p++) {
                unsigned wo = (unsigned)((warpCol + p * 16) * SPITCH) * 2 + w_lane;
                ldsm_x4(bh[p], WhB + wo);
                ldsm_x4(bl[p], WlB + wo);
            }
#pragma unroll
            for (int nb = 0; nb < 4; nb++) {
                const unsigned* ph = &bh[nb >> 1][(nb & 1) * 2];
                const unsigned* pl = &bl[nb >> 1][(nb & 1) * 2];
                mma_bf16(acc[nb], ah, ph);
                mma_bf16(acc[nb], ah, pl);
                mma_bf16(acc[nb], al, ph);
            }
        }
        cur ^= 1;
    }

#pragma unroll
    for (int nb = 0; nb < 4; nb++) {
        int col = cb + warpCol + nb * 8 + tg * 2;
        int r0 = rb + warpRow + g, r1 = r0 + 8;
        if (col < N) {
            float bs = bias ? bias[col] : 0.f;
            if (r0 < M) C[(size_t)r0 * N + col] = acc[nb][0] + bs;
            if (r1 < M) C[(size_t)r1 * N + col] = acc[nb][2] + bs;
        }
        if (col + 1 < N) {
            float bs = bias ? bias[col + 1] : 0.f;
            if (r0 < M) C[(size_t)r0 * N + col + 1] = acc[nb][1] + bs;
            if (r1 < M) C[(size_t)r1 * N + col + 1] = acc[nb][3] + bs;
        }
    }
}

// -------------------- GRU combine + zero attention score buffers --------------------
__global__ void gru_kernel(const float* __restrict__ gi, const float* __restrict__ gh,
                           const float* __restrict__ h0, float* __restrict__ hlast,
                           float* __restrict__ cat, float* __restrict__ out_h,
                           float* __restrict__ wsc, float* __restrict__ ssc) {
    int idx = blockIdx.x * 256 + threadIdx.x;
    if (idx >= BB * HH) return;
    if (idx < BB * LW) wsc[idx] = 0.f;
    if (idx < BB * SSL) ssc[idx] = 0.f;
    int b = idx / HH, j = idx % HH;
    const float* gib = gi + (size_t)b * 3 * HH;
    const float* ghb = gh + (size_t)b * 3 * HH;
    float ir = gib[j], iz = gib[HH + j], in_ = gib[2 * HH + j];
    float hr = ghb[j], hz = ghb[HH + j], hn = ghb[2 * HH + j];
    float r = 1.f / (1.f + expf(-(ir + hr)));
    float z = 1.f / (1.f + expf(-(iz + hz)));
    float n = tanhf(in_ + r * hn);
    float hl = (1.f - z) * n + z * h0[idx];
    hlast[idx] = hl;
    cat[(size_t)b * 1536 + 1024 + j] = hl;
    out_h[idx] = hl;
}

// -------------------- softmax -> mask -> renormalize (+ coverage update) --------------------
__global__ void softmax_mask_kernel(const float* __restrict__ scores, const float* __restrict__ mask,
                                    const float* __restrict__ cov, float* __restrict__ attn_out,
                                    float* __restrict__ cov_out, int N) {
    __shared__ float buf[512];
    __shared__ float red[128];
    int b = blockIdx.x, tid = threadIdx.x;
    const float* s = scores + (size_t)b * N;
    float mx = -1e30f;
    for (int i = tid; i < N; i += 128) { float vv = s[i]; buf[i] = vv; mx = fmaxf(mx, vv); }
    red[tid] = mx; __syncthreads();
    for (int off = 64; off; off >>= 1) { if (tid < off) red[tid] = fmaxf(red[tid], red[tid + off]); __syncthreads(); }
    mx = red[0]; __syncthreads();
    float sum = 0.f;
    for (int i = tid; i < N; i += 128) { float e = expf(buf[i] - mx); buf[i] = e; sum += e; }
    red[tid] = sum; __syncthreads();
    for (int off = 64; off; off >>= 1) { if (tid < off) red[tid] += red[tid + off]; __syncthreads(); }
    sum = red[0]; __syncthreads();
    float s2 = 0.f;
    for (int i = tid; i < N; i += 128) { float t = (buf[i] / sum) * mask[(size_t)b * N + i]; buf[i] = t; s2 += t; }
    red[tid] = s2; __syncthreads();
    for (int off = 64; off; off >>= 1) { if (tid < off) red[tid] += red[tid + off]; __syncthreads(); }
    s2 = red[0];
    float inv = 1.f / (s2 + 1e-10f);
    for (int i = tid; i < N; i += 128) {
        float a = buf[i] * inv;
        attn_out[(size_t)b * N + i] = a;
        if (cov_out) cov_out[(size_t)b * N + i] = cov[(size_t)b * N + i] + a;
    }
}

// -------------------- context: ctx[b,m] = sum_l attn[b,l] * mem[b,l,m] --------------------
__global__ void context_kernel(const float* __restrict__ attn, const float* __restrict__ mem,
                               float* __restrict__ ctx_out, float* __restrict__ cat,
                               int Lc, int catOff) {
    __shared__ float a_s[512];
    int b = blockIdx.x;
    int m = blockIdx.y * 128 + threadIdx.x;
    for (int i = threadIdx.x; i < Lc; i += 128) a_s[i] = attn[(size_t)b * Lc + i];
    __syncthreads();
    const float* mb = mem + (size_t)b * Lc * MMD + m;
    float acc = 0.f;
#pragma unroll 4
    for (int l = 0; l < Lc; l++) acc += a_s[l] * mb[(size_t)l * MMD];
    if (ctx_out) ctx_out[(size_t)b * MMD + m] = acc;
    cat[(size_t)b * 1536 + catOff + m] = acc;
}

// -------------------- p_gen --------------------
__global__ void pgen_kernel(const float* __restrict__ cat, const float* __restrict__ yemb,
                            const float* __restrict__ pw, const float* __restrict__ pb,
                            float* __restrict__ pg_scr, float* __restrict__ pg_out) {
    __shared__ float red[256];
    int b = blockIdx.x, tid = threadIdx.x;
    float s = 0.f;
    for (int i = tid; i < 1536; i += 256) s += cat[(size_t)b * 1536 + i] * pw[i];
    for (int i = tid; i < EMB_; i += 256) s += yemb[(size_t)b * EMB_ + i] * pw[1536 + i];
    red[tid] = s; __syncthreads();
    for (int off = 128; off; off >>= 1) { if (tid < off) red[tid] += red[tid + off]; __syncthreads(); }
    if (tid == 0) {
        float p = 1.f / (1.f + expf(-(red[0] + pb[0])));
        pg_scr[b] = p;
        pg_out[b] = p;
    }
}

// -------------------- vocab softmax + p_gen mix + OOV scatter (1024 thr) --------------------
__global__ void __launch_bounds__(1024)
final_kernel(const float* __restrict__ logits, const float* __restrict__ pgen,
             const float* __restrict__ wattn, const int* __restrict__ src_oov,
             float* __restrict__ out_final) {
    __shared__ float red[1024];
    int b = blockIdx.x, tid = threadIdx.x;
    const float4* lg4 = (const float4*)(logits + (size_t)b * VV);
    const int n4 = VV / 4;
    float* fr = out_final + (size_t)b * VE;
    float2* fr2 = (float2*)fr;

    float mx = -1e30f;
    for (int i = tid; i < n4; i += 1024) {
        float4 x = lg4[i];
        mx = fmaxf(mx, fmaxf(fmaxf(x.x, x.y), fmaxf(x.z, x.w)));
    }
    red[tid] = mx; __syncthreads();
    for (int off = 512; off; off >>= 1) { if (tid < off) red[tid] = fmaxf(red[tid], red[tid + off]); __syncthreads(); }
    mx = red[0]; __syncthreads();

    float sum = 0.f;
    for (int i = tid; i < n4; i += 1024) {
        float4 x = lg4[i];
        float e0 = expf(x.x - mx), e1 = expf(x.y - mx);
        float e2 = expf(x.z - mx), e3 = expf(x.w - mx);
        sum += (e0 + e1) + (e2 + e3);
        fr2[2 * i]     = make_float2(e0, e1);
        fr2[2 * i + 1] = make_float2(e2, e3);
    }
    red[tid] = sum; __syncthreads();
    for (int off = 512; off; off >>= 1) { if (tid < off) red[tid] += red[tid + off]; __syncthreads(); }
    sum = red[0];
    float pg = pgen[b];
    float scale = pg / sum;
    for (int i = tid; i < n4; i += 1024) {
        float2 p0 = fr2[2 * i], p1 = fr2[2 * i + 1];
        p0.x *= scale; p0.y *= scale; p1.x *= scale; p1.y *= scale;
        fr2[2 * i] = p0; fr2[2 * i + 1] = p1;
    }
    for (int i = VV + tid; i < VE; i += 1024) fr[i] = 0.f;
    __syncthreads();
    float om = 1.f - pg;
    if (tid < LW) {
        int idx = src_oov[(size_t)b * LW + tid];
        atomicAdd(&fr[idx], om * wattn[(size_t)b * LW + tid]);
    }
}

// -------------------- launcher --------------------
extern "C" void kernel_launch(void* const* d_in, const int* in_sizes, int n_in,
                              void* d_out, int out_size) {
    (void)in_sizes; (void)n_in; (void)out_size;
    const float* h0   = (const float*)d_in[0];
    const float* wmem = (const float*)d_in[1];
    const float* smem_bank = (const float*)d_in[2];
    const float* wmask = (const float*)d_in[3];
    const float* smask = (const float*)d_in[4];
    const float* cov   = (const float*)d_in[5];
    const float* emb   = (const float*)d_in[6];
    const float* gwih  = (const float*)d_in[7];
    const float* gwhh  = (const float*)d_in[8];
    const float* gbih  = (const float*)d_in[9];
    const float* gbhh  = (const float*)d_in[10];
    const float* wmp   = (const float*)d_in[11];
    const float* wdpw  = (const float*)d_in[12];
    const float* wdpb  = (const float*)d_in[13];
    const float* wv    = (const float*)d_in[14];
    const float* wcp   = (const float*)d_in[15];
    const float* smp   = (const float*)d_in[16];
    const float* sdpw  = (const float*)d_in[17];
    const float* sdpb  = (const float*)d_in[18];
    const float* sv    = (const float*)d_in[19];
    const float* pgw   = (const float*)d_in[20];
    const float* pgb   = (const float*)d_in[21];
    const float* vd1w  = (const float*)d_in[22];
    const float* vd1b  = (const float*)d_in[23];
    const float* vd2w  = (const float*)d_in[24];
    const float* vd2b  = (const float*)d_in[25];
    const int*   y     = (const int*)d_in[26];
    const int*   soov  = (const int*)d_in[27];
    float* out = (float*)d_out;

    float *yemb, *gi, *gh, *hl, *dpw, *dps, *wsc, *ssc, *sat, *cat, *hid, *pg, *lg;
    __nv_bfloat16 *wmH, *wmL, *smH, *smL, *wpH, *wpL, *spH, *spL, *hdH, *hdL, *v2H, *v2L;
    cudaGetSymbolAddress((void**)&yemb, g_yemb);
    cudaGetSymbolAddress((void**)&gi,   g_gi);
    cudaGetSymbolAddress((void**)&gh,   g_gh);
    cudaGetSymbolAddress((void**)&hl,   g_hlast);
    cudaGetSymbolAddress((void**)&dpw,  g_dpw);
    cudaGetSymbolAddress((void**)&dps,  g_dps);
    cudaGetSymbolAddress((void**)&wsc,  g_wscores);
    cudaGetSymbolAddress((void**)&ssc,  g_sscores);
    cudaGetSymbolAddress((void**)&sat,  g_sattn);
    cudaGetSymbolAddress((void**)&cat,  g_cat);
    cudaGetSymbolAddress((void**)&hid,  g_hid);
    cudaGetSymbolAddress((void**)&pg,   g_pgen);
    cudaGetSymbolAddress((void**)&lg,   g_logits);
    cudaGetSymbolAddress((void**)&wmH,  g_wmemH);
    cudaGetSymbolAddress((void**)&wmL,  g_wmemL);
    cudaGetSymbolAddress((void**)&smH,  g_smemH);
    cudaGetSymbolAddress((void**)&smL,  g_smemL);
    cudaGetSymbolAddress((void**)&wpH,  g_wmpH);
    cudaGetSymbolAddress((void**)&wpL,  g_wmpL);
    cudaGetSymbolAddress((void**)&spH,  g_smpH);
    cudaGetSymbolAddress((void**)&spL,  g_smpL);
    cudaGetSymbolAddress((void**)&hdH,  g_hidH);
    cudaGetSymbolAddress((void**)&hdL,  g_hidL);
    cudaGetSymbolAddress((void**)&v2H,  g_vd2wH);
    cudaGetSymbolAddress((void**)&v2L,  g_vd2wL);

    cudaFuncSetAttribute(attn_scores_mma<true>,
                         cudaFuncAttributeMaxDynamicSharedMemorySize, AT_DYN);
    cudaFuncSetAttribute(attn_scores_mma<false>,
                         cudaFuncAttributeMaxDynamicSharedMemorySize, AT_DYN);

    // 0: prep — gigh GEMMs + all big presplits, one launch
    prep_kernel<<<NB_PREP, 256>>>(emb, y, h0, gwih, gbih, gwhh, gbhh, gi, gh, yemb,
                                  wmem, wmH, wmL, smem_bank, smH, smL,
                                  wmp, wpH, wpL, smp, spH, spL, vd2w, v2H, v2L);
    // 1: GRU combine (+ zero score buffers for atomic accumulation)
    gru_kernel<<<(BB * HH + 255) / 256, 256>>>(gi, gh, h0, hl, cat, out + OUT_H, wsc, ssc);
    // 2: fused decoder-state projections
    dpwdps_kernel<<<dim3(8, 2, 2), 256>>>(hl, wdpw, wdpb, sdpw, sdpb, dpw, dps);
    // 3: word attention scores (chunk-parallel)  <-- profiled launch
    attn_scores_mma<true ><<<dim3((BB * LW) / 128, 4), 256, AT_DYN>>>(wmH, wmL, wpH, wpL, dpw, wv, wcp, cov, wsc, LW);
    // 4: sentence attention scores (chunk-parallel)
    attn_scores_mma<false><<<dim3((BB * SSL) / 128, 4), 256, AT_DYN>>>(smH, smL, spH, spL, dps, sv, nullptr, nullptr, ssc, SSL);

    // softmax + mask + renorm (+ coverage output for word)
    softmax_mask_kernel<<<BB, 128>>>(wsc, wmask, cov, out + OUT_WATTN, out + OUT_WCOV, LW);
    softmax_mask_kernel<<<BB, 128>>>(ssc, smask, nullptr, sat, nullptr, SSL);

    // contexts
    context_kernel<<<dim3(BB, 4), 128>>>(out + OUT_WATTN, wmem, out + OUT_WCTX, cat, LW, 0);
    context_kernel<<<dim3(BB, 4), 128>>>(sat, smem_bank, nullptr, cat, SSL, 512);

    // p_gen
    pgen_kernel<<<BB, 256>>>(cat, yemb, pgw, pgb, pg, out + OUT_PGEN);

    // vocab head
    gemm_bias_kernel<<<dim3(8, 2), 256>>>(cat, vd1w, vd1b, hid, BB, HH, 3 * HH);
    presplit_kernel<<<(BB * HH / 4 + 255) / 256, 256>>>(hid, hdH, hdL, BB * HH / 4);
    mma_gemm_bias<<<dim3((VV + 63) / 64, 2), 256>>>(hdH, hdL, v2H, v2L, vd2b, lg, BB, VV, HH);

    // vocab softmax, p_gen mix, zeros for OOV slots, scatter-add of copy dist
    final_kernel<<<BB, 1024>>>(lg, pg, out + OUT_WATTN, soov, out + OUT_FINAL);
}

// round 14
// speedup vs baseline: 1.2881x; 1.0539x over previous
#include <cuda_runtime.h>
#include <cuda_bf16.h>
#include <math.h>

// Problem constants
#define BB   128
#define LW   400
#define SSL  30
#define VV   50000
#define EMB_ 128
#define HH   512
#define MMD  512
#define OOVN 30
#define VE   (VV + OOVN)   // 50030

// Output layout: concat of (final_dist, h_next, word_ctx, word_attn, p_gen, word_cov)
#define OUT_FINAL 0
#define OUT_H     (BB * VE)
#define OUT_WCTX  (OUT_H + BB * HH)
#define OUT_WATTN (OUT_WCTX + BB * MMD)
#define OUT_PGEN  (OUT_WATTN + BB * LW)
#define OUT_WCOV  (OUT_PGEN + BB)

#define SPITCH 40   // smem bf16 row pitch (80B rows; 32 k-cols + pad; ldmatrix conflict-free)

// -------------------- scratch (no allocations allowed) --------------------
__device__ float g_yemb[BB * EMB_];
__device__ float g_gi[BB * 3 * HH];
__device__ float g_gh[BB * 3 * HH];
__device__ float g_hlast[BB * HH];
__device__ float g_dpw[BB * HH];
__device__ float g_dps[BB * HH];
__device__ float g_wscores[BB * LW];
__device__ float g_sscores[BB * SSL];
__device__ float g_sattn[BB * SSL];
__device__ float g_cat[BB * 3 * HH];     // [word_ctx | sent_ctx | h_last]
__device__ float g_hid[BB * HH];
__device__ float g_pgen[BB];
__device__ float g_logits[(size_t)BB * VV];

// pre-split bf16 (hi, lo) buffers
__device__ __nv_bfloat16 g_wmemH[(size_t)BB * LW * MMD];
__device__ __nv_bfloat16 g_wmemL[(size_t)BB * LW * MMD];
__device__ __nv_bfloat16 g_smemH[BB * SSL * MMD];
__device__ __nv_bfloat16 g_smemL[BB * SSL * MMD];
__device__ __nv_bfloat16 g_wmpH[HH * MMD];
__device__ __nv_bfloat16 g_wmpL[HH * MMD];
__device__ __nv_bfloat16 g_smpH[HH * MMD];
__device__ __nv_bfloat16 g_smpL[HH * MMD];
__device__ __nv_bfloat16 g_hidH[BB * HH];
__device__ __nv_bfloat16 g_hidL[BB * HH];
__device__ __nv_bfloat16 g_vd2wH[(size_t)VV * HH];
__device__ __nv_bfloat16 g_vd2wL[(size_t)VV * HH];

// -------------------- helpers --------------------
__device__ __forceinline__ unsigned pack_bf2(__nv_bfloat16 a, __nv_bfloat16 b) {
    __nv_bfloat162 t(a, b);
    return *(unsigned*)&t;
}
__device__ __forceinline__ void split1(float x, __nv_bfloat16& h, __nv_bfloat16& l) {
    h = __float2bfloat16_rn(x);
    l = __float2bfloat16_rn(x - __bfloat162float(h));
}
__device__ __forceinline__ void split2(float x, float y, unsigned& hi2, unsigned& lo2) {
    __nv_bfloat16 hx, lx, hy, ly;
    split1(x, hx, lx); split1(y, hy, ly);
    hi2 = pack_bf2(hx, hy);
    lo2 = pack_bf2(lx, ly);
}
__device__ __forceinline__ void split_store(const float4& x, __nv_bfloat16* dh, __nv_bfloat16* dl, size_t i) {
    unsigned h01, l01, h23, l23;
    split2(x.x, x.y, h01, l01);
    split2(x.z, x.w, h23, l23);
    ((uint2*)dh)[i] = make_uint2(h01, h23);
    ((uint2*)dl)[i] = make_uint2(l01, l23);
}
__device__ __forceinline__ void mma_bf16(float* c, const unsigned* a, const unsigned* b) {
    asm volatile(
        "mma.sync.aligned.m16n8k16.row.col.f32.bf16.bf16.f32 "
        "{%0,%1,%2,%3}, {%4,%5,%6,%7}, {%8,%9}, {%0,%1,%2,%3};"
        : "+f"(c[0]), "+f"(c[1]), "+f"(c[2]), "+f"(c[3])
        : "r"(a[0]), "r"(a[1]), "r"(a[2]), "r"(a[3]), "r"(b[0]), "r"(b[1]));
}
// ldmatrix x4: four 8x8 b16 matrices; lane i supplies row addr for matrix i/8
__device__ __forceinline__ void ldsm_x4(unsigned* r, unsigned saddr) {
    asm volatile("ldmatrix.sync.aligned.m8n8.x4.shared.b16 {%0,%1,%2,%3}, [%4];"
        : "=r"(r[0]), "=r"(r[1]), "=r"(r[2]), "=r"(r[3]) : "r"(saddr));
}
// cp.async 16B
__device__ __forceinline__ void cp16(void* sptr, const void* gptr) {
    unsigned sa = (unsigned)__cvta_generic_to_shared(sptr);
    asm volatile("cp.async.cg.shared.global [%0], [%1], 16;" :: "r"(sa), "l"(gptr));
}
__device__ __forceinline__ void cp16z(void* sptr, const void* gptr, bool ok) {
    unsigned sa = (unsigned)__cvta_generic_to_shared(sptr);
    int sz = ok ? 16 : 0;
    asm volatile("cp.async.cg.shared.global [%0], [%1], 16, %2;" :: "r"(sa), "l"(gptr), "r"(sz));
}
#define CP_COMMIT() asm volatile("cp.async.commit_group;")
template <int N> __device__ __forceinline__ void cp_wait() {
    asm volatile("cp.async.wait_group %0;" :: "n"(N));
}

// -------------------- hid presplit (separate small launch) --------------------
__global__ void presplit_kernel(const float* __restrict__ src, __nv_bfloat16* __restrict__ dh,
                                __nv_bfloat16* __restrict__ dl, int n4) {
    int i = blockIdx.x * 256 + threadIdx.x;
    if (i >= n4) return;
    float4 x = ((const float4*)src)[i];
    split_store(x, dh, dl, i);
}

// ==================== prep: gigh GEMMs + ALL big presplits (4 float4/thread), one launch ====================
#define NB_GIGH 96
#define NB_WMEM 6400    // BB*LW*MMD/4096
#define NB_SMEM 480     // BB*SSL*MMD/4096
#define NB_WMP  64      // HH*MMD/4096
#define NB_SMP  64
#define NB_VD2W 6250    // VV*HH/4096
#define NB_PREP (NB_GIGH + NB_WMEM + NB_SMEM + NB_WMP + NB_SMP + NB_VD2W)

__global__ void prep_kernel(
    const float* __restrict__ emb, const int* __restrict__ y, const float* __restrict__ h0,
    const float* __restrict__ gwih, const float* __restrict__ gbih,
    const float* __restrict__ gwhh, const float* __restrict__ gbhh,
    float* __restrict__ gi, float* __restrict__ gh, float* __restrict__ yemb,
    const float* __restrict__ wmem, __nv_bfloat16* __restrict__ wmH, __nv_bfloat16* __restrict__ wmL,
    const float* __restrict__ smemb, __nv_bfloat16* __restrict__ smH, __nv_bfloat16* __restrict__ smL,
    const float* __restrict__ wmp, __nv_bfloat16* __restrict__ wpH, __nv_bfloat16* __restrict__ wpL,
    const float* __restrict__ smp, __nv_bfloat16* __restrict__ spH, __nv_bfloat16* __restrict__ spL,
    const float* __restrict__ vd2w, __nv_bfloat16* __restrict__ v2H, __nv_bfloat16* __restrict__ v2L)
{
    __shared__ float As[16][68];
    __shared__ float Ws[16][68];
    int bid = blockIdx.x;
    int tid = threadIdx.x;

    if (bid >= NB_GIGH) {
        // ---- presplit region: 4 front-loaded float4s per thread (MLP=4) ----
        int pb = bid - NB_GIGH;
        const float* src; __nv_bfloat16* dh; __nv_bfloat16* dl; int base;
        if (pb < NB_WMEM)                       { src = wmem;  dh = wmH; dl = wmL; base = pb; }
        else if (pb < NB_WMEM + NB_SMEM)        { src = smemb; dh = smH; dl = smL; base = pb - NB_WMEM; }
        else if (pb < NB_WMEM + NB_SMEM + NB_WMP) { src = wmp; dh = wpH; dl = wpL; base = pb - NB_WMEM - NB_SMEM; }
        else if (pb < NB_WMEM + NB_SMEM + NB_WMP + NB_SMP) { src = smp; dh = spH; dl = spL; base = pb - NB_WMEM - NB_SMEM - NB_WMP; }
        else { src = vd2w; dh = v2H; dl = v2L; base = pb - NB_WMEM - NB_SMEM - NB_WMP - NB_SMP; }
        size_t i0 = (size_t)base * 1024 + tid;
        float4 x0 = ((const float4*)src)[i0];
        float4 x1 = ((const float4*)src)[i0 + 256];
        float4 x2 = ((const float4*)src)[i0 + 512];
        float4 x3 = ((const float4*)src)[i0 + 768];
        split_store(x0, dh, dl, i0);
        split_store(x1, dh, dl, i0 + 256);
        split_store(x2, dh, dl, i0 + 512);
        split_store(x3, dh, dl, i0 + 768);
        return;
    }

    // ---- gigh GEMM: z=0 -> gi (A = emb[y]); z=1 -> gh (A = h0) ----
    int gx = bid % 24, gy = (bid / 24) % 2, gz = bid / 48;
    int tx = tid & 15, ty = tid >> 4;
    int K = gz ? HH : EMB_;
    const float* W = gz ? gwhh : gwih;
    const float* bias = gz ? gbhh : gbih;
    float* C = gz ? gh : gi;
    int rb = gy * 64, cb = gx * 64;
    int lr = tid >> 2, kq = tid & 3;
    int yrow = gz ? 0 : y[rb + lr];
    const float* Arow = gz ? &h0[(size_t)(rb + lr) * HH] : &emb[(size_t)yrow * EMB_];
    float acc[4][4] = {};

    for (int k0 = 0; k0 < K; k0 += 16) {
        float4 a4 = *(const float4*)&Arow[k0 + kq * 4];
        float4 w4 = *(const float4*)&W[(size_t)(cb + lr) * K + k0 + kq * 4];
        if (gz == 0 && gx == 0)
            *(float4*)&yemb[(size_t)(rb + lr) * EMB_ + k0 + kq * 4] = a4;
        As[kq * 4 + 0][lr] = a4.x; As[kq * 4 + 1][lr] = a4.y;
        As[kq * 4 + 2][lr] = a4.z; As[kq * 4 + 3][lr] = a4.w;
        Ws[kq * 4 + 0][lr] = w4.x; Ws[kq * 4 + 1][lr] = w4.y;
        Ws[kq * 4 + 2][lr] = w4.z; Ws[kq * 4 + 3][lr] = w4.w;
        __syncthreads();
#pragma unroll
        for (int kk = 0; kk < 16; kk++) {
            float4 a = *(const float4*)&As[kk][ty * 4];
            float4 w = *(const float4*)&Ws[kk][tx * 4];
            acc[0][0] += a.x * w.x; acc[0][1] += a.x * w.y; acc[0][2] += a.x * w.z; acc[0][3] += a.x * w.w;
            acc[1][0] += a.y * w.x; acc[1][1] += a.y * w.y; acc[1][2] += a.y * w.z; acc[1][3] += a.y * w.w;
            acc[2][0] += a.z * w.x; acc[2][1] += a.z * w.y; acc[2][2] += a.z * w.z; acc[2][3] += a.z * w.w;
            acc[3][0] += a.w * w.x; acc[3][1] += a.w * w.y; acc[3][2] += a.w * w.z; acc[3][3] += a.w * w.w;
        }
        __syncthreads();
    }
#pragma unroll
    for (int i = 0; i < 4; i++) {
        int row = rb + ty * 4 + i;
#pragma unroll
        for (int j = 0; j < 4; j++) {
            int col = cb + tx * 4 + j;
            C[(size_t)row * (3 * HH) + col] = acc[i][j] + bias[col];
        }
    }
}

// -------------------- fused decoder projections: z=0 -> dpw, z=1 -> dps --------------------
__global__ void dpwdps_kernel(const float* __restrict__ hl,
                              const float* __restrict__ wdpw, const float* __restrict__ wdpb,
                              const float* __restrict__ sdpw, const float* __restrict__ sdpb,
                              float* __restrict__ dpw, float* __restrict__ dps) {
    __shared__ float As[16][68];
    __shared__ float Ws[16][68];
    int tid = threadIdx.x;
    int tx = tid & 15, ty = tid >> 4;
    int z = blockIdx.z;
    const float* W = z ? sdpw : wdpw;
    const float* bias = z ? sdpb : wdpb;
    float* C = z ? dps : dpw;
    const int K = HH;
    int rb = blockIdx.y * 64, cb = blockIdx.x * 64;
    int lr = tid >> 2, kq = tid & 3;
    float acc[4][4] = {};

    for (int k0 = 0; k0 < K; k0 += 16) {
        float4 a4 = *(const float4*)&hl[(size_t)(rb + lr) * K + k0 + kq * 4];
        float4 w4 = *(const float4*)&W[(size_t)(cb + lr) * K + k0 + kq * 4];
        As[kq * 4 + 0][lr] = a4.x; As[kq * 4 + 1][lr] = a4.y;
        As[kq * 4 + 2][lr] = a4.z; As[kq * 4 + 3][lr] = a4.w;
        Ws[kq * 4 + 0][lr] = w4.x; Ws[kq * 4 + 1][lr] = w4.y;
        Ws[kq * 4 + 2][lr] = w4.z; Ws[kq * 4 + 3][lr] = w4.w;
        __syncthreads();
#pragma unroll
        for (int kk = 0; kk < 16; kk++) {
            float4 a = *(const float4*)&As[kk][ty * 4];
            float4 w = *(const float4*)&Ws[kk][tx * 4];
            acc[0][0] += a.x * w.x; acc[0][1] += a.x * w.y; acc[0][2] += a.x * w.z; acc[0][3] += a.x * w.w;
            acc[1][0] += a.y * w.x; acc[1][1] += a.y * w.y; acc[1][2] += a.y * w.z; acc[1][3] += a.y * w.w;
            acc[2][0] += a.z * w.x; acc[2][1] += a.z * w.y; acc[2][2] += a.z * w.z; acc[2][3] += a.z * w.w;
            acc[3][0] += a.w * w.x; acc[3][1] += a.w * w.y; acc[3][2] += a.w * w.z; acc[3][3] += a.w * w.w;
        }
        __syncthreads();
    }
#pragma unroll
    for (int i = 0; i < 4; i++) {
        int row = rb + ty * 4 + i;
#pragma unroll
        for (int j = 0; j < 4; j++) {
            int col = cb + tx * 4 + j;
            C[(size_t)row * HH + col] = acc[i][j] + bias[col];
        }
    }
}

// -------------------- generic scalar SGEMM (hid) --------------------
__global__ void gemm_bias_kernel(const float* __restrict__ A, const float* __restrict__ W,
                                 const float* __restrict__ bias, float* __restrict__ C,
                                 int M, int N, int K) {
    __shared__ float As[16][68];
    __shared__ float Ws[16][68];
    int tid = threadIdx.x;
    int tx = tid & 15, ty = tid >> 4;
    int rb = blockIdx.y * 64, cb = blockIdx.x * 64;
    int lr = tid >> 2, kq = tid & 3;
    float acc[4][4] = {};

    for (int k0 = 0; k0 < K; k0 += 16) {
        float4 a4 = make_float4(0.f, 0.f, 0.f, 0.f);
        float4 w4 = make_float4(0.f, 0.f, 0.f, 0.f);
        if (rb + lr < M) a4 = *(const float4*)&A[(size_t)(rb + lr) * K + k0 + kq * 4];
        if (cb + lr < N) w4 = *(const float4*)&W[(size_t)(cb + lr) * K + k0 + kq * 4];
        As[kq * 4 + 0][lr] = a4.x; As[kq * 4 + 1][lr] = a4.y;
        As[kq * 4 + 2][lr] = a4.z; As[kq * 4 + 3][lr] = a4.w;
        Ws[kq * 4 + 0][lr] = w4.x; Ws[kq * 4 + 1][lr] = w4.y;
        Ws[kq * 4 + 2][lr] = w4.z; Ws[kq * 4 + 3][lr] = w4.w;
        __syncthreads();
#pragma unroll
        for (int kk = 0; kk < 16; kk++) {
            float4 a = *(const float4*)&As[kk][ty * 4];
            float4 w = *(const float4*)&Ws[kk][tx * 4];
            acc[0][0] += a.x * w.x; acc[0][1] += a.x * w.y; acc[0][2] += a.x * w.z; acc[0][3] += a.x * w.w;
            acc[1][0] += a.y * w.x; acc[1][1] += a.y * w.y; acc[1][2] += a.y * w.z; acc[1][3] += a.y * w.w;
            acc[2][0] += a.z * w.x; acc[2][1] += a.z * w.y; acc[2][2] += a.z * w.z; acc[2][3] += a.z * w.w;
            acc[3][0] += a.w * w.x; acc[3][1] += a.w * w.y; acc[3][2] += a.w * w.z; acc[3][3] += a.w * w.w;
        }
        __syncthreads();
    }
#pragma unroll
    for (int i = 0; i < 4; i++) {
        int row = rb + ty * 4 + i;
        if (row >= M) continue;
#pragma unroll
        for (int j = 0; j < 4; j++) {
            int col = cb + tx * 4 + j;
            if (col < N) C[(size_t)row * N + col] = acc[i][j] + (bias ? bias[col] : 0.f);
        }
    }
}

// ==================== attention scores: chunk-parallel 128x128 tiles, k-step 32, 1 barrier/stage ====================
#define AT_T   (128 * SPITCH)                // 5120 elems per half-tile (128 rows x 40 pitch; 32 k used)
#define AT_BUF (4 * AT_T)                    // Ah|Al|Wh|Wl
#define AT_DYN (2 * AT_BUF * 2)              // 81920 bytes
template <bool HAS_COV>
__global__ void __launch_bounds__(256, 2)
attn_scores_mma(const __nv_bfloat16* __restrict__ memH, const __nv_bfloat16* __restrict__ memL,
                const __nv_bfloat16* __restrict__ WmH, const __nv_bfloat16* __restrict__ WmL,
                const float* __restrict__ dproj, const float* __restrict__ v,
                const float* __restrict__ wcov, const float* __restrict__ cov,
                float* __restrict__ scores, int Lper) {
    const int K = 512;
    extern __shared__ __nv_bfloat16 dyn[];
    __shared__ float rowred[128];

    int tid = threadIdx.x;
    int wid = tid >> 5, lane = tid & 31;
    int rg = wid >> 2, cg = wid & 3;         // 2 row-groups x 4 col-groups
    int warpRow = rg * 64, warpCol = cg * 32;
    int g = lane >> 2, tg = lane & 3;
    int rowBase = blockIdx.x * 128;
    int col0 = blockIdx.y * 128;
    int frow = tid & 127, fhf = tid >> 7;    // fill: 128 rows x 2 base-halves; each thread 2 chunks/half-tile

    // ldmatrix per-lane offsets (bytes)
    int r8 = lane & 7, quad = lane >> 3;
    unsigned a_lane = ((unsigned)((r8 + (quad & 1) * 8) * SPITCH + (quad >> 1) * 8)) * 2;
    unsigned w_lane = ((unsigned)(((quad >> 1) * 8 + r8) * SPITCH + (quad & 1) * 8)) * 2;
    unsigned sdyn = (unsigned)__cvta_generic_to_shared(dyn);

    if (tid < 128) rowred[tid] = 0.f;

    float covr[8];
    if (HAS_COV) {
#pragma unroll
        for (int mt = 0; mt < 4; mt++) {
            covr[2 * mt]     = cov[rowBase + warpRow + mt * 16 + g];
            covr[2 * mt + 1] = cov[rowBase + warpRow + mt * 16 + g + 8];
        }
    }
    float rs[8] = {};

    // fills 32 k-columns: each thread 2x 16B chunks per half-tile (k-offsets fhf*8 and fhf*8+16)
    auto do_fill = [&](int b, int k0) {
        __nv_bfloat16* base = dyn + b * AT_BUF;
        size_t ga = (size_t)(rowBase + frow) * K + k0 + fhf * 8;
        size_t gw = (size_t)(col0 + frow) * K + k0 + fhf * 8;
        unsigned so = frow * SPITCH + fhf * 8;
        cp16(&base[0 * AT_T + so],      &memH[ga]);
        cp16(&base[0 * AT_T + so + 16], &memH[ga + 16]);
        cp16(&base[1 * AT_T + so],      &memL[ga]);
        cp16(&base[1 * AT_T + so + 16], &memL[ga + 16]);
        cp16(&base[2 * AT_T + so],      &WmH[gw]);
        cp16(&base[2 * AT_T + so + 16], &WmH[gw + 16]);
        cp16(&base[3 * AT_T + so],      &WmL[gw]);
        cp16(&base[3 * AT_T + so + 16], &WmL[gw + 16]);
        CP_COMMIT();
    };

    do_fill(0, 0);
    int cur = 0;
    float acc[4][4][4] = {};
    for (int k0 = 0; k0 < K; k0 += 32) {
        cp_wait<0>();
        __syncthreads();               // all warps' fills visible; prior reads done
        if (k0 + 32 < K) do_fill(cur ^ 1, k0 + 32);   // refill issued AFTER barrier -> safe

        unsigned sbase = sdyn + (unsigned)cur * (AT_BUF * 2);
#pragma unroll
        for (int h = 0; h < 2; h++) {
            unsigned hoff = (unsigned)(h * 16) * 2;   // +16 k-cols in bytes
            unsigned AhB = sbase + hoff;
            unsigned AlB = sbase + AT_T * 2 + hoff;
            unsigned WhB = sbase + 2 * AT_T * 2 + hoff;
            unsigned WlB = sbase + 3 * AT_T * 2 + hoff;

            unsigned bh[2][4], bl[2][4];
#pragma unroll
            for (int p = 0; p < 2; p++) {
                unsigned wo = (unsigned)((warpCol + p * 16) * SPITCH) * 2 + w_lane;
                ldsm_x4(bh[p], WhB + wo);
                ldsm_x4(bl[p], WlB + wo);
            }
#pragma unroll
            for (int mt = 0; mt < 4; mt++) {
                unsigned ao = (unsigned)((warpRow + mt * 16) * SPITCH) * 2 + a_lane;
                unsigned ah[4], al[4];
                ldsm_x4(ah, AhB + ao);
                ldsm_x4(al, AlB + ao);
#pragma unroll
                for (int nb = 0; nb < 4; nb++) {
                    const unsigned* ph = &bh[nb >> 1][(nb & 1) * 2];
                    const unsigned* pl = &bl[nb >> 1][(nb & 1) * 2];
                    mma_bf16(acc[mt][nb], ah, ph);
                    mma_bf16(acc[mt][nb], ah, pl);
                    mma_bf16(acc[mt][nb], al, ph);
                }
            }
        }
        cur ^= 1;
    }
    // epilogue: tanh + v-weighted partial sums over this block's 128 d-columns
#pragma unroll
    for (int mt = 0; mt < 4; mt++) {
        int r0 = rowBase + warpRow + mt * 16 + g;
        int r1 = r0 + 8;
        int b0 = r0 / Lper, b1 = r1 / Lper;
#pragma unroll
        for (int nb = 0; nb < 4; nb++) {
            int d = col0 + warpCol + nb * 8 + tg * 2;
#pragma unroll
            for (int jj = 0; jj < 2; jj++) {
                int dd = d + jj;
                float vd = v[dd];
                float wc = HAS_COV ? wcov[dd] : 0.f;
                float f0 = acc[mt][nb][jj]     + dproj[(size_t)b0 * HH + dd];
                float f1 = acc[mt][nb][2 + jj] + dproj[(size_t)b1 * HH + dd];
                if (HAS_COV) { f0 += covr[2 * mt] * wc; f1 += covr[2 * mt + 1] * wc; }
                rs[2 * mt]     += tanhf(f0) * vd;
                rs[2 * mt + 1] += tanhf(f1) * vd;
            }
        }
    }
#pragma unroll
    for (int i = 0; i < 8; i++) {
        float s = rs[i];
        s += __shfl_xor_sync(0xffffffffu, s, 1);
        s += __shfl_xor_sync(0xffffffffu, s, 2);
        int mt = i >> 1;
        int localRow = warpRow + mt * 16 + g + (i & 1) * 8;
        if (tg == 0) atomicAdd(&rowred[localRow], s);
    }
    __syncthreads();
    if (tid < 128) atomicAdd(&scores[rowBase + tid], rowred[tid]);
}

// ==================== bf16x3 mma GEMM (vocab logits): 128x64 tiles, k-step 32, 1 barrier/stage ====================
#define VB_A  (128 * SPITCH)                 // A half-tile (128 rows)
#define VB_W  (64 * SPITCH)                  // W half-tile (64 rows)
#define VB_SZ (2 * VB_A + 2 * VB_W)          // Ah|Al|Wh|Wl
#define VB_DYN (2 * VB_SZ * 2)               // 61440 bytes
__global__ void __launch_bounds__(256)
mma_gemm_bias(const __nv_bfloat16* __restrict__ AH, const __nv_bfloat16* __restrict__ AL,
              const __nv_bfloat16* __restrict__ WH, const __nv_bfloat16* __restrict__ WL,
              const float* __restrict__ bias, float* __restrict__ C,
              int M, int N, int K) {
    extern __shared__ __nv_bfloat16 dsm[];
    int tid = threadIdx.x;
    int wid = tid >> 5, lane = tid & 31;
    int warpM = wid & 3, warpN = wid >> 2;     // 4 m-groups (32 rows) x 2 n-groups (32 cols)
    int warpRow = warpM * 32, warpCol = warpN * 32;
    int g = lane >> 2, tg = lane & 3;
    int cb = blockIdx.x * 64;

    // A fill: 128 rows x 2 base-halves, 2 chunks each; W fill: 64 rows x 4 chunks, 1 each
    int frow = tid & 127, fhf = tid >> 7;
    int wfrow = tid & 63, wfq = tid >> 6;      // 0..3

    int r8 = lane & 7, quad = lane >> 3;
    unsigned a_lane = ((unsigned)((r8 + (quad & 1) * 8) * SPITCH + (quad >> 1) * 8)) * 2;
    unsigned w_lane = ((unsigned)(((quad >> 1) * 8 + r8) * SPITCH + (quad & 1) * 8)) * 2;
    unsigned ssm = (unsigned)__cvta_generic_to_shared(dsm);

    float acc[2][4][4] = {};

    auto do_fill = [&](int b, int k0) {
        __nv_bfloat16* base = dsm + b * VB_SZ;
        {
            size_t ga = (size_t)frow * K + k0 + fhf * 8;
            unsigned so = frow * SPITCH + fhf * 8;
            cp16(&base[0 * VB_A + so],      &AH[ga]);
            cp16(&base[0 * VB_A + so + 16], &AH[ga + 16]);
            cp16(&base[1 * VB_A + so],      &AL[ga]);
            cp16(&base[1 * VB_A + so + 16], &AL[ga + 16]);
        }
        {
            bool ok = cb + wfrow < N;
            size_t gw = (size_t)(ok ? cb + wfrow : 0) * K + k0 + wfq * 8;
            unsigned so = wfrow * SPITCH + wfq * 8;
            cp16z(&base[2 * VB_A + so],          &WH[gw], ok);
            cp16z(&base[2 * VB_A + VB_W + so],   &WL[gw], ok);
        }
        CP_COMMIT();
    };

    do_fill(0, 0);
    int cur = 0;
    for (int k0 = 0; k0 < K; k0 += 32) {
        cp_wait<0>();
        __syncthreads();
        if (k0 + 32 < K) do_fill(cur ^ 1, k0 + 32);

        unsigned sbase = ssm + (unsigned)cur * (VB_SZ * 2);
#pragma unroll
        for (int h = 0; h < 2; h++) {
            unsigned hoff = (unsigned)(h * 16) * 2;
            unsigned AhB = sbase + hoff;
            unsigned AlB = sbase + VB_A * 2 + hoff;
            unsigned WhB = sbase + 2 * VB_A * 2 + hoff;
            unsigned WlB = sbase + (2 * VB_A + VB_W) * 2 + hoff;

            unsigned bh[2][4], bl[2][4];
#pragma unroll
            for (int p = 0; p < 2; p++) {
                unsigned wo = (unsigned)((warpCol + p * 16) * SPITCH) * 2 + w_lane;
                ldsm_x4(bh[p], WhB + wo);
                ldsm_x4(bl[p], WlB + wo);
            }
#pragma unroll
            for (int mt = 0; mt < 2; mt++) {
                unsigned ao = (unsigned)((warpRow + mt * 16) * SPITCH) * 2 + a_lane;
                unsigned ah[4], al[4];
                ldsm_x4(ah, AhB + ao);
                ldsm_x4(al, AlB + ao);
#pragma unroll
                for (int nb = 0; nb < 4; nb++) {
                    const unsigned* ph = &bh[nb >> 1][(nb & 1) * 2];
                    const unsigned* pl = &bl[nb >> 1][(nb & 1) * 2];
                    mma_bf16(acc[mt][nb], ah, ph);
                    mma_bf16(acc[mt][nb], ah, pl);
                    mma_bf16(acc[mt][nb], al, ph);
                }
            }
        }
        cur ^= 1;
    }

#pragma unroll
    for (int mt = 0; mt < 2; mt++) {
#pragma unroll
        for (int nb = 0; nb < 4; nb++) {
            int col = cb + warpCol + nb * 8 + tg * 2;
            int r0 = warpRow + mt * 16 + g, r1 = r0 + 8;
            if (col < N) {
                float bs = bias ? bias[col] : 0.f;
                C[(size_t)r0 * N + col] = acc[mt][nb][0] + bs;
                C[(size_t)r1 * N + col] = acc[mt][nb][2] + bs;
            }
            if (col + 1 < N) {
                float bs = bias ? bias[col + 1] : 0.f;
                C[(size_t)r0 * N + col + 1] = acc[mt][nb][1] + bs;
                C[(size_t)r1 * N + col + 1] = acc[mt][nb][3] + bs;
            }
        }
    }
}

// -------------------- GRU combine + zero attention score buffers --------------------
__global__ void gru_kernel(const float* __restrict__ gi, const float* __restrict__ gh,
                           const float* __restrict__ h0, float* __restrict__ hlast,
                           float* __restrict__ cat, float* __restrict__ out_h,
                           float* __restrict__ wsc, float* __restrict__ ssc) {
    int idx = blockIdx.x * 256 + threadIdx.x;
    if (idx >= BB * HH) return;
    if (idx < BB * LW) wsc[idx] = 0.f;
    if (idx < BB * SSL) ssc[idx] = 0.f;
    int b = idx / HH, j = idx % HH;
    const float* gib = gi + (size_t)b * 3 * HH;
    const float* ghb = gh + (size_t)b * 3 * HH;
    float ir = gib[j], iz = gib[HH + j], in_ = gib[2 * HH + j];
    float hr = ghb[j], hz = ghb[HH + j], hn = ghb[2 * HH + j];
    float r = 1.f / (1.f + expf(-(ir + hr)));
    float z = 1.f / (1.f + expf(-(iz + hz)));
    float n = tanhf(in_ + r * hn);
    float hl = (1.f - z) * n + z * h0[idx];
    hlast[idx] = hl;
    cat[(size_t)b * 1536 + 1024 + j] = hl;
    out_h[idx] = hl;
}

// -------------------- softmax -> mask -> renormalize (+ coverage update) --------------------
__global__ void softmax_mask_kernel(const float* __restrict__ scores, const float* __restrict__ mask,
                                    const float* __restrict__ cov, float* __restrict__ attn_out,
                                    float* __restrict__ cov_out, int N) {
    __shared__ float buf[512];
    __shared__ float red[128];
    int b = blockIdx.x, tid = threadIdx.x;
    const float* s = scores + (size_t)b * N;
    float mx = -1e30f;
    for (int i = tid; i < N; i += 128) { float vv = s[i]; buf[i] = vv; mx = fmaxf(mx, vv); }
    red[tid] = mx; __syncthreads();
    for (int off = 64; off; off >>= 1) { if (tid < off) red[tid] = fmaxf(red[tid], red[tid + off]); __syncthreads(); }
    mx = red[0]; __syncthreads();
    float sum = 0.f;
    for (int i = tid; i < N; i += 128) { float e = expf(buf[i] - mx); buf[i] = e; sum += e; }
    red[tid] = sum; __syncthreads();
    for (int off = 64; off; off >>= 1) { if (tid < off) red[tid] += red[tid + off]; __syncthreads(); }
    sum = red[0]; __syncthreads();
    float s2 = 0.f;
    for (int i = tid; i < N; i += 128) { float t = (buf[i] / sum) * mask[(size_t)b * N + i]; buf[i] = t; s2 += t; }
    red[tid] = s2; __syncthreads();
    for (int off = 64; off; off >>= 1) { if (tid < off) red[tid] += red[tid + off]; __syncthreads(); }
    s2 = red[0];
    float inv = 1.f / (s2 + 1e-10f);
    for (int i = tid; i < N; i += 128) {
        float a = buf[i] * inv;
        attn_out[(size_t)b * N + i] = a;
        if (cov_out) cov_out[(size_t)b * N + i] = cov[(size_t)b * N + i] + a;
    }
}

// -------------------- context: ctx[b,m] = sum_l attn[b,l] * mem[b,l,m] --------------------
__global__ void context_kernel(const float* __restrict__ attn, const float* __restrict__ mem,
                               float* __restrict__ ctx_out, float* __restrict__ cat,
                               int Lc, int catOff) {
    __shared__ float a_s[512];
    int b = blockIdx.x;
    int m = blockIdx.y * 128 + threadIdx.x;
    for (int i = threadIdx.x; i < Lc; i += 128) a_s[i] = attn[(size_t)b * Lc + i];
    __syncthreads();
    const float* mb = mem + (size_t)b * Lc * MMD + m;
    float a0 = 0.f, a1 = 0.f, a2 = 0.f, a3 = 0.f;
    int l = 0;
    for (; l + 4 <= Lc; l += 4) {
        a0 += a_s[l]     * mb[(size_t)l * MMD];
        a1 += a_s[l + 1] * mb[(size_t)(l + 1) * MMD];
        a2 += a_s[l + 2] * mb[(size_t)(l + 2) * MMD];
        a3 += a_s[l + 3] * mb[(size_t)(l + 3) * MMD];
    }
    for (; l < Lc; l++) a0 += a_s[l] * mb[(size_t)l * MMD];
    float acc = (a0 + a1) + (a2 + a3);
    if (ctx_out) ctx_out[(size_t)b * MMD + m] = acc;
    cat[(size_t)b * 1536 + catOff + m] = acc;
}

// -------------------- p_gen --------------------
__global__ void pgen_kernel(const float* __restrict__ cat, const float* __restrict__ yemb,
                            const float* __restrict__ pw, const float* __restrict__ pb,
                            float* __restrict__ pg_scr, float* __restrict__ pg_out) {
    __shared__ float red[256];
    int b = blockIdx.x, tid = threadIdx.x;
    float s = 0.f;
    for (int i = tid; i < 1536; i += 256) s += cat[(size_t)b * 1536 + i] * pw[i];
    for (int i = tid; i < EMB_; i += 256) s += yemb[(size_t)b * EMB_ + i] * pw[1536 + i];
    red[tid] = s; __syncthreads();
    for (int off = 128; off; off >>= 1) { if (tid < off) red[tid] += red[tid + off]; __syncthreads(); }
    if (tid == 0) {
        float p = 1.f / (1.f + expf(-(red[0] + pb[0])));
        pg_scr[b] = p;
        pg_out[b] = p;
    }
}

// -------------------- vocab softmax + p_gen mix + OOV scatter (1024 thr) --------------------
__global__ void __launch_bounds__(1024)
final_kernel(const float* __restrict__ logits, const float* __restrict__ pgen,
             const float* __restrict__ wattn, const int* __restrict__ src_oov,
             float* __restrict__ out_final) {
    __shared__ float red[1024];
    int b = blockIdx.x, tid = threadIdx.x;
    const float4* lg4 = (const float4*)(logits + (size_t)b * VV);
    const int n4 = VV / 4;
    float* fr = out_final + (size_t)b * VE;
    float2* fr2 = (float2*)fr;

    float mx = -1e30f;
    for (int i = tid; i < n4; i += 1024) {
        float4 x = lg4[i];
        mx = fmaxf(mx, fmaxf(fmaxf(x.x, x.y), fmaxf(x.z, x.w)));
    }
    red[tid] = mx; __syncthreads();
    for (int off = 512; off; off >>= 1) { if (tid < off) red[tid] = fmaxf(red[tid], red[tid + off]); __syncthreads(); }
    mx = red[0]; __syncthreads();

    float sum = 0.f;
    for (int i = tid; i < n4; i += 1024) {
        float4 x = lg4[i];
        float e0 = expf(x.x - mx), e1 = expf(x.y - mx);
        float e2 = expf(x.z - mx), e3 = expf(x.w - mx);
        sum += (e0 + e1) + (e2 + e3);
        fr2[2 * i]     = make_float2(e0, e1);
        fr2[2 * i + 1] = make_float2(e2, e3);
    }
    red[tid] = sum; __syncthreads();
    for (int off = 512; off; off >>= 1) { if (tid < off) red[tid] += red[tid + off]; __syncthreads(); }
    sum = red[0];
    float pg = pgen[b];
    float scale = pg / sum;
    for (int i = tid; i < n4; i += 1024) {
        float2 p0 = fr2[2 * i], p1 = fr2[2 * i + 1];
        p0.x *= scale; p0.y *= scale; p1.x *= scale; p1.y *= scale;
        fr2[2 * i] = p0; fr2[2 * i + 1] = p1;
    }
    for (int i = VV + tid; i < VE; i += 1024) fr[i] = 0.f;
    __syncthreads();
    float om = 1.f - pg;
    if (tid < LW) {
        int idx = src_oov[(size_t)b * LW + tid];
        atomicAdd(&fr[idx], om * wattn[(size_t)b * LW + tid]);
    }
}

// -------------------- launcher --------------------
extern "C" void kernel_launch(void* const* d_in, const int* in_sizes, int n_in,
                              void* d_out, int out_size) {
    (void)in_sizes; (void)n_in; (void)out_size;
    const float* h0   = (const float*)d_in[0];
    const float* wmem = (const float*)d_in[1];
    const float* smem_bank = (const float*)d_in[2];
    const float* wmask = (const float*)d_in[3];
    const float* smask = (const float*)d_in[4];
    const float* cov   = (const float*)d_in[5];
    const float* emb   = (const float*)d_in[6];
    const float* gwih  = (const float*)d_in[7];
    const float* gwhh  = (const float*)d_in[8];
    const float* gbih  = (const float*)d_in[9];
    const float* gbhh  = (const float*)d_in[10];
    const float* wmp   = (const float*)d_in[11];
    const float* wdpw  = (const float*)d_in[12];
    const float* wdpb  = (const float*)d_in[13];
    const float* wv    = (const float*)d_in[14];
    const float* wcp   = (const float*)d_in[15];
    const float* smp   = (const float*)d_in[16];
    const float* sdpw  = (const float*)d_in[17];
    const float* sdpb  = (const float*)d_in[18];
    const float* sv    = (const float*)d_in[19];
    const float* pgw   = (const float*)d_in[20];
    const float* pgb   = (const float*)d_in[21];
    const float* vd1w  = (const float*)d_in[22];
    const float* vd1b  = (const float*)d_in[23];
    const float* vd2w  = (const float*)d_in[24];
    const float* vd2b  = (const float*)d_in[25];
    const int*   y     = (const int*)d_in[26];
    const int*   soov  = (const int*)d_in[27];
    float* out = (float*)d_out;

    float *yemb, *gi, *gh, *hl, *dpw, *dps, *wsc, *ssc, *sat, *cat, *hid, *pg, *lg;
    __nv_bfloat16 *wmH, *wmL, *smH, *smL, *wpH, *wpL, *spH, *spL, *hdH, *hdL, *v2H, *v2L;
    cudaGetSymbolAddress((void**)&yemb, g_yemb);
    cudaGetSymbolAddress((void**)&gi,   g_gi);
    cudaGetSymbolAddress((void**)&gh,   g_gh);
    cudaGetSymbolAddress((void**)&hl,   g_hlast);
    cudaGetSymbolAddress((void**)&dpw,  g_dpw);
    cudaGetSymbolAddress((void**)&dps,  g_dps);
    cudaGetSymbolAddress((void**)&wsc,  g_wscores);
    cudaGetSymbolAddress((void**)&ssc,  g_sscores);
    cudaGetSymbolAddress((void**)&sat,  g_sattn);
    cudaGetSymbolAddress((void**)&cat,  g_cat);
    cudaGetSymbolAddress((void**)&hid,  g_hid);
    cudaGetSymbolAddress((void**)&pg,   g_pgen);
    cudaGetSymbolAddress((void**)&lg,   g_logits);
    cudaGetSymbolAddress((void**)&wmH,  g_wmemH);
    cudaGetSymbolAddress((void**)&wmL,  g_wmemL);
    cudaGetSymbolAddress((void**)&smH,  g_smemH);
    cudaGetSymbolAddress((void**)&smL,  g_smemL);
    cudaGetSymbolAddress((void**)&wpH,  g_wmpH);
    cudaGetSymbolAddress((void**)&wpL,  g_wmpL);
    cudaGetSymbolAddress((void**)&spH,  g_smpH);
    cudaGetSymbolAddress((void**)&spL,  g_smpL);
    cudaGetSymbolAddress((void**)&hdH,  g_hidH);
    cudaGetSymbolAddress((void**)&hdL,  g_hidL);
    cudaGetSymbolAddress((void**)&v2H,  g_vd2wH);
    cudaGetSymbolAddress((void**)&v2L,  g_vd2wL);

    cudaFuncSetAttribute(attn_scores_mma<true>,
                         cudaFuncAttributeMaxDynamicSharedMemorySize, AT_DYN);
    cudaFuncSetAttribute(attn_scores_mma<false>,
                         cudaFuncAttributeMaxDynamicSharedMemorySize, AT_DYN);
    cudaFuncSetAttribute(mma_gemm_bias,
                         cudaFuncAttributeMaxDynamicSharedMemorySize, VB_DYN);

    // 0: prep — gigh GEMMs + all big presplits (MLP-4), one launch
    prep_kernel<<<NB_PREP, 256>>>(emb, y, h0, gwih, gbih, gwhh, gbhh, gi, gh, yemb,
                                  wmem, wmH, wmL, smem_bank, smH, smL,
                                  wmp, wpH, wpL, smp, spH, spL, vd2w, v2H, v2L);
    // 1: GRU combine (+ zero score buffers for atomic accumulation)
    gru_kernel<<<(BB * HH + 255) / 256, 256>>>(gi, gh, h0, hl, cat, out + OUT_H, wsc, ssc);
    // 2: fused decoder-state projections
    dpwdps_kernel<<<dim3(8, 2, 2), 256>>>(hl, wdpw, wdpb, sdpw, sdpb, dpw, dps);
    // 3: word attention scores (chunk-parallel)  <-- profiled launch
    attn_scores_mma<true ><<<dim3((BB * LW) / 128, 4), 256, AT_DYN>>>(wmH, wmL, wpH, wpL, dpw, wv, wcp, cov, wsc, LW);
    // 4: sentence attention scores (chunk-parallel)
    attn_scores_mma<false><<<dim3((BB * SSL) / 128, 4), 256, AT_DYN>>>(smH, smL, spH, spL, dps, sv, nullptr, nullptr, ssc, SSL);

    // softmax + mask + renorm (+ coverage output for word)
    softmax_mask_kernel<<<BB, 128>>>(wsc, wmask, cov, out + OUT_WATTN, out + OUT_WCOV, LW);
    softmax_mask_kernel<<<BB, 128>>>(ssc, smask, nullptr, sat, nullptr, SSL);

    // contexts
    context_kernel<<<dim3(BB, 4), 128>>>(out + OUT_WATTN, wmem, out + OUT_WCTX, cat, LW, 0);
    context_kernel<<<dim3(BB, 4), 128>>>(sat, smem_bank, nullptr, cat, SSL, 512);

    // p_gen
    pgen_kernel<<<BB, 256>>>(cat, yemb, pgw, pgb, pg, out + OUT_PGEN);

    // vocab head
    gemm_bias_kernel<<<dim3(8, 2), 256>>>(cat, vd1w, vd1b, hid, BB, HH, 3 * HH);
    presplit_kernel<<<(BB * HH / 4 + 255) / 256, 256>>>(hid, hdH, hdL, BB * HH / 4);
    mma_gemm_bias<<<(VV + 63) / 64, 256, VB_DYN>>>(hdH, hdL, v2H, v2L, vd2b, lg, BB, VV, HH);

    // vocab softmax, p_gen mix, zeros for OOV slots, scatter-add of copy dist
    final_kernel<<<BB, 1024>>>(lg, pg, out + OUT_WATTN, soov, out + OUT_FINAL);
}